// round 2
// baseline (speedup 1.0000x reference)
#include <cuda_runtime.h>
#include <cstddef>

#define N_TOK   8192
#define D_IN    384
#define D_H     64
#define N_HEADS 4
#define N_CLS   6
#define LN_EPS  1e-5f

// Scratch (no allocations allowed)
__device__ float g_hp[(size_t)N_HEADS * N_TOK * D_H];   // per-head projected features (V and K)
__device__ float g_ss[(size_t)N_HEADS * N_TOK];         // per-head row sum-of-squares
__device__ float g_hh[(size_t)N_HEADS * N_TOK * D_H];   // per-head attention outputs

// ---------------------------------------------------------------------------
// Kernel 1: h = relu(x@proj_w + proj_b); hp[h] = h@head_w[h] + head_b[h];
//           sumsq[h][n] = ||hp[h][n]||^2
// 64 rows per block, 256 threads, 4x4 register tiles.
// ---------------------------------------------------------------------------
__global__ void __launch_bounds__(256) k_proj(const float* __restrict__ x,
                                              const float* __restrict__ pw,
                                              const float* __restrict__ pb,
                                              const float* __restrict__ hw,
                                              const float* __restrict__ hb)
{
    __shared__ float As[64 * 68];   // x tile (then h tile), stride 68
    __shared__ float Ws[64 * 64];   // weight tile, stride 64

    const int tid = threadIdx.x;
    const int ty = tid >> 4, tx = tid & 15;
    const int row0 = blockIdx.x * 64;

    float acc[4][4];
#pragma unroll
    for (int i = 0; i < 4; i++)
#pragma unroll
        for (int j = 0; j < 4; j++) acc[i][j] = 0.f;

    for (int kk = 0; kk < D_IN; kk += 64) {
#pragma unroll
        for (int l = 0; l < 4; l++) {
            int idx = tid + l * 256;
            int r = idx >> 4;
            int c = (idx & 15) << 2;
            *(float4*)&As[r * 68 + c] = *(const float4*)&x[(size_t)(row0 + r) * D_IN + kk + c];
            *(float4*)&Ws[r * 64 + c] = *(const float4*)&pw[(size_t)(kk + r) * D_H + c];
        }
        __syncthreads();
#pragma unroll 8
        for (int k = 0; k < 64; k++) {
            float a0 = As[(4 * ty + 0) * 68 + k];
            float a1 = As[(4 * ty + 1) * 68 + k];
            float a2 = As[(4 * ty + 2) * 68 + k];
            float a3 = As[(4 * ty + 3) * 68 + k];
            float4 b = *(const float4*)&Ws[k * 64 + 4 * tx];
            acc[0][0] += a0 * b.x; acc[0][1] += a0 * b.y; acc[0][2] += a0 * b.z; acc[0][3] += a0 * b.w;
            acc[1][0] += a1 * b.x; acc[1][1] += a1 * b.y; acc[1][2] += a1 * b.z; acc[1][3] += a1 * b.w;
            acc[2][0] += a2 * b.x; acc[2][1] += a2 * b.y; acc[2][2] += a2 * b.z; acc[2][3] += a2 * b.w;
            acc[3][0] += a3 * b.x; acc[3][1] += a3 * b.y; acc[3][2] += a3 * b.z; acc[3][3] += a3 * b.w;
        }
        __syncthreads();
    }

    // bias + relu -> write h tile into As
    {
        float4 pbv = *(const float4*)&pb[4 * tx];
        float pbz[4] = {pbv.x, pbv.y, pbv.z, pbv.w};
#pragma unroll
        for (int i = 0; i < 4; i++)
#pragma unroll
            for (int j = 0; j < 4; j++)
                As[(4 * ty + i) * 68 + 4 * tx + j] = fmaxf(acc[i][j] + pbz[j], 0.f);
    }
    __syncthreads();

    for (int h = 0; h < N_HEADS; h++) {
#pragma unroll
        for (int l = 0; l < 4; l++) {
            int idx = tid + l * 256;
            int r = idx >> 4;
            int c = (idx & 15) << 2;
            *(float4*)&Ws[r * 64 + c] = *(const float4*)&hw[((size_t)h * 64 + r) * 64 + c];
        }
        __syncthreads();

        float a2c[4][4];
#pragma unroll
        for (int i = 0; i < 4; i++)
#pragma unroll
            for (int j = 0; j < 4; j++) a2c[i][j] = 0.f;

#pragma unroll 8
        for (int k = 0; k < 64; k++) {
            float a0 = As[(4 * ty + 0) * 68 + k];
            float a1 = As[(4 * ty + 1) * 68 + k];
            float a2 = As[(4 * ty + 2) * 68 + k];
            float a3 = As[(4 * ty + 3) * 68 + k];
            float4 b = *(const float4*)&Ws[k * 64 + 4 * tx];
            a2c[0][0] += a0 * b.x; a2c[0][1] += a0 * b.y; a2c[0][2] += a0 * b.z; a2c[0][3] += a0 * b.w;
            a2c[1][0] += a1 * b.x; a2c[1][1] += a1 * b.y; a2c[1][2] += a1 * b.z; a2c[1][3] += a1 * b.w;
            a2c[2][0] += a2 * b.x; a2c[2][1] += a2 * b.y; a2c[2][2] += a2 * b.z; a2c[2][3] += a2 * b.w;
            a2c[3][0] += a3 * b.x; a2c[3][1] += a3 * b.y; a2c[3][2] += a3 * b.z; a2c[3][3] += a3 * b.w;
        }

        float4 hbv = *(const float4*)&hb[h * 64 + 4 * tx];
        float hbz[4] = {hbv.x, hbv.y, hbv.z, hbv.w};
#pragma unroll
        for (int i = 0; i < 4; i++) {
            float v0 = a2c[i][0] + hbz[0];
            float v1 = a2c[i][1] + hbz[1];
            float v2 = a2c[i][2] + hbz[2];
            float v3 = a2c[i][3] + hbz[3];
            float rs = v0 * v0 + v1 * v1 + v2 * v2 + v3 * v3;
            *(float4*)&g_hp[((size_t)h * N_TOK + row0 + 4 * ty + i) * D_H + 4 * tx] =
                make_float4(v0, v1, v2, v3);
#pragma unroll
            for (int w = 1; w < 16; w <<= 1)
                rs += __shfl_xor_sync(0xffffffffu, rs, w, 16);
            if (tx == 0) g_ss[(size_t)h * N_TOK + row0 + 4 * ty + i] = rs;
        }
        __syncthreads();
    }
}

// ---------------------------------------------------------------------------
// Kernel 2: flash-attention style distance attention, per (head, 64-query block).
// S = -sqrt(max(qq + kk - 2 Q.K, 0)); online softmax; O += P@V.
// Q/K/P in smem transposed + XOR-swizzled (conflict-free LDS.128 on both frags).
// ---------------------------------------------------------------------------
__global__ void __launch_bounds__(256) k_attn()
{
    __shared__ float Qs[64 * 64];   // [d][row] swizzled
    __shared__ float KPs[64 * 64];  // K [d][key] swizzled, reused as P [key][row] swizzled
    __shared__ float Vs[64 * 64];   // [key][d] natural

    const int tid = threadIdx.x;
    const int ty = tid >> 4, tx = tid & 15;
    const int head = blockIdx.y;
    const int q0 = blockIdx.x * 64;
    const float* __restrict__ hp = g_hp + (size_t)head * (N_TOK * D_H);
    const float* __restrict__ ss = g_ss + (size_t)head * N_TOK;

    // Load Q transposed + swizzled (coalesced global reads: consecutive tid -> consecutive d)
#pragma unroll
    for (int l = 0; l < 16; l++) {
        int idx = tid + l * 256;   // 0..4095
        int d = idx & 63;
        int r = idx >> 6;
        Qs[d * 64 + ((((r >> 2) ^ (d & 15)) << 2) | (r & 3))] = hp[(size_t)(q0 + r) * D_H + d];
    }

    float qq[4];
#pragma unroll
    for (int i = 0; i < 4; i++) qq[i] = ss[q0 + 4 * ty + i];

    float m[4], lsum[4], O[4][4];
#pragma unroll
    for (int i = 0; i < 4; i++) {
        m[i] = -1e30f; lsum[i] = 0.f;
#pragma unroll
        for (int j = 0; j < 4; j++) O[i][j] = 0.f;
    }
    __syncthreads();

    for (int kt = 0; kt < N_TOK; kt += 64) {
        // K transposed + swizzled
#pragma unroll
        for (int l = 0; l < 16; l++) {
            int idx = tid + l * 256;
            int d = idx & 63;
            int r = idx >> 6;
            KPs[d * 64 + ((((r >> 2) ^ (d & 15)) << 2) | (r & 3))] = hp[(size_t)(kt + r) * D_H + d];
        }
        // V natural
#pragma unroll
        for (int l = 0; l < 4; l++) {
            int idx = tid + l * 256;
            int r = idx >> 4;
            int c = (idx & 15) << 2;
            *(float4*)&Vs[r * 64 + c] = *(const float4*)&hp[(size_t)(kt + r) * D_H + c];
        }
        __syncthreads();

        // S = Q.K^T
        float S[4][4];
#pragma unroll
        for (int i = 0; i < 4; i++)
#pragma unroll
            for (int j = 0; j < 4; j++) S[i][j] = 0.f;

#pragma unroll 8
        for (int k = 0; k < 64; k++) {
            float4 a = *(const float4*)&Qs[k * 64 + ((ty ^ (k & 15)) << 2)];
            float4 b = *(const float4*)&KPs[k * 64 + ((tx ^ (k & 15)) << 2)];
            S[0][0] += a.x * b.x; S[0][1] += a.x * b.y; S[0][2] += a.x * b.z; S[0][3] += a.x * b.w;
            S[1][0] += a.y * b.x; S[1][1] += a.y * b.y; S[1][2] += a.y * b.z; S[1][3] += a.y * b.w;
            S[2][0] += a.z * b.x; S[2][1] += a.z * b.y; S[2][2] += a.z * b.z; S[2][3] += a.z * b.w;
            S[3][0] += a.w * b.x; S[3][1] += a.w * b.y; S[3][2] += a.w * b.z; S[3][3] += a.w * b.w;
        }

        float4 kkv = *(const float4*)&ss[kt + 4 * tx];
        float kkz[4] = {kkv.x, kkv.y, kkv.z, kkv.w};

#pragma unroll
        for (int i = 0; i < 4; i++) {
            float best = -1e30f;
#pragma unroll
            for (int j = 0; j < 4; j++) {
                float sq = qq[i] + kkz[j] - 2.f * S[i][j];
                float s = (sq > 0.f) ? -sqrtf(sq) : 0.f;   // safe cdist (0 at 0)
                S[i][j] = s;
                best = fmaxf(best, s);
            }
#pragma unroll
            for (int w = 1; w < 16; w <<= 1)
                best = fmaxf(best, __shfl_xor_sync(0xffffffffu, best, w, 16));
            float newm = fmaxf(m[i], best);
            float scale = __expf(m[i] - newm);
            m[i] = newm;
            float rs = 0.f;
#pragma unroll
            for (int j = 0; j < 4; j++) {
                float p = __expf(S[i][j] - newm);
                S[i][j] = p;
                rs += p;
            }
#pragma unroll
            for (int w = 1; w < 16; w <<= 1)
                rs += __shfl_xor_sync(0xffffffffu, rs, w, 16);
            lsum[i] = lsum[i] * scale + rs;
#pragma unroll
            for (int c = 0; c < 4; c++) O[i][c] *= scale;
        }

        __syncthreads();   // everyone done reading KPs as K
        // Write P transposed + swizzled into KPs
#pragma unroll
        for (int i = 0; i < 4; i++) {
#pragma unroll
            for (int j = 0; j < 4; j++) {
                int col = 4 * tx + j;
                KPs[col * 64 + (((ty ^ (col & 15)) << 2) | i)] = S[i][j];
            }
        }
        __syncthreads();

        // O += P @ V
#pragma unroll 8
        for (int j = 0; j < 64; j++) {
            float4 a = *(const float4*)&KPs[j * 64 + ((ty ^ (j & 15)) << 2)];
            float4 b = *(const float4*)&Vs[j * 64 + 4 * tx];
            O[0][0] += a.x * b.x; O[0][1] += a.x * b.y; O[0][2] += a.x * b.z; O[0][3] += a.x * b.w;
            O[1][0] += a.y * b.x; O[1][1] += a.y * b.y; O[1][2] += a.y * b.z; O[1][3] += a.y * b.w;
            O[2][0] += a.z * b.x; O[2][1] += a.z * b.y; O[2][2] += a.z * b.z; O[2][3] += a.z * b.w;
            O[3][0] += a.w * b.x; O[3][1] += a.w * b.y; O[3][2] += a.w * b.z; O[3][3] += a.w * b.w;
        }
        __syncthreads();   // before next tile overwrites KPs/Vs
    }

#pragma unroll
    for (int i = 0; i < 4; i++) {
        float inv = 1.f / lsum[i];
        *(float4*)&g_hh[((size_t)head * N_TOK + q0 + 4 * ty + i) * D_H + 4 * tx] =
            make_float4(O[i][0] * inv, O[i][1] * inv, O[i][2] * inv, O[i][3] * inv);
    }
}

// ---------------------------------------------------------------------------
// Kernel 3: combine heads (softmax(attn_w) weights), LayerNorm(D_H=64), FC to 6.
// One warp per row; each lane owns dims {lane, lane+32}.
// ---------------------------------------------------------------------------
__global__ void __launch_bounds__(256) k_final(const float* __restrict__ attn_w,
                                               const float* __restrict__ gamma,
                                               const float* __restrict__ beta,
                                               const float* __restrict__ fcw,
                                               const float* __restrict__ fcb,
                                               float* __restrict__ out)
{
    const int warp = threadIdx.x >> 5;
    const int lane = threadIdx.x & 31;
    const int row = blockIdx.x * 8 + warp;

    float a0 = attn_w[0], a1 = attn_w[1], a2 = attn_w[2], a3 = attn_w[3];
    float mx = fmaxf(fmaxf(a0, a1), fmaxf(a2, a3));
    float aw[4];
    aw[0] = __expf(a0 - mx); aw[1] = __expf(a1 - mx);
    aw[2] = __expf(a2 - mx); aw[3] = __expf(a3 - mx);
    float ainv = 1.f / (aw[0] + aw[1] + aw[2] + aw[3]);

    const int d0 = lane, d1 = lane + 32;
    float c0 = 0.f, c1 = 0.f;
#pragma unroll
    for (int h = 0; h < N_HEADS; h++) {
        const float* p = g_hh + ((size_t)h * N_TOK + row) * D_H;
        c0 += aw[h] * p[d0];
        c1 += aw[h] * p[d1];
    }
    c0 *= ainv; c1 *= ainv;

    float s = c0 + c1;
#pragma unroll
    for (int w = 16; w; w >>= 1) s += __shfl_xor_sync(0xffffffffu, s, w);
    float mu = s * (1.f / 64.f);
    float v0 = c0 - mu, v1 = c1 - mu;
    float vv = v0 * v0 + v1 * v1;
#pragma unroll
    for (int w = 16; w; w >>= 1) vv += __shfl_xor_sync(0xffffffffu, vv, w);
    float inv = rsqrtf(vv * (1.f / 64.f) + LN_EPS);
    float n0 = v0 * inv * gamma[d0] + beta[d0];
    float n1 = v1 * inv * gamma[d1] + beta[d1];

    float o[N_CLS];
#pragma unroll
    for (int c = 0; c < N_CLS; c++)
        o[c] = n0 * fcw[d0 * N_CLS + c] + n1 * fcw[d1 * N_CLS + c];
#pragma unroll
    for (int c = 0; c < N_CLS; c++)
#pragma unroll
        for (int w = 16; w; w >>= 1) o[c] += __shfl_xor_sync(0xffffffffu, o[c], w);

    if (lane == 0) {
#pragma unroll
        for (int c = 0; c < N_CLS; c++)
            out[(size_t)row * N_CLS + c] = o[c] + fcb[c];
    }
}

// ---------------------------------------------------------------------------
extern "C" void kernel_launch(void* const* d_in, const int* in_sizes, int n_in,
                              void* d_out, int out_size)
{
    const float* x      = (const float*)d_in[0];
    const float* proj_w = (const float*)d_in[1];
    const float* proj_b = (const float*)d_in[2];
    const float* head_w = (const float*)d_in[3];
    const float* head_b = (const float*)d_in[4];
    const float* attn_w = (const float*)d_in[5];
    const float* gamma  = (const float*)d_in[6];
    const float* beta   = (const float*)d_in[7];
    const float* fc_w   = (const float*)d_in[8];
    const float* fc_b   = (const float*)d_in[9];
    float* out = (float*)d_out;

    k_proj<<<N_TOK / 64, 256>>>(x, proj_w, proj_b, head_w, head_b);

    dim3 g2(N_TOK / 64, N_HEADS);
    k_attn<<<g2, 256>>>();

    k_final<<<N_TOK / 8, 256>>>(attn_w, gamma, beta, fc_w, fc_b, out);
}

// round 3
// speedup vs baseline: 1.6084x; 1.6084x over previous
#include <cuda_runtime.h>
#include <cstddef>

typedef unsigned long long u64;

#define N_TOK   8192
#define D_IN    384
#define D_H     64
#define N_HEADS 4
#define N_CLS   6
#define LN_EPS  1e-5f

__device__ float g_hp[(size_t)N_HEADS * N_TOK * D_H];
__device__ float g_ss[(size_t)N_HEADS * N_TOK];
__device__ float g_hh[(size_t)N_HEADS * N_TOK * D_H];

__device__ __forceinline__ void fma2(u64 &d, u64 a, u64 b) {
    asm("fma.rn.f32x2 %0, %1, %2, %0;" : "+l"(d) : "l"(a), "l"(b));
}
__device__ __forceinline__ u64 dup2(float x) {
    u64 r; asm("mov.b64 %0, {%1, %1};" : "=l"(r) : "f"(x)); return r;
}
__device__ __forceinline__ void mul2(u64 &d, u64 s) {
    asm("mul.rn.f32x2 %0, %0, %1;" : "+l"(d) : "l"(s));
}
__device__ __forceinline__ float2 unp(u64 v) {
    float2 f; asm("mov.b64 {%0, %1}, %2;" : "=f"(f.x), "=f"(f.y) : "l"(v)); return f;
}
__device__ __forceinline__ float ex2f(float x) {
    float r; asm("ex2.approx.f32 %0, %1;" : "=f"(r) : "f"(x)); return r;
}
__device__ __forceinline__ float sqrtapx(float x) {
    float r; asm("sqrt.approx.f32 %0, %1;" : "=f"(r) : "f"(x)); return r;
}

// ---------------------------------------------------------------------------
// Kernel 1: unchanged (34us, 1% of runtime)
// ---------------------------------------------------------------------------
__global__ void __launch_bounds__(256) k_proj(const float* __restrict__ x,
                                              const float* __restrict__ pw,
                                              const float* __restrict__ pb,
                                              const float* __restrict__ hw,
                                              const float* __restrict__ hb)
{
    __shared__ float As[64 * 68];
    __shared__ float Ws[64 * 64];
    const int tid = threadIdx.x;
    const int ty = tid >> 4, tx = tid & 15;
    const int row0 = blockIdx.x * 64;

    float acc[4][4];
#pragma unroll
    for (int i = 0; i < 4; i++)
#pragma unroll
        for (int j = 0; j < 4; j++) acc[i][j] = 0.f;

    for (int kk = 0; kk < D_IN; kk += 64) {
#pragma unroll
        for (int l = 0; l < 4; l++) {
            int idx = tid + l * 256;
            int r = idx >> 4, c = (idx & 15) << 2;
            *(float4*)&As[r * 68 + c] = *(const float4*)&x[(size_t)(row0 + r) * D_IN + kk + c];
            *(float4*)&Ws[r * 64 + c] = *(const float4*)&pw[(size_t)(kk + r) * D_H + c];
        }
        __syncthreads();
#pragma unroll 8
        for (int k = 0; k < 64; k++) {
            float a0 = As[(4 * ty + 0) * 68 + k];
            float a1 = As[(4 * ty + 1) * 68 + k];
            float a2 = As[(4 * ty + 2) * 68 + k];
            float a3 = As[(4 * ty + 3) * 68 + k];
            float4 b = *(const float4*)&Ws[k * 64 + 4 * tx];
            acc[0][0] += a0 * b.x; acc[0][1] += a0 * b.y; acc[0][2] += a0 * b.z; acc[0][3] += a0 * b.w;
            acc[1][0] += a1 * b.x; acc[1][1] += a1 * b.y; acc[1][2] += a1 * b.z; acc[1][3] += a1 * b.w;
            acc[2][0] += a2 * b.x; acc[2][1] += a2 * b.y; acc[2][2] += a2 * b.z; acc[2][3] += a2 * b.w;
            acc[3][0] += a3 * b.x; acc[3][1] += a3 * b.y; acc[3][2] += a3 * b.z; acc[3][3] += a3 * b.w;
        }
        __syncthreads();
    }
    {
        float4 pbv = *(const float4*)&pb[4 * tx];
        float pbz[4] = {pbv.x, pbv.y, pbv.z, pbv.w};
#pragma unroll
        for (int i = 0; i < 4; i++)
#pragma unroll
            for (int j = 0; j < 4; j++)
                As[(4 * ty + i) * 68 + 4 * tx + j] = fmaxf(acc[i][j] + pbz[j], 0.f);
    }
    __syncthreads();

    for (int h = 0; h < N_HEADS; h++) {
#pragma unroll
        for (int l = 0; l < 4; l++) {
            int idx = tid + l * 256;
            int r = idx >> 4, c = (idx & 15) << 2;
            *(float4*)&Ws[r * 64 + c] = *(const float4*)&hw[((size_t)h * 64 + r) * 64 + c];
        }
        __syncthreads();

        float a2c[4][4];
#pragma unroll
        for (int i = 0; i < 4; i++)
#pragma unroll
            for (int j = 0; j < 4; j++) a2c[i][j] = 0.f;

#pragma unroll 8
        for (int k = 0; k < 64; k++) {
            float a0 = As[(4 * ty + 0) * 68 + k];
            float a1 = As[(4 * ty + 1) * 68 + k];
            float a2 = As[(4 * ty + 2) * 68 + k];
            float a3 = As[(4 * ty + 3) * 68 + k];
            float4 b = *(const float4*)&Ws[k * 64 + 4 * tx];
            a2c[0][0] += a0 * b.x; a2c[0][1] += a0 * b.y; a2c[0][2] += a0 * b.z; a2c[0][3] += a0 * b.w;
            a2c[1][0] += a1 * b.x; a2c[1][1] += a1 * b.y; a2c[1][2] += a1 * b.z; a2c[1][3] += a1 * b.w;
            a2c[2][0] += a2 * b.x; a2c[2][1] += a2 * b.y; a2c[2][2] += a2 * b.z; a2c[2][3] += a2 * b.w;
            a2c[3][0] += a3 * b.x; a2c[3][1] += a3 * b.y; a2c[3][2] += a3 * b.z; a2c[3][3] += a3 * b.w;
        }

        float4 hbv = *(const float4*)&hb[h * 64 + 4 * tx];
        float hbz[4] = {hbv.x, hbv.y, hbv.z, hbv.w};
#pragma unroll
        for (int i = 0; i < 4; i++) {
            float v0 = a2c[i][0] + hbz[0];
            float v1 = a2c[i][1] + hbz[1];
            float v2 = a2c[i][2] + hbz[2];
            float v3 = a2c[i][3] + hbz[3];
            float rs = v0 * v0 + v1 * v1 + v2 * v2 + v3 * v3;
            *(float4*)&g_hp[((size_t)h * N_TOK + row0 + 4 * ty + i) * D_H + 4 * tx] =
                make_float4(v0, v1, v2, v3);
#pragma unroll
            for (int w = 1; w < 16; w <<= 1)
                rs += __shfl_xor_sync(0xffffffffu, rs, w, 16);
            if (tx == 0) g_ss[(size_t)h * N_TOK + row0 + 4 * ty + i] = rs;
        }
        __syncthreads();
    }
}

// ---------------------------------------------------------------------------
// Kernel 2: distance flash-attention, 128x128 CTA tile, 8x8/thread, f32x2.
// Smem (dynamic 132KB): Qt[64][132] k-major | Kt[64][132] k-major (=V^T) |
// Ps[128][132] natural. Swizzle: phys col = col ^ (row & 60).
// GEMM1 N-packed (dup-a), GEMM2 K-packed over keys (fold at end).
// ---------------------------------------------------------------------------
__global__ void __launch_bounds__(256, 1) k_attn()
{
    extern __shared__ float sm[];
    float* Qt = sm;            // 8448 words
    float* Kt = sm + 8448;     // 8448 words
    float* Ps = sm + 16896;    // 16896 words

    const int tid = threadIdx.x;
    const int ty = tid >> 4, tx = tid & 15;
    const int head = blockIdx.y;
    const int q0 = blockIdx.x * 128;
    const float* __restrict__ hp = g_hp + (size_t)head * (N_TOK * D_H);
    const float* __restrict__ ss = g_ss + (size_t)head * N_TOK;

    const float L2SQ = 2.0813689810056077f;   // (log2 e)^2
    const float QSC  = 2.0f * L2SQ;

    // Load Q tile (scaled), k-major transposed + swizzled
#pragma unroll
    for (int l = 0; l < 8; l++) {
        int idx = tid + l * 256;
        int r = idx >> 4;
        int c4 = (idx & 15) << 2;
        float4 v = *(const float4*)&hp[(size_t)(q0 + r) * D_H + c4];
        int col = r ^ c4;   // (c4+s)&60 == c4 for s<4
        Qt[(c4 + 0) * 132 + col] = v.x * QSC;
        Qt[(c4 + 1) * 132 + col] = v.y * QSC;
        Qt[(c4 + 2) * 132 + col] = v.z * QSC;
        Qt[(c4 + 3) * 132 + col] = v.w * QSC;
    }

    float qq2[8], m[8], ls[8];
    u64 O2[8][4];
#pragma unroll
    for (int i = 0; i < 8; i++) {
        qq2[i] = L2SQ * ss[q0 + 8 * ty + i];
        m[i] = -1e30f; ls[i] = 0.f;
#pragma unroll
        for (int d = 0; d < 4; d++) O2[i][d] = 0ull;
    }

    for (int kt = 0; kt < N_TOK; kt += 128) {
        __syncthreads();   // Kt/Ps free from previous tile

        float4 ka = *(const float4*)&ss[kt + 8 * tx];
        float4 kb4 = *(const float4*)&ss[kt + 8 * tx + 4];
        float kk2[8] = {ka.x * L2SQ, ka.y * L2SQ, ka.z * L2SQ, ka.w * L2SQ,
                        kb4.x * L2SQ, kb4.y * L2SQ, kb4.z * L2SQ, kb4.w * L2SQ};

        // Load K tile k-major transposed + swizzled (doubles as V^T)
#pragma unroll
        for (int l = 0; l < 8; l++) {
            int idx = tid + l * 256;
            int r = idx >> 4;
            int c4 = (idx & 15) << 2;
            float4 v = *(const float4*)&hp[(size_t)(kt + r) * D_H + c4];
            int col = r ^ c4;
            Kt[(c4 + 0) * 132 + col] = v.x;
            Kt[(c4 + 1) * 132 + col] = v.y;
            Kt[(c4 + 2) * 132 + col] = v.z;
            Kt[(c4 + 3) * 132 + col] = v.w;
        }
        __syncthreads();

        // ---- GEMM1: S = Qs . K^T, N-packed pairs over key cols ----
        u64 S2[8][4];
#pragma unroll
        for (int i = 0; i < 8; i++)
#pragma unroll
            for (int j = 0; j < 4; j++) S2[i][j] = 0ull;

#pragma unroll 4
        for (int k = 0; k < 64; k++) {
            int base = k * 132;
            int v = k & 60;
            int ao = (8 * ty) ^ v;
            int bo = (8 * tx) ^ v;
            float4 qA = *(const float4*)&Qt[base + ao];
            float4 qB = *(const float4*)&Qt[base + (ao ^ 4)];
            ulonglong2 B0 = *(const ulonglong2*)&Kt[base + bo];
            ulonglong2 B1 = *(const ulonglong2*)&Kt[base + (bo ^ 4)];
            u64 qd[8] = {dup2(qA.x), dup2(qA.y), dup2(qA.z), dup2(qA.w),
                         dup2(qB.x), dup2(qB.y), dup2(qB.z), dup2(qB.w)};
            u64 bb[4] = {B0.x, B0.y, B1.x, B1.y};
#pragma unroll
            for (int i = 0; i < 8; i++)
#pragma unroll
                for (int j = 0; j < 4; j++) fma2(S2[i][j], qd[i], bb[j]);
        }

        // ---- softmax epilogue (log2 domain) + write P ----
#pragma unroll
        for (int i = 0; i < 8; i++) {
            float s[8];
            float mx = -1e30f;
#pragma unroll
            for (int jj = 0; jj < 4; jj++) {
                float2 e = unp(S2[i][jj]);
                float sq0 = qq2[i] + kk2[2 * jj]     - e.x;
                float sq1 = qq2[i] + kk2[2 * jj + 1] - e.y;
                float s0 = (sq0 > 0.f) ? -sqrtapx(sq0) : 0.f;
                float s1 = (sq1 > 0.f) ? -sqrtapx(sq1) : 0.f;
                s[2 * jj] = s0; s[2 * jj + 1] = s1;
                mx = fmaxf(mx, fmaxf(s0, s1));
            }
#pragma unroll
            for (int w = 1; w < 16; w <<= 1)
                mx = fmaxf(mx, __shfl_xor_sync(0xffffffffu, mx, w, 16));
            float nm = fmaxf(m[i], mx);
            float sc = ex2f(m[i] - nm);
            m[i] = nm;
            float rs = 0.f;
#pragma unroll
            for (int c = 0; c < 8; c++) {
                float p = ex2f(s[c] - nm);
                s[c] = p; rs += p;
            }
#pragma unroll
            for (int w = 1; w < 16; w <<= 1)
                rs += __shfl_xor_sync(0xffffffffu, rs, w, 16);
            ls[i] = ls[i] * sc + rs;
            u64 scd = dup2(sc);
#pragma unroll
            for (int d = 0; d < 4; d++) mul2(O2[i][d], scd);

            int q = 8 * ty + i;
            int fo = (8 * tx) ^ (q & 60);
            *(float4*)&Ps[q * 132 + fo]       = make_float4(s[0], s[1], s[2], s[3]);
            *(float4*)&Ps[q * 132 + (fo ^ 4)] = make_float4(s[4], s[5], s[6], s[7]);
        }
        __syncthreads();

        // ---- GEMM2: O += P @ V, K-packed pairs over keys (Kt = V^T) ----
#pragma unroll 4
        for (int jq = 0; jq < 128; jq += 4) {
            u64 pa[8][2];
#pragma unroll
            for (int i = 0; i < 8; i++) {
                int q = 8 * ty + i;
                ulonglong2 t = *(const ulonglong2*)&Ps[q * 132 + (jq ^ (q & 60))];
                pa[i][0] = t.x; pa[i][1] = t.y;
            }
            u64 vb[4][2];
#pragma unroll
            for (int dd = 0; dd < 4; dd++) {
                int d = 4 * tx + dd;
                ulonglong2 t = *(const ulonglong2*)&Kt[d * 132 + (jq ^ (d & 60))];
                vb[dd][0] = t.x; vb[dd][1] = t.y;
            }
#pragma unroll
            for (int i = 0; i < 8; i++)
#pragma unroll
                for (int dd = 0; dd < 4; dd++) {
                    fma2(O2[i][dd], pa[i][0], vb[dd][0]);
                    fma2(O2[i][dd], pa[i][1], vb[dd][1]);
                }
        }
    }

    // fold pair-partials + normalize + store
#pragma unroll
    for (int i = 0; i < 8; i++) {
        float inv = 1.f / ls[i];
        float o[4];
#pragma unroll
        for (int dd = 0; dd < 4; dd++) {
            float2 e = unp(O2[i][dd]);
            o[dd] = (e.x + e.y) * inv;
        }
        *(float4*)&g_hh[((size_t)head * N_TOK + q0 + 8 * ty + i) * D_H + 4 * tx] =
            make_float4(o[0], o[1], o[2], o[3]);
    }
}

// ---------------------------------------------------------------------------
// Kernel 3: combine heads + LayerNorm + FC (unchanged)
// ---------------------------------------------------------------------------
__global__ void __launch_bounds__(256) k_final(const float* __restrict__ attn_w,
                                               const float* __restrict__ gamma,
                                               const float* __restrict__ beta,
                                               const float* __restrict__ fcw,
                                               const float* __restrict__ fcb,
                                               float* __restrict__ out)
{
    const int warp = threadIdx.x >> 5;
    const int lane = threadIdx.x & 31;
    const int row = blockIdx.x * 8 + warp;

    float a0 = attn_w[0], a1 = attn_w[1], a2 = attn_w[2], a3 = attn_w[3];
    float mx = fmaxf(fmaxf(a0, a1), fmaxf(a2, a3));
    float aw[4];
    aw[0] = __expf(a0 - mx); aw[1] = __expf(a1 - mx);
    aw[2] = __expf(a2 - mx); aw[3] = __expf(a3 - mx);
    float ainv = 1.f / (aw[0] + aw[1] + aw[2] + aw[3]);

    const int d0 = lane, d1 = lane + 32;
    float c0 = 0.f, c1 = 0.f;
#pragma unroll
    for (int h = 0; h < N_HEADS; h++) {
        const float* p = g_hh + ((size_t)h * N_TOK + row) * D_H;
        c0 += aw[h] * p[d0];
        c1 += aw[h] * p[d1];
    }
    c0 *= ainv; c1 *= ainv;

    float s = c0 + c1;
#pragma unroll
    for (int w = 16; w; w >>= 1) s += __shfl_xor_sync(0xffffffffu, s, w);
    float mu = s * (1.f / 64.f);
    float v0 = c0 - mu, v1 = c1 - mu;
    float vv = v0 * v0 + v1 * v1;
#pragma unroll
    for (int w = 16; w; w >>= 1) vv += __shfl_xor_sync(0xffffffffu, vv, w);
    float inv = rsqrtf(vv * (1.f / 64.f) + LN_EPS);
    float n0 = v0 * inv * gamma[d0] + beta[d0];
    float n1 = v1 * inv * gamma[d1] + beta[d1];

    float o[N_CLS];
#pragma unroll
    for (int c = 0; c < N_CLS; c++)
        o[c] = n0 * fcw[d0 * N_CLS + c] + n1 * fcw[d1 * N_CLS + c];
#pragma unroll
    for (int c = 0; c < N_CLS; c++)
#pragma unroll
        for (int w = 16; w; w >>= 1) o[c] += __shfl_xor_sync(0xffffffffu, o[c], w);

    if (lane == 0) {
#pragma unroll
        for (int c = 0; c < N_CLS; c++)
            out[(size_t)row * N_CLS + c] = o[c] + fcb[c];
    }
}

// ---------------------------------------------------------------------------
extern "C" void kernel_launch(void* const* d_in, const int* in_sizes, int n_in,
                              void* d_out, int out_size)
{
    const float* x      = (const float*)d_in[0];
    const float* proj_w = (const float*)d_in[1];
    const float* proj_b = (const float*)d_in[2];
    const float* head_w = (const float*)d_in[3];
    const float* head_b = (const float*)d_in[4];
    const float* attn_w = (const float*)d_in[5];
    const float* gamma  = (const float*)d_in[6];
    const float* beta   = (const float*)d_in[7];
    const float* fc_w   = (const float*)d_in[8];
    const float* fc_b   = (const float*)d_in[9];
    float* out = (float*)d_out;

    static int smem_set = 0;
    if (!smem_set) {
        cudaFuncSetAttribute(k_attn, cudaFuncAttributeMaxDynamicSharedMemorySize,
                             33792 * (int)sizeof(float));
        smem_set = 1;
    }

    k_proj<<<N_TOK / 64, 256>>>(x, proj_w, proj_b, head_w, head_b);

    dim3 g2(N_TOK / 128, N_HEADS);
    k_attn<<<g2, 256, 33792 * sizeof(float)>>>();

    k_final<<<N_TOK / 8, 256>>>(attn_w, gamma, beta, fc_w, fc_b, out);
}

// round 5
// speedup vs baseline: 2.9496x; 1.8339x over previous
#include <cuda_runtime.h>
#include <cuda_bf16.h>
#include <cstdint>
#include <cstddef>

#define N_TOK   8192
#define D_IN    384
#define D_H     64
#define N_HEADS 4
#define N_CLS   6
#define LN_EPS  1e-5f

// ---------------- scratch (no allocations allowed) ----------------
__device__ float g_hp[(size_t)N_HEADS * N_TOK * D_H];
__device__ float g_ss[(size_t)N_HEADS * N_TOK];
__device__ float g_hh[(size_t)N_HEADS * N_TOK * D_H];
// padded bf16 tile images, stored as u32 (2 bf16):
//  K image per tile: 128 rows x 36 u32 (72 bf16, d 0..63 + pad)   = 4608 u32
//  Vt image per tile: 64 d-rows x 68 u32 (136 bf16, key 0..127+pad) = 4352 u32
__device__ __align__(256) uint32_t g_khi[(size_t)N_HEADS * 64 * 4608];
__device__ __align__(256) uint32_t g_klo[(size_t)N_HEADS * 64 * 4608];
__device__ __align__(256) uint32_t g_vhi[(size_t)N_HEADS * 64 * 4352];
__device__ __align__(256) uint32_t g_vlo[(size_t)N_HEADS * 64 * 4352];

// ---------------- helpers ----------------
__device__ __forceinline__ uint32_t smem_u32(const void* p) {
    uint32_t a;
    asm("{ .reg .u64 t; cvta.to.shared.u64 t, %1; cvt.u32.u64 %0, t; }" : "=r"(a) : "l"(p));
    return a;
}
__device__ __forceinline__ float ex2f(float x) {
    float r; asm("ex2.approx.f32 %0, %1;" : "=f"(r) : "f"(x)); return r;
}
__device__ __forceinline__ float sqrtapx(float x) {
    float r; asm("sqrt.approx.f32 %0, %1;" : "=f"(r) : "f"(x)); return r;
}
__device__ __forceinline__ uint32_t pack_bf2(__nv_bfloat16 a, __nv_bfloat16 b) {
    __nv_bfloat162 t; t.x = a; t.y = b;
    return *reinterpret_cast<uint32_t*>(&t);
}
__device__ __forceinline__ void pack_hl(float x, float y, uint32_t &hi, uint32_t &lo) {
    __nv_bfloat16 hx = __float2bfloat16(x), hy = __float2bfloat16(y);
    hi = pack_bf2(hx, hy);
    lo = pack_bf2(__float2bfloat16(x - __bfloat162float(hx)),
                  __float2bfloat16(y - __bfloat162float(hy)));
}
__device__ __forceinline__ void mma16816(float c[4], const uint32_t a[4], uint32_t b0, uint32_t b1) {
    asm volatile("mma.sync.aligned.m16n8k16.row.col.f32.bf16.bf16.f32 "
        "{%0,%1,%2,%3}, {%4,%5,%6,%7}, {%8,%9}, {%0,%1,%2,%3};"
        : "+f"(c[0]), "+f"(c[1]), "+f"(c[2]), "+f"(c[3])
        : "r"(a[0]), "r"(a[1]), "r"(a[2]), "r"(a[3]), "r"(b0), "r"(b1));
}
__device__ __forceinline__ void ldsm4(uint32_t r[4], uint32_t addr) {
    asm volatile("ldmatrix.sync.aligned.m8n8.x4.shared.b16 {%0,%1,%2,%3}, [%4];"
        : "=r"(r[0]), "=r"(r[1]), "=r"(r[2]), "=r"(r[3]) : "r"(addr));
}

#define MBARRIER_INIT(addr, cnt) \
    asm volatile("mbarrier.init.shared.b64 [%0], %1;" :: "r"((uint32_t)(addr)), "r"((uint32_t)(cnt)) : "memory")
#define MBARRIER_EXPECT_TX(addr, tx) \
    asm volatile("mbarrier.arrive.expect_tx.shared.b64 _, [%0], %1;" :: "r"((uint32_t)(addr)), "r"((uint32_t)(tx)) : "memory")
#define MBARRIER_WAIT_PARITY(addr, par) do {                                     \
    uint32_t _m = (uint32_t)(addr); uint32_t _p = (uint32_t)(par); uint32_t _d;  \
    asm volatile("{\n\t.reg .pred p;\n\t"                                        \
        "mbarrier.try_wait.parity.acquire.cta.shared::cta.b64 p, [%1], %2;\n\t"  \
        "selp.b32 %0, 1, 0, p;\n\t}" : "=r"(_d) : "r"(_m), "r"(_p) : "memory");  \
    if (!_d) {                                                                   \
        asm volatile("{\n\t.reg .pred P1;\n\t"                                   \
            "WL_%=:\n\t"                                                         \
            "mbarrier.try_wait.parity.acquire.cta.shared::cta.b64 P1, [%0], %1, 0x989680;\n\t" \
            "@P1 bra.uni WD_%=;\n\t"                                             \
            "bra.uni WL_%=;\n\t"                                                 \
            "WD_%=:\n\t}" :: "r"(_m), "r"(_p) : "memory");                       \
    }                                                                            \
} while (0)

__device__ __forceinline__ void bulk_g2s(uint32_t dst, const void* src, uint32_t bytes, uint32_t mbar) {
    asm volatile("cp.async.bulk.shared::cta.global.mbarrier::complete_tx::bytes [%0], [%1], %2, [%3];"
        :: "r"(dst), "l"(src), "r"(bytes), "r"(mbar) : "memory");
}

// ---------------------------------------------------------------------------
// Kernel 1: proj + head projections + sumsq (unchanged, ~35us)
// ---------------------------------------------------------------------------
__global__ void __launch_bounds__(256) k_proj(const float* __restrict__ x,
                                              const float* __restrict__ pw,
                                              const float* __restrict__ pb,
                                              const float* __restrict__ hw,
                                              const float* __restrict__ hb)
{
    __shared__ float As[64 * 68];
    __shared__ float Ws[64 * 64];
    const int tid = threadIdx.x;
    const int ty = tid >> 4, tx = tid & 15;
    const int row0 = blockIdx.x * 64;

    float acc[4][4];
#pragma unroll
    for (int i = 0; i < 4; i++)
#pragma unroll
        for (int j = 0; j < 4; j++) acc[i][j] = 0.f;

    for (int kk = 0; kk < D_IN; kk += 64) {
#pragma unroll
        for (int l = 0; l < 4; l++) {
            int idx = tid + l * 256;
            int r = idx >> 4, c = (idx & 15) << 2;
            *(float4*)&As[r * 68 + c] = *(const float4*)&x[(size_t)(row0 + r) * D_IN + kk + c];
            *(float4*)&Ws[r * 64 + c] = *(const float4*)&pw[(size_t)(kk + r) * D_H + c];
        }
        __syncthreads();
#pragma unroll 8
        for (int k = 0; k < 64; k++) {
            float a0 = As[(4 * ty + 0) * 68 + k];
            float a1 = As[(4 * ty + 1) * 68 + k];
            float a2 = As[(4 * ty + 2) * 68 + k];
            float a3 = As[(4 * ty + 3) * 68 + k];
            float4 b = *(const float4*)&Ws[k * 64 + 4 * tx];
            acc[0][0] += a0 * b.x; acc[0][1] += a0 * b.y; acc[0][2] += a0 * b.z; acc[0][3] += a0 * b.w;
            acc[1][0] += a1 * b.x; acc[1][1] += a1 * b.y; acc[1][2] += a1 * b.z; acc[1][3] += a1 * b.w;
            acc[2][0] += a2 * b.x; acc[2][1] += a2 * b.y; acc[2][2] += a2 * b.z; acc[2][3] += a2 * b.w;
            acc[3][0] += a3 * b.x; acc[3][1] += a3 * b.y; acc[3][2] += a3 * b.z; acc[3][3] += a3 * b.w;
        }
        __syncthreads();
    }
    {
        float4 pbv = *(const float4*)&pb[4 * tx];
        float pbz[4] = {pbv.x, pbv.y, pbv.z, pbv.w};
#pragma unroll
        for (int i = 0; i < 4; i++)
#pragma unroll
            for (int j = 0; j < 4; j++)
                As[(4 * ty + i) * 68 + 4 * tx + j] = fmaxf(acc[i][j] + pbz[j], 0.f);
    }
    __syncthreads();

    for (int h = 0; h < N_HEADS; h++) {
#pragma unroll
        for (int l = 0; l < 4; l++) {
            int idx = tid + l * 256;
            int r = idx >> 4, c = (idx & 15) << 2;
            *(float4*)&Ws[r * 64 + c] = *(const float4*)&hw[((size_t)h * 64 + r) * 64 + c];
        }
        __syncthreads();

        float a2c[4][4];
#pragma unroll
        for (int i = 0; i < 4; i++)
#pragma unroll
            for (int j = 0; j < 4; j++) a2c[i][j] = 0.f;

#pragma unroll 8
        for (int k = 0; k < 64; k++) {
            float a0 = As[(4 * ty + 0) * 68 + k];
            float a1 = As[(4 * ty + 1) * 68 + k];
            float a2 = As[(4 * ty + 2) * 68 + k];
            float a3 = As[(4 * ty + 3) * 68 + k];
            float4 b = *(const float4*)&Ws[k * 64 + 4 * tx];
            a2c[0][0] += a0 * b.x; a2c[0][1] += a0 * b.y; a2c[0][2] += a0 * b.z; a2c[0][3] += a0 * b.w;
            a2c[1][0] += a1 * b.x; a2c[1][1] += a1 * b.y; a2c[1][2] += a1 * b.z; a2c[1][3] += a1 * b.w;
            a2c[2][0] += a2 * b.x; a2c[2][1] += a2 * b.y; a2c[2][2] += a2 * b.z; a2c[2][3] += a2 * b.w;
            a2c[3][0] += a3 * b.x; a2c[3][1] += a3 * b.y; a2c[3][2] += a3 * b.z; a2c[3][3] += a3 * b.w;
        }

        float4 hbv = *(const float4*)&hb[h * 64 + 4 * tx];
        float hbz[4] = {hbv.x, hbv.y, hbv.z, hbv.w};
#pragma unroll
        for (int i = 0; i < 4; i++) {
            float v0 = a2c[i][0] + hbz[0];
            float v1 = a2c[i][1] + hbz[1];
            float v2 = a2c[i][2] + hbz[2];
            float v3 = a2c[i][3] + hbz[3];
            float rs = v0 * v0 + v1 * v1 + v2 * v2 + v3 * v3;
            *(float4*)&g_hp[((size_t)h * N_TOK + row0 + 4 * ty + i) * D_H + 4 * tx] =
                make_float4(v0, v1, v2, v3);
#pragma unroll
            for (int w = 1; w < 16; w <<= 1)
                rs += __shfl_xor_sync(0xffffffffu, rs, w, 16);
            if (tx == 0) g_ss[(size_t)h * N_TOK + row0 + 4 * ty + i] = rs;
        }
        __syncthreads();
    }
}

// ---------------------------------------------------------------------------
// Kernel 1b: build padded bf16 hi/lo tile images for ldmatrix-friendly layouts.
//   K image: [128 keys][72 bf16] (d-major rows, stride 144B = 9 granules)
//   Vt image: [64 d][136 bf16]   (key-major rows, stride 272B = 17 granules)
// ---------------------------------------------------------------------------
__global__ void __launch_bounds__(128) k_prep()
{
    __shared__ float tile[128][65];
    const int t = blockIdx.x, head = blockIdx.y, tid = threadIdx.x;

    const float* src = g_hp + ((size_t)head * N_TOK + (size_t)t * 128 + tid) * 64;
    uint32_t* kh = g_khi + ((size_t)head * 64 + t) * 4608;
    uint32_t* kl = g_klo + ((size_t)head * 64 + t) * 4608;
#pragma unroll 8
    for (int m = 0; m < 32; m++) {
        float f0 = src[2 * m], f1 = src[2 * m + 1];
        tile[tid][2 * m] = f0;
        tile[tid][2 * m + 1] = f1;
        __nv_bfloat16 h0 = __float2bfloat16(f0), h1 = __float2bfloat16(f1);
        kh[tid * 36 + m] = pack_bf2(h0, h1);
        kl[tid * 36 + m] = pack_bf2(__float2bfloat16(f0 - __bfloat162float(h0)),
                                    __float2bfloat16(f1 - __bfloat162float(h1)));
    }
    __syncthreads();

    uint32_t* vh = g_vhi + ((size_t)head * 64 + t) * 4352;
    uint32_t* vl = g_vlo + ((size_t)head * 64 + t) * 4352;
    const int d = tid >> 1, half = tid & 1;
#pragma unroll 8
    for (int m = 0; m < 32; m++) {
        int key = half * 64 + 2 * m;
        float f0 = tile[key][d], f1 = tile[key + 1][d];
        __nv_bfloat16 h0 = __float2bfloat16(f0), h1 = __float2bfloat16(f1);
        vh[d * 68 + half * 32 + m] = pack_bf2(h0, h1);
        vl[d * 68 + half * 32 + m] = pack_bf2(__float2bfloat16(f0 - __bfloat162float(h0)),
                                              __float2bfloat16(f1 - __bfloat162float(h1)));
    }
}

// ---------------------------------------------------------------------------
// Kernel 2: distance flash-attention via mma.sync.m16n8k16 bf16 (hi/lo split).
// Softmax max is identically 0 (diagonal dist = 0): no online rescale.
// Diagonal p forced to exactly 1 (kills bf16 cancellation error on the
// dominant weight). Double-buffered cp.async.bulk tile loads.
// ---------------------------------------------------------------------------
#define SM_MBAR0   0
#define SM_MBAR1   8
#define SM_QHI     128
#define SM_QLO     (SM_QHI + 18432)          // 18560
#define SM_STG     36992
#define STG_BYTES  72192
#define OFF_KHI    0
#define OFF_KLO    18432
#define OFF_VHI    36864
#define OFF_VLO    54272
#define OFF_KK     71680
#define SM_TOTAL   (SM_STG + 2 * STG_BYTES)  // 181376

__global__ void __launch_bounds__(256, 1) k_attn()
{
    extern __shared__ char smem[];
    const uint32_t sb = smem_u32(smem);
    const int tid  = threadIdx.x;
    const int warp = tid >> 5;
    const int lane = tid & 31;
    const int g  = lane >> 2;    // 0..7
    const int lt = lane & 3;     // 0..3
    const int mm = lane >> 3;    // ldmatrix matrix index 0..3
    const int r8 = lane & 7;
    const int head = blockIdx.y;
    const int q0 = blockIdx.x * 128;

    if (tid == 0) {
        MBARRIER_INIT(sb + SM_MBAR0, 1);
        MBARRIER_INIT(sb + SM_MBAR1, 1);
    }

    // copy Q tile images (this q-block's K images) into smem
    {
        const uint4* sh = (const uint4*)(g_khi + ((size_t)head * 64 + blockIdx.x) * 4608);
        const uint4* sl = (const uint4*)(g_klo + ((size_t)head * 64 + blockIdx.x) * 4608);
        uint4* dh = (uint4*)(smem + SM_QHI);
        uint4* dl = (uint4*)(smem + SM_QLO);
#pragma unroll
        for (int i = tid; i < 1152; i += 256) { dh[i] = sh[i]; dl[i] = sl[i]; }
    }
    __syncthreads();

    // first tile load
    if (tid == 0) {
        const size_t tb = (size_t)head * 64;
        MBARRIER_EXPECT_TX(sb + SM_MBAR0, STG_BYTES);
        bulk_g2s(sb + SM_STG + OFF_KHI, g_khi + tb * 4608, 18432, sb + SM_MBAR0);
        bulk_g2s(sb + SM_STG + OFF_KLO, g_klo + tb * 4608, 18432, sb + SM_MBAR0);
        bulk_g2s(sb + SM_STG + OFF_VHI, g_vhi + tb * 4352, 17408, sb + SM_MBAR0);
        bulk_g2s(sb + SM_STG + OFF_VLO, g_vlo + tb * 4352, 17408, sb + SM_MBAR0);
        bulk_g2s(sb + SM_STG + OFF_KK, g_ss + (size_t)head * N_TOK, 512, sb + SM_MBAR0);
    }

    const float* ssq = g_ss + (size_t)head * N_TOK;
    const int r0g = q0 + 16 * warp + g;
    const int r1g = r0g + 8;
    const float qq0 = ssq[r0g];
    const float qq1 = ssq[r1g];
    const float NL2E = -1.4426950408889634f;

    float O[8][4];
#pragma unroll
    for (int n = 0; n < 8; n++)
#pragma unroll
        for (int e = 0; e < 4; e++) O[n][e] = 0.f;
    float l0 = 0.f, l1 = 0.f;

    // precomputed ldmatrix lane-address components
    const int q_row = 16 * warp + r8 + (mm & 1) * 8;       // A-frag rows
    const int k_rowofs = r8 + (mm >> 1) * 8;               // B-frag rows (key)
    const int q_dsel = (mm >> 1) * 16;                     // A dofs part (bytes)
    const int k_dsel = (mm & 1) * 16;                      // B dofs part (bytes)

    for (int t = 0; t < 64; t++) {
        const int s = t & 1;
        // prefetch next tile into the other stage (freed at end of iter t-1)
        if (tid == 0 && t + 1 < 64) {
            const uint32_t mb = sb + ((t + 1) & 1 ? SM_MBAR1 : SM_MBAR0);
            const uint32_t st = sb + SM_STG + ((t + 1) & 1) * STG_BYTES;
            const size_t tb = (size_t)head * 64 + (t + 1);
            MBARRIER_EXPECT_TX(mb, STG_BYTES);
            bulk_g2s(st + OFF_KHI, g_khi + tb * 4608, 18432, mb);
            bulk_g2s(st + OFF_KLO, g_klo + tb * 4608, 18432, mb);
            bulk_g2s(st + OFF_VHI, g_vhi + tb * 4352, 17408, mb);
            bulk_g2s(st + OFF_VLO, g_vlo + tb * 4352, 17408, mb);
            bulk_g2s(st + OFF_KK, ssq + (size_t)(t + 1) * 128, 512, mb);
        }
        MBARRIER_WAIT_PARITY(sb + (s ? SM_MBAR1 : SM_MBAR0), (t >> 1) & 1);

        const uint32_t stg = sb + SM_STG + s * STG_BYTES;

        // ---- GEMM1: S = Q.K^T (hi*hi + lo*hi + hi*lo) ----
        float S[16][4];
#pragma unroll
        for (int n = 0; n < 16; n++)
#pragma unroll
            for (int e = 0; e < 4; e++) S[n][e] = 0.f;

#pragma unroll
        for (int kc = 0; kc < 4; kc++) {
            uint32_t qh[4], ql[4];
            uint32_t qa = sb + SM_QHI + q_row * 144 + kc * 32 + q_dsel;
            ldsm4(qh, qa);
            ldsm4(ql, qa + 18432);
#pragma unroll
            for (int np = 0; np < 8; np++) {
                uint32_t kb[4], lb[4];
                uint32_t ka = stg + OFF_KHI + (16 * np + k_rowofs) * 144 + kc * 32 + k_dsel;
                ldsm4(kb, ka);
                ldsm4(lb, ka + 18432);
                mma16816(S[2 * np],     qh, kb[0], kb[1]);
                mma16816(S[2 * np],     ql, kb[0], kb[1]);
                mma16816(S[2 * np],     qh, lb[0], lb[1]);
                mma16816(S[2 * np + 1], qh, kb[2], kb[3]);
                mma16816(S[2 * np + 1], ql, kb[2], kb[3]);
                mma16816(S[2 * np + 1], qh, lb[2], lb[3]);
            }
        }

        // ---- softmax weights (max == 0 structurally) ----
        const float* kkp = (const float*)(smem + SM_STG + s * STG_BYTES + OFF_KK);
        const int kt = t * 128;
#pragma unroll
        for (int nt = 0; nt < 16; nt++) {
            const int colg = kt + 8 * nt + 2 * lt;
            float2 kkv = *(const float2*)(kkp + 8 * nt + 2 * lt);
            float sq00 = qq0 + kkv.x - 2.f * S[nt][0];
            float sq01 = qq0 + kkv.y - 2.f * S[nt][1];
            float sq10 = qq1 + kkv.x - 2.f * S[nt][2];
            float sq11 = qq1 + kkv.y - 2.f * S[nt][3];
            S[nt][0] = (colg == r0g     || sq00 <= 0.f) ? 1.f : ex2f(NL2E * sqrtapx(sq00));
            S[nt][1] = (colg + 1 == r0g || sq01 <= 0.f) ? 1.f : ex2f(NL2E * sqrtapx(sq01));
            S[nt][2] = (colg == r1g     || sq10 <= 0.f) ? 1.f : ex2f(NL2E * sqrtapx(sq10));
            S[nt][3] = (colg + 1 == r1g || sq11 <= 0.f) ? 1.f : ex2f(NL2E * sqrtapx(sq11));
            l0 += S[nt][0] + S[nt][1];
            l1 += S[nt][2] + S[nt][3];
        }

        // ---- GEMM2: O += P.V (Phi*Vhi + Plo*Vhi + Phi*Vlo) ----
#pragma unroll
        for (int kc2 = 0; kc2 < 8; kc2++) {
            uint32_t aH[4], aL[4];
            pack_hl(S[2 * kc2][0],     S[2 * kc2][1],     aH[0], aL[0]);
            pack_hl(S[2 * kc2][2],     S[2 * kc2][3],     aH[1], aL[1]);
            pack_hl(S[2 * kc2 + 1][0], S[2 * kc2 + 1][1], aH[2], aL[2]);
            pack_hl(S[2 * kc2 + 1][2], S[2 * kc2 + 1][3], aH[3], aL[3]);
#pragma unroll
            for (int j = 0; j < 4; j++) {
                uint32_t vb[4], wb[4];
                uint32_t va = stg + OFF_VHI + (16 * j + k_rowofs) * 272 + kc2 * 32 + k_dsel;
                ldsm4(vb, va);
                ldsm4(wb, va + 17408);
                mma16816(O[2 * j],     aH, vb[0], vb[1]);
                mma16816(O[2 * j],     aL, vb[0], vb[1]);
                mma16816(O[2 * j],     aH, wb[0], wb[1]);
                mma16816(O[2 * j + 1], aH, vb[2], vb[3]);
                mma16816(O[2 * j + 1], aL, vb[2], vb[3]);
                mma16816(O[2 * j + 1], aH, wb[2], wb[3]);
            }
        }
        __syncthreads();   // stage s fully consumed -> safe to overwrite next iter
    }

    // reduce l over the 4 lanes sharing each row, normalize, store
    l0 += __shfl_xor_sync(0xffffffffu, l0, 1);
    l0 += __shfl_xor_sync(0xffffffffu, l0, 2);
    l1 += __shfl_xor_sync(0xffffffffu, l1, 1);
    l1 += __shfl_xor_sync(0xffffffffu, l1, 2);
    const float inv0 = 1.f / l0, inv1 = 1.f / l1;

    float* dst0 = g_hh + ((size_t)head * N_TOK + r0g) * D_H;
    float* dst1 = g_hh + ((size_t)head * N_TOK + r1g) * D_H;
#pragma unroll
    for (int n = 0; n < 8; n++) {
        *(float2*)&dst0[8 * n + 2 * lt] = make_float2(O[n][0] * inv0, O[n][1] * inv0);
        *(float2*)&dst1[8 * n + 2 * lt] = make_float2(O[n][2] * inv1, O[n][3] * inv1);
    }
}

// ---------------------------------------------------------------------------
// Kernel 3: combine heads + LayerNorm + FC (unchanged)
// ---------------------------------------------------------------------------
__global__ void __launch_bounds__(256) k_final(const float* __restrict__ attn_w,
                                               const float* __restrict__ gamma,
                                               const float* __restrict__ beta,
                                               const float* __restrict__ fcw,
                                               const float* __restrict__ fcb,
                                               float* __restrict__ out)
{
    const int warp = threadIdx.x >> 5;
    const int lane = threadIdx.x & 31;
    const int row = blockIdx.x * 8 + warp;

    float a0 = attn_w[0], a1 = attn_w[1], a2 = attn_w[2], a3 = attn_w[3];
    float mx = fmaxf(fmaxf(a0, a1), fmaxf(a2, a3));
    float aw[4];
    aw[0] = __expf(a0 - mx); aw[1] = __expf(a1 - mx);
    aw[2] = __expf(a2 - mx); aw[3] = __expf(a3 - mx);
    float ainv = 1.f / (aw[0] + aw[1] + aw[2] + aw[3]);

    const int d0 = lane, d1 = lane + 32;
    float c0 = 0.f, c1 = 0.f;
#pragma unroll
    for (int h = 0; h < N_HEADS; h++) {
        const float* p = g_hh + ((size_t)h * N_TOK + row) * D_H;
        c0 += aw[h] * p[d0];
        c1 += aw[h] * p[d1];
    }
    c0 *= ainv; c1 *= ainv;

    float s = c0 + c1;
#pragma unroll
    for (int w = 16; w; w >>= 1) s += __shfl_xor_sync(0xffffffffu, s, w);
    float mu = s * (1.f / 64.f);
    float v0 = c0 - mu, v1 = c1 - mu;
    float vv = v0 * v0 + v1 * v1;
#pragma unroll
    for (int w = 16; w; w >>= 1) vv += __shfl_xor_sync(0xffffffffu, vv, w);
    float inv = rsqrtf(vv * (1.f / 64.f) + LN_EPS);
    float n0 = v0 * inv * gamma[d0] + beta[d0];
    float n1 = v1 * inv * gamma[d1] + beta[d1];

    float o[N_CLS];
#pragma unroll
    for (int c = 0; c < N_CLS; c++)
        o[c] = n0 * fcw[d0 * N_CLS + c] + n1 * fcw[d1 * N_CLS + c];
#pragma unroll
    for (int c = 0; c < N_CLS; c++)
#pragma unroll
        for (int w = 16; w; w >>= 1) o[c] += __shfl_xor_sync(0xffffffffu, o[c], w);

    if (lane == 0) {
#pragma unroll
        for (int c = 0; c < N_CLS; c++)
            out[(size_t)row * N_CLS + c] = o[c] + fcb[c];
    }
}

// ---------------------------------------------------------------------------
extern "C" void kernel_launch(void* const* d_in, const int* in_sizes, int n_in,
                              void* d_out, int out_size)
{
    const float* x      = (const float*)d_in[0];
    const float* proj_w = (const float*)d_in[1];
    const float* proj_b = (const float*)d_in[2];
    const float* head_w = (const float*)d_in[3];
    const float* head_b = (const float*)d_in[4];
    const float* attn_w = (const float*)d_in[5];
    const float* gamma  = (const float*)d_in[6];
    const float* beta   = (const float*)d_in[7];
    const float* fc_w   = (const float*)d_in[8];
    const float* fc_b   = (const float*)d_in[9];
    float* out = (float*)d_out;

    static int smem_set = 0;
    if (!smem_set) {
        cudaFuncSetAttribute(k_attn, cudaFuncAttributeMaxDynamicSharedMemorySize, SM_TOTAL);
        smem_set = 1;
    }

    k_proj<<<N_TOK / 64, 256>>>(x, proj_w, proj_b, head_w, head_b);

    dim3 gp(64, N_HEADS);
    k_prep<<<gp, 128>>>();

    dim3 g2(N_TOK / 128, N_HEADS);
    k_attn<<<g2, 256, SM_TOTAL>>>();

    k_final<<<N_TOK / 8, 256>>>(attn_w, gamma, beta, fc_w, fc_b, out);
}

// round 6
// speedup vs baseline: 3.6087x; 1.2235x over previous
#include <cuda_runtime.h>
#include <cuda_bf16.h>
#include <cuda_fp16.h>
#include <cstdint>
#include <cstddef>

#define N_TOK   8192
#define D_IN    384
#define D_H     64
#define N_HEADS 4
#define N_CLS   6
#define LN_EPS  1e-5f

// ---------------- scratch (no allocations allowed) ----------------
__device__ float g_hp[(size_t)N_HEADS * N_TOK * D_H];
__device__ float g_ss[(size_t)N_HEADS * N_TOK];
__device__ float g_hh[(size_t)N_HEADS * N_TOK * D_H];
// padded tile images, stored as u32 (2 halves):
//  K image per tile: 128 rows x 36 u32 (72 bf16: d 0..63 + pad)    = 4608 u32
//  Vt image per tile: 64 d-rows x 68 u32 (136 fp16: key 0..127+pad) = 4352 u32
__device__ __align__(256) uint32_t g_khi[(size_t)N_HEADS * 64 * 4608];
__device__ __align__(256) uint32_t g_klo[(size_t)N_HEADS * 64 * 4608];
__device__ __align__(256) uint32_t g_v16[(size_t)N_HEADS * 64 * 4352];

// ---------------- helpers ----------------
__device__ __forceinline__ uint32_t smem_u32(const void* p) {
    uint32_t a;
    asm("{ .reg .u64 t; cvta.to.shared.u64 t, %1; cvt.u32.u64 %0, t; }" : "=r"(a) : "l"(p));
    return a;
}
__device__ __forceinline__ float ex2f(float x) {
    float r; asm("ex2.approx.f32 %0, %1;" : "=f"(r) : "f"(x)); return r;
}
__device__ __forceinline__ float sqrtapx(float x) {
    float r; asm("sqrt.approx.f32 %0, %1;" : "=f"(r) : "f"(x)); return r;
}
__device__ __forceinline__ uint32_t pack_bf2(__nv_bfloat16 a, __nv_bfloat16 b) {
    __nv_bfloat162 t; t.x = a; t.y = b;
    return *reinterpret_cast<uint32_t*>(&t);
}
// pack (lo,hi) floats into one u32 of two fp16
__device__ __forceinline__ uint32_t f16pack(float lo, float hi) {
    uint32_t r; asm("cvt.rn.f16x2.f32 %0, %1, %2;" : "=r"(r) : "f"(hi), "f"(lo)); return r;
}
__device__ __forceinline__ void mma16816b(float c[4], const uint32_t a[4], uint32_t b0, uint32_t b1) {
    asm volatile("mma.sync.aligned.m16n8k16.row.col.f32.bf16.bf16.f32 "
        "{%0,%1,%2,%3}, {%4,%5,%6,%7}, {%8,%9}, {%0,%1,%2,%3};"
        : "+f"(c[0]), "+f"(c[1]), "+f"(c[2]), "+f"(c[3])
        : "r"(a[0]), "r"(a[1]), "r"(a[2]), "r"(a[3]), "r"(b0), "r"(b1));
}
__device__ __forceinline__ void mma16816h(float c[4], const uint32_t a[4], uint32_t b0, uint32_t b1) {
    asm volatile("mma.sync.aligned.m16n8k16.row.col.f32.f16.f16.f32 "
        "{%0,%1,%2,%3}, {%4,%5,%6,%7}, {%8,%9}, {%0,%1,%2,%3};"
        : "+f"(c[0]), "+f"(c[1]), "+f"(c[2]), "+f"(c[3])
        : "r"(a[0]), "r"(a[1]), "r"(a[2]), "r"(a[3]), "r"(b0), "r"(b1));
}
__device__ __forceinline__ void ldsm4(uint32_t r[4], uint32_t addr) {
    asm volatile("ldmatrix.sync.aligned.m8n8.x4.shared.b16 {%0,%1,%2,%3}, [%4];"
        : "=r"(r[0]), "=r"(r[1]), "=r"(r[2]), "=r"(r[3]) : "r"(addr));
}

#define MBARRIER_INIT(addr, cnt) \
    asm volatile("mbarrier.init.shared.b64 [%0], %1;" :: "r"((uint32_t)(addr)), "r"((uint32_t)(cnt)) : "memory")
#define MBARRIER_EXPECT_TX(addr, tx) \
    asm volatile("mbarrier.arrive.expect_tx.shared.b64 _, [%0], %1;" :: "r"((uint32_t)(addr)), "r"((uint32_t)(tx)) : "memory")
#define MBARRIER_ARRIVE(addr) \
    asm volatile("mbarrier.arrive.shared.b64 _, [%0];" :: "r"((uint32_t)(addr)) : "memory")
#define MBARRIER_WAIT_PARITY(addr, par) do {                                     \
    uint32_t _m = (uint32_t)(addr); uint32_t _p = (uint32_t)(par); uint32_t _d;  \
    asm volatile("{\n\t.reg .pred p;\n\t"                                        \
        "mbarrier.try_wait.parity.acquire.cta.shared::cta.b64 p, [%1], %2;\n\t"  \
        "selp.b32 %0, 1, 0, p;\n\t}" : "=r"(_d) : "r"(_m), "r"(_p) : "memory");  \
    if (!_d) {                                                                   \
        asm volatile("{\n\t.reg .pred P1;\n\t"                                   \
            "WL_%=:\n\t"                                                         \
            "mbarrier.try_wait.parity.acquire.cta.shared::cta.b64 P1, [%0], %1, 0x989680;\n\t" \
            "@P1 bra.uni WD_%=;\n\t"                                             \
            "bra.uni WL_%=;\n\t"                                                 \
            "WD_%=:\n\t}" :: "r"(_m), "r"(_p) : "memory");                       \
    }                                                                            \
} while (0)

__device__ __forceinline__ void bulk_g2s(uint32_t dst, const void* src, uint32_t bytes, uint32_t mbar) {
    asm volatile("cp.async.bulk.shared::cta.global.mbarrier::complete_tx::bytes [%0], [%1], %2, [%3];"
        :: "r"(dst), "l"(src), "r"(bytes), "r"(mbar) : "memory");
}

// ---------------------------------------------------------------------------
// Kernel 1: proj + head projections + sumsq (unchanged, ~35us)
// ---------------------------------------------------------------------------
__global__ void __launch_bounds__(256) k_proj(const float* __restrict__ x,
                                              const float* __restrict__ pw,
                                              const float* __restrict__ pb,
                                              const float* __restrict__ hw,
                                              const float* __restrict__ hb)
{
    __shared__ float As[64 * 68];
    __shared__ float Ws[64 * 64];
    const int tid = threadIdx.x;
    const int ty = tid >> 4, tx = tid & 15;
    const int row0 = blockIdx.x * 64;

    float acc[4][4];
#pragma unroll
    for (int i = 0; i < 4; i++)
#pragma unroll
        for (int j = 0; j < 4; j++) acc[i][j] = 0.f;

    for (int kk = 0; kk < D_IN; kk += 64) {
#pragma unroll
        for (int l = 0; l < 4; l++) {
            int idx = tid + l * 256;
            int r = idx >> 4, c = (idx & 15) << 2;
            *(float4*)&As[r * 68 + c] = *(const float4*)&x[(size_t)(row0 + r) * D_IN + kk + c];
            *(float4*)&Ws[r * 64 + c] = *(const float4*)&pw[(size_t)(kk + r) * D_H + c];
        }
        __syncthreads();
#pragma unroll 8
        for (int k = 0; k < 64; k++) {
            float a0 = As[(4 * ty + 0) * 68 + k];
            float a1 = As[(4 * ty + 1) * 68 + k];
            float a2 = As[(4 * ty + 2) * 68 + k];
            float a3 = As[(4 * ty + 3) * 68 + k];
            float4 b = *(const float4*)&Ws[k * 64 + 4 * tx];
            acc[0][0] += a0 * b.x; acc[0][1] += a0 * b.y; acc[0][2] += a0 * b.z; acc[0][3] += a0 * b.w;
            acc[1][0] += a1 * b.x; acc[1][1] += a1 * b.y; acc[1][2] += a1 * b.z; acc[1][3] += a1 * b.w;
            acc[2][0] += a2 * b.x; acc[2][1] += a2 * b.y; acc[2][2] += a2 * b.z; acc[2][3] += a2 * b.w;
            acc[3][0] += a3 * b.x; acc[3][1] += a3 * b.y; acc[3][2] += a3 * b.z; acc[3][3] += a3 * b.w;
        }
        __syncthreads();
    }
    {
        float4 pbv = *(const float4*)&pb[4 * tx];
        float pbz[4] = {pbv.x, pbv.y, pbv.z, pbv.w};
#pragma unroll
        for (int i = 0; i < 4; i++)
#pragma unroll
            for (int j = 0; j < 4; j++)
                As[(4 * ty + i) * 68 + 4 * tx + j] = fmaxf(acc[i][j] + pbz[j], 0.f);
    }
    __syncthreads();

    for (int h = 0; h < N_HEADS; h++) {
#pragma unroll
        for (int l = 0; l < 4; l++) {
            int idx = tid + l * 256;
            int r = idx >> 4, c = (idx & 15) << 2;
            *(float4*)&Ws[r * 64 + c] = *(const float4*)&hw[((size_t)h * 64 + r) * 64 + c];
        }
        __syncthreads();

        float a2c[4][4];
#pragma unroll
        for (int i = 0; i < 4; i++)
#pragma unroll
            for (int j = 0; j < 4; j++) a2c[i][j] = 0.f;

#pragma unroll 8
        for (int k = 0; k < 64; k++) {
            float a0 = As[(4 * ty + 0) * 68 + k];
            float a1 = As[(4 * ty + 1) * 68 + k];
            float a2 = As[(4 * ty + 2) * 68 + k];
            float a3 = As[(4 * ty + 3) * 68 + k];
            float4 b = *(const float4*)&Ws[k * 64 + 4 * tx];
            a2c[0][0] += a0 * b.x; a2c[0][1] += a0 * b.y; a2c[0][2] += a0 * b.z; a2c[0][3] += a0 * b.w;
            a2c[1][0] += a1 * b.x; a2c[1][1] += a1 * b.y; a2c[1][2] += a1 * b.z; a2c[1][3] += a1 * b.w;
            a2c[2][0] += a2 * b.x; a2c[2][1] += a2 * b.y; a2c[2][2] += a2 * b.z; a2c[2][3] += a2 * b.w;
            a2c[3][0] += a3 * b.x; a2c[3][1] += a3 * b.y; a2c[3][2] += a3 * b.z; a2c[3][3] += a3 * b.w;
        }

        float4 hbv = *(const float4*)&hb[h * 64 + 4 * tx];
        float hbz[4] = {hbv.x, hbv.y, hbv.z, hbv.w};
#pragma unroll
        for (int i = 0; i < 4; i++) {
            float v0 = a2c[i][0] + hbz[0];
            float v1 = a2c[i][1] + hbz[1];
            float v2 = a2c[i][2] + hbz[2];
            float v3 = a2c[i][3] + hbz[3];
            float rs = v0 * v0 + v1 * v1 + v2 * v2 + v3 * v3;
            *(float4*)&g_hp[((size_t)h * N_TOK + row0 + 4 * ty + i) * D_H + 4 * tx] =
                make_float4(v0, v1, v2, v3);
#pragma unroll
            for (int w = 1; w < 16; w <<= 1)
                rs += __shfl_xor_sync(0xffffffffu, rs, w, 16);
            if (tx == 0) g_ss[(size_t)h * N_TOK + row0 + 4 * ty + i] = rs;
        }
        __syncthreads();
    }
}

// ---------------------------------------------------------------------------
// Kernel 1b: padded tile images.
//   K image (bf16 hi/lo): [128 keys][72 bf16]  (stride 144B)
//   Vt image (fp16):      [64 d][136 fp16]     (stride 272B)
// ---------------------------------------------------------------------------
__global__ void __launch_bounds__(128) k_prep()
{
    __shared__ float tile[128][65];
    const int t = blockIdx.x, head = blockIdx.y, tid = threadIdx.x;

    const float* src = g_hp + ((size_t)head * N_TOK + (size_t)t * 128 + tid) * 64;
    uint32_t* kh = g_khi + ((size_t)head * 64 + t) * 4608;
    uint32_t* kl = g_klo + ((size_t)head * 64 + t) * 4608;
#pragma unroll 8
    for (int m = 0; m < 32; m++) {
        float f0 = src[2 * m], f1 = src[2 * m + 1];
        tile[tid][2 * m] = f0;
        tile[tid][2 * m + 1] = f1;
        __nv_bfloat16 h0 = __float2bfloat16(f0), h1 = __float2bfloat16(f1);
        kh[tid * 36 + m] = pack_bf2(h0, h1);
        kl[tid * 36 + m] = pack_bf2(__float2bfloat16(f0 - __bfloat162float(h0)),
                                    __float2bfloat16(f1 - __bfloat162float(h1)));
    }
    __syncthreads();

    uint32_t* vh = g_v16 + ((size_t)head * 64 + t) * 4352;
    const int d = tid >> 1, half = tid & 1;
#pragma unroll 8
    for (int m = 0; m < 32; m++) {
        int key = half * 64 + 2 * m;
        vh[d * 68 + half * 32 + m] = f16pack(tile[key][d], tile[key + 1][d]);
    }
}

// ---------------------------------------------------------------------------
// Kernel 2: distance flash-attention, mma.sync; GEMM1 bf16 3-product,
// GEMM2 fp16 single-product. 3-stage TMA pipeline with a dedicated producer
// warp; per-stage full/empty mbarriers (no per-tile __syncthreads) —
// consumer warps free-run, overlapping MUFU epilogue with tensor work.
// ---------------------------------------------------------------------------
#define SM_FULL(s)  ((s) * 8)
#define SM_EMPTY(s) (24 + (s) * 8)
#define SM_QHI     128
#define SM_QLO     (SM_QHI + 18432)
#define SM_STG     36992
#define OFF_KHI    0
#define OFF_KLO    18432
#define OFF_V16    36864
#define OFF_KK     54272
#define STG_BYTES  54784
#define N_STAGES   3
#define SM_TOTAL   (SM_STG + N_STAGES * STG_BYTES)   // 201344

__global__ void __launch_bounds__(288, 1) k_attn()
{
    extern __shared__ char smem[];
    const uint32_t sb = smem_u32(smem);
    const int tid  = threadIdx.x;
    const int warp = tid >> 5;
    const int lane = tid & 31;
    const int head = blockIdx.y;
    const int q0 = blockIdx.x * 128;
    const float* ssq = g_ss + (size_t)head * N_TOK;

    if (tid == 0) {
#pragma unroll
        for (int s = 0; s < N_STAGES; s++) {
            MBARRIER_INIT(sb + SM_FULL(s), 1);
            MBARRIER_INIT(sb + SM_EMPTY(s), 8);
        }
    }

    // copy Q tile images (this q-block's K images) into smem
    {
        const uint4* sh = (const uint4*)(g_khi + ((size_t)head * 64 + blockIdx.x) * 4608);
        const uint4* sl = (const uint4*)(g_klo + ((size_t)head * 64 + blockIdx.x) * 4608);
        uint4* dh = (uint4*)(smem + SM_QHI);
        uint4* dl = (uint4*)(smem + SM_QLO);
        for (int i = tid; i < 1152; i += 288) { dh[i] = sh[i]; dl[i] = sl[i]; }
    }
    __syncthreads();

    // ---------------- producer warp ----------------
    if (warp == 8) {
        if (lane == 0) {
            const size_t hb = (size_t)head * 64;
#pragma unroll
            for (int t = 0; t < N_STAGES; t++) {
                const uint32_t st = sb + SM_STG + t * STG_BYTES;
                MBARRIER_EXPECT_TX(sb + SM_FULL(t), STG_BYTES);
                bulk_g2s(st + OFF_KHI, g_khi + (hb + t) * 4608, 18432, sb + SM_FULL(t));
                bulk_g2s(st + OFF_KLO, g_klo + (hb + t) * 4608, 18432, sb + SM_FULL(t));
                bulk_g2s(st + OFF_V16, g_v16 + (hb + t) * 4352, 17408, sb + SM_FULL(t));
                bulk_g2s(st + OFF_KK,  ssq + (size_t)t * 128,     512, sb + SM_FULL(t));
            }
            int s = 0, pe = 0;
            for (int t = N_STAGES; t < 64; t++) {
                MBARRIER_WAIT_PARITY(sb + SM_EMPTY(s), pe);
                const uint32_t st = sb + SM_STG + s * STG_BYTES;
                MBARRIER_EXPECT_TX(sb + SM_FULL(s), STG_BYTES);
                bulk_g2s(st + OFF_KHI, g_khi + (hb + t) * 4608, 18432, sb + SM_FULL(s));
                bulk_g2s(st + OFF_KLO, g_klo + (hb + t) * 4608, 18432, sb + SM_FULL(s));
                bulk_g2s(st + OFF_V16, g_v16 + (hb + t) * 4352, 17408, sb + SM_FULL(s));
                bulk_g2s(st + OFF_KK,  ssq + (size_t)t * 128,     512, sb + SM_FULL(s));
                if (++s == N_STAGES) { s = 0; pe ^= 1; }
            }
        }
        return;
    }

    // ---------------- consumer warps (0..7) ----------------
    const int g  = lane >> 2;
    const int lt = lane & 3;
    const int mm = lane >> 3;
    const int r8 = lane & 7;

    const int r0g = q0 + 16 * warp + g;
    const int r1g = r0g + 8;
    const float qq0 = ssq[r0g];
    const float qq1 = ssq[r1g];
    const float NL2E = -1.4426950408889634f;

    float O[8][4];
#pragma unroll
    for (int n = 0; n < 8; n++)
#pragma unroll
        for (int e = 0; e < 4; e++) O[n][e] = 0.f;
    float l0 = 0.f, l1 = 0.f;

    const int q_row = 16 * warp + r8 + (mm & 1) * 8;
    const int k_rowofs = r8 + (mm >> 1) * 8;
    const int q_dsel = (mm >> 1) * 16;
    const int k_dsel = (mm & 1) * 16;

    int s = 0, ph = 0;
    for (int t = 0; t < 64; t++) {
        MBARRIER_WAIT_PARITY(sb + SM_FULL(s), ph);
        const uint32_t stg = sb + SM_STG + s * STG_BYTES;

        // ---- GEMM1: S = Q.K^T (bf16: hi*hi + lo*hi + hi*lo) ----
        float S[16][4];
#pragma unroll
        for (int n = 0; n < 16; n++)
#pragma unroll
            for (int e = 0; e < 4; e++) S[n][e] = 0.f;

#pragma unroll
        for (int kc = 0; kc < 4; kc++) {
            uint32_t qh[4], ql[4];
            uint32_t qa = sb + SM_QHI + q_row * 144 + kc * 32 + q_dsel;
            ldsm4(qh, qa);
            ldsm4(ql, qa + 18432);
#pragma unroll
            for (int np = 0; np < 8; np++) {
                uint32_t kb[4], lb[4];
                uint32_t ka = stg + OFF_KHI + (16 * np + k_rowofs) * 144 + kc * 32 + k_dsel;
                ldsm4(kb, ka);
                ldsm4(lb, ka + 18432);
                mma16816b(S[2 * np],     qh, kb[0], kb[1]);
                mma16816b(S[2 * np],     ql, kb[0], kb[1]);
                mma16816b(S[2 * np],     qh, lb[0], lb[1]);
                mma16816b(S[2 * np + 1], qh, kb[2], kb[3]);
                mma16816b(S[2 * np + 1], ql, kb[2], kb[3]);
                mma16816b(S[2 * np + 1], qh, lb[2], lb[3]);
            }
        }

        // ---- softmax weights (row max == 0 structurally; diagonal exact) ----
        const float* kkp = (const float*)(smem + SM_STG + s * STG_BYTES + OFF_KK);
        const int kt = t * 128;
#pragma unroll
        for (int nt = 0; nt < 16; nt++) {
            const int colg = kt + 8 * nt + 2 * lt;
            float2 kkv = *(const float2*)(kkp + 8 * nt + 2 * lt);
            float sq00 = qq0 + kkv.x - 2.f * S[nt][0];
            float sq01 = qq0 + kkv.y - 2.f * S[nt][1];
            float sq10 = qq1 + kkv.x - 2.f * S[nt][2];
            float sq11 = qq1 + kkv.y - 2.f * S[nt][3];
            S[nt][0] = (colg == r0g     || sq00 <= 0.f) ? 1.f : ex2f(NL2E * sqrtapx(sq00));
            S[nt][1] = (colg + 1 == r0g || sq01 <= 0.f) ? 1.f : ex2f(NL2E * sqrtapx(sq01));
            S[nt][2] = (colg == r1g     || sq10 <= 0.f) ? 1.f : ex2f(NL2E * sqrtapx(sq10));
            S[nt][3] = (colg + 1 == r1g || sq11 <= 0.f) ? 1.f : ex2f(NL2E * sqrtapx(sq11));
            l0 += S[nt][0] + S[nt][1];
            l1 += S[nt][2] + S[nt][3];
        }

        // ---- GEMM2: O += P.V (fp16 single product) ----
#pragma unroll
        for (int kc2 = 0; kc2 < 8; kc2++) {
            uint32_t aF[4];
            aF[0] = f16pack(S[2 * kc2][0],     S[2 * kc2][1]);
            aF[1] = f16pack(S[2 * kc2][2],     S[2 * kc2][3]);
            aF[2] = f16pack(S[2 * kc2 + 1][0], S[2 * kc2 + 1][1]);
            aF[3] = f16pack(S[2 * kc2 + 1][2], S[2 * kc2 + 1][3]);
#pragma unroll
            for (int j = 0; j < 4; j++) {
                uint32_t vb[4];
                uint32_t va = stg + OFF_V16 + (16 * j + k_rowofs) * 272 + kc2 * 32 + k_dsel;
                ldsm4(vb, va);
                mma16816h(O[2 * j],     aF, vb[0], vb[1]);
                mma16816h(O[2 * j + 1], aF, vb[2], vb[3]);
            }
        }

        if (lane == 0) MBARRIER_ARRIVE(sb + SM_EMPTY(s));
        if (++s == N_STAGES) { s = 0; ph ^= 1; }
    }

    // reduce l over the 4 lanes sharing each row, normalize, store
    l0 += __shfl_xor_sync(0xffffffffu, l0, 1);
    l0 += __shfl_xor_sync(0xffffffffu, l0, 2);
    l1 += __shfl_xor_sync(0xffffffffu, l1, 1);
    l1 += __shfl_xor_sync(0xffffffffu, l1, 2);
    const float inv0 = 1.f / l0, inv1 = 1.f / l1;

    float* dst0 = g_hh + ((size_t)head * N_TOK + r0g) * D_H;
    float* dst1 = g_hh + ((size_t)head * N_TOK + r1g) * D_H;
#pragma unroll
    for (int n = 0; n < 8; n++) {
        *(float2*)&dst0[8 * n + 2 * lt] = make_float2(O[n][0] * inv0, O[n][1] * inv0);
        *(float2*)&dst1[8 * n + 2 * lt] = make_float2(O[n][2] * inv1, O[n][3] * inv1);
    }
}

// ---------------------------------------------------------------------------
// Kernel 3: combine heads + LayerNorm + FC (unchanged)
// ---------------------------------------------------------------------------
__global__ void __launch_bounds__(256) k_final(const float* __restrict__ attn_w,
                                               const float* __restrict__ gamma,
                                               const float* __restrict__ beta,
                                               const float* __restrict__ fcw,
                                               const float* __restrict__ fcb,
                                               float* __restrict__ out)
{
    const int warp = threadIdx.x >> 5;
    const int lane = threadIdx.x & 31;
    const int row = blockIdx.x * 8 + warp;

    float a0 = attn_w[0], a1 = attn_w[1], a2 = attn_w[2], a3 = attn_w[3];
    float mx = fmaxf(fmaxf(a0, a1), fmaxf(a2, a3));
    float aw[4];
    aw[0] = __expf(a0 - mx); aw[1] = __expf(a1 - mx);
    aw[2] = __expf(a2 - mx); aw[3] = __expf(a3 - mx);
    float ainv = 1.f / (aw[0] + aw[1] + aw[2] + aw[3]);

    const int d0 = lane, d1 = lane + 32;
    float c0 = 0.f, c1 = 0.f;
#pragma unroll
    for (int h = 0; h < N_HEADS; h++) {
        const float* p = g_hh + ((size_t)h * N_TOK + row) * D_H;
        c0 += aw[h] * p[d0];
        c1 += aw[h] * p[d1];
    }
    c0 *= ainv; c1 *= ainv;

    float s = c0 + c1;
#pragma unroll
    for (int w = 16; w; w >>= 1) s += __shfl_xor_sync(0xffffffffu, s, w);
    float mu = s * (1.f / 64.f);
    float v0 = c0 - mu, v1 = c1 - mu;
    float vv = v0 * v0 + v1 * v1;
#pragma unroll
    for (int w = 16; w; w >>= 1) vv += __shfl_xor_sync(0xffffffffu, vv, w);
    float inv = rsqrtf(vv * (1.f / 64.f) + LN_EPS);
    float n0 = v0 * inv * gamma[d0] + beta[d0];
    float n1 = v1 * inv * gamma[d1] + beta[d1];

    float o[N_CLS];
#pragma unroll
    for (int c = 0; c < N_CLS; c++)
        o[c] = n0 * fcw[d0 * N_CLS + c] + n1 * fcw[d1 * N_CLS + c];
#pragma unroll
    for (int c = 0; c < N_CLS; c++)
#pragma unroll
        for (int w = 16; w; w >>= 1) o[c] += __shfl_xor_sync(0xffffffffu, o[c], w);

    if (lane == 0) {
#pragma unroll
        for (int c = 0; c < N_CLS; c++)
            out[(size_t)row * N_CLS + c] = o[c] + fcb[c];
    }
}

// ---------------------------------------------------------------------------
extern "C" void kernel_launch(void* const* d_in, const int* in_sizes, int n_in,
                              void* d_out, int out_size)
{
    const float* x      = (const float*)d_in[0];
    const float* proj_w = (const float*)d_in[1];
    const float* proj_b = (const float*)d_in[2];
    const float* head_w = (const float*)d_in[3];
    const float* head_b = (const float*)d_in[4];
    const float* attn_w = (const float*)d_in[5];
    const float* gamma  = (const float*)d_in[6];
    const float* beta   = (const float*)d_in[7];
    const float* fc_w   = (const float*)d_in[8];
    const float* fc_b   = (const float*)d_in[9];
    float* out = (float*)d_out;

    static int smem_set = 0;
    if (!smem_set) {
        cudaFuncSetAttribute(k_attn, cudaFuncAttributeMaxDynamicSharedMemorySize, SM_TOTAL);
        smem_set = 1;
    }

    k_proj<<<N_TOK / 64, 256>>>(x, proj_w, proj_b, head_w, head_b);

    dim3 gp(64, N_HEADS);
    k_prep<<<gp, 128>>>();

    dim3 g2(N_TOK / 128, N_HEADS);
    k_attn<<<g2, 288, SM_TOTAL>>>();

    k_final<<<N_TOK / 8, 256>>>(attn_w, gamma, beta, fc_w, fc_b, out);
}

// round 7
// speedup vs baseline: 3.9941x; 1.1068x over previous
#include <cuda_runtime.h>
#include <cuda_bf16.h>
#include <cuda_fp16.h>
#include <cstdint>
#include <cstddef>

#define N_TOK   8192
#define D_IN    384
#define D_H     64
#define N_HEADS 4
#define N_CLS   6
#define N_SPLIT 4
#define LN_EPS  1e-5f

// ---------------- scratch (no allocations allowed) ----------------
__device__ float g_hp[(size_t)N_HEADS * N_TOK * D_H];
__device__ float g_ss[(size_t)N_HEADS * N_TOK];
__device__ float g_ho[(size_t)N_HEADS * N_SPLIT * N_TOK * D_H];   // partial O (unnormalized)
__device__ float g_l [(size_t)N_HEADS * N_SPLIT * N_TOK];         // partial softmax denominators
// padded tile images, stored as u32 (2 halves):
//  K image per tile: 128 rows x 36 u32 (72 bf16: d 0..63 + pad)    = 4608 u32
//  Vt image per tile: 64 d-rows x 68 u32 (136 fp16: key 0..127+pad) = 4352 u32
__device__ __align__(256) uint32_t g_khi[(size_t)N_HEADS * 64 * 4608];
__device__ __align__(256) uint32_t g_klo[(size_t)N_HEADS * 64 * 4608];
__device__ __align__(256) uint32_t g_v16[(size_t)N_HEADS * 64 * 4352];

// ---------------- helpers ----------------
__device__ __forceinline__ uint32_t smem_u32(const void* p) {
    uint32_t a;
    asm("{ .reg .u64 t; cvta.to.shared.u64 t, %1; cvt.u32.u64 %0, t; }" : "=r"(a) : "l"(p));
    return a;
}
__device__ __forceinline__ float ex2f(float x) {
    float r; asm("ex2.approx.f32 %0, %1;" : "=f"(r) : "f"(x)); return r;
}
__device__ __forceinline__ float sqrtapx(float x) {
    float r; asm("sqrt.approx.f32 %0, %1;" : "=f"(r) : "f"(x)); return r;
}
__device__ __forceinline__ uint32_t pack_bf2(__nv_bfloat16 a, __nv_bfloat16 b) {
    __nv_bfloat162 t; t.x = a; t.y = b;
    return *reinterpret_cast<uint32_t*>(&t);
}
__device__ __forceinline__ uint32_t f16pack(float lo, float hi) {
    uint32_t r; asm("cvt.rn.f16x2.f32 %0, %1, %2;" : "=r"(r) : "f"(hi), "f"(lo)); return r;
}
__device__ __forceinline__ void mma16816b(float c[4], const uint32_t a[4], uint32_t b0, uint32_t b1) {
    asm volatile("mma.sync.aligned.m16n8k16.row.col.f32.bf16.bf16.f32 "
        "{%0,%1,%2,%3}, {%4,%5,%6,%7}, {%8,%9}, {%0,%1,%2,%3};"
        : "+f"(c[0]), "+f"(c[1]), "+f"(c[2]), "+f"(c[3])
        : "r"(a[0]), "r"(a[1]), "r"(a[2]), "r"(a[3]), "r"(b0), "r"(b1));
}
__device__ __forceinline__ void mma16816h(float c[4], const uint32_t a[4], uint32_t b0, uint32_t b1) {
    asm volatile("mma.sync.aligned.m16n8k16.row.col.f32.f16.f16.f32 "
        "{%0,%1,%2,%3}, {%4,%5,%6,%7}, {%8,%9}, {%0,%1,%2,%3};"
        : "+f"(c[0]), "+f"(c[1]), "+f"(c[2]), "+f"(c[3])
        : "r"(a[0]), "r"(a[1]), "r"(a[2]), "r"(a[3]), "r"(b0), "r"(b1));
}
__device__ __forceinline__ void ldsm4(uint32_t r[4], uint32_t addr) {
    asm volatile("ldmatrix.sync.aligned.m8n8.x4.shared.b16 {%0,%1,%2,%3}, [%4];"
        : "=r"(r[0]), "=r"(r[1]), "=r"(r[2]), "=r"(r[3]) : "r"(addr));
}

#define MBARRIER_INIT(addr, cnt) \
    asm volatile("mbarrier.init.shared.b64 [%0], %1;" :: "r"((uint32_t)(addr)), "r"((uint32_t)(cnt)) : "memory")
#define MBARRIER_EXPECT_TX(addr, tx) \
    asm volatile("mbarrier.arrive.expect_tx.shared.b64 _, [%0], %1;" :: "r"((uint32_t)(addr)), "r"((uint32_t)(tx)) : "memory")
#define MBARRIER_ARRIVE(addr) \
    asm volatile("mbarrier.arrive.shared.b64 _, [%0];" :: "r"((uint32_t)(addr)) : "memory")
#define MBARRIER_WAIT_PARITY(addr, par) do {                                     \
    uint32_t _m = (uint32_t)(addr); uint32_t _p = (uint32_t)(par); uint32_t _d;  \
    asm volatile("{\n\t.reg .pred p;\n\t"                                        \
        "mbarrier.try_wait.parity.acquire.cta.shared::cta.b64 p, [%1], %2;\n\t"  \
        "selp.b32 %0, 1, 0, p;\n\t}" : "=r"(_d) : "r"(_m), "r"(_p) : "memory");  \
    if (!_d) {                                                                   \
        asm volatile("{\n\t.reg .pred P1;\n\t"                                   \
            "WL_%=:\n\t"                                                         \
            "mbarrier.try_wait.parity.acquire.cta.shared::cta.b64 P1, [%0], %1, 0x989680;\n\t" \
            "@P1 bra.uni WD_%=;\n\t"                                             \
            "bra.uni WL_%=;\n\t"                                                 \
            "WD_%=:\n\t}" :: "r"(_m), "r"(_p) : "memory");                       \
    }                                                                            \
} while (0)

__device__ __forceinline__ void bulk_g2s(uint32_t dst, const void* src, uint32_t bytes, uint32_t mbar) {
    asm volatile("cp.async.bulk.shared::cta.global.mbarrier::complete_tx::bytes [%0], [%1], %2, [%3];"
        :: "r"(dst), "l"(src), "r"(bytes), "r"(mbar) : "memory");
}

// ---------------------------------------------------------------------------
// Kernel 1: proj + head projections + sumsq (unchanged, ~35us)
// ---------------------------------------------------------------------------
__global__ void __launch_bounds__(256) k_proj(const float* __restrict__ x,
                                              const float* __restrict__ pw,
                                              const float* __restrict__ pb,
                                              const float* __restrict__ hw,
                                              const float* __restrict__ hb)
{
    __shared__ float As[64 * 68];
    __shared__ float Ws[64 * 64];
    const int tid = threadIdx.x;
    const int ty = tid >> 4, tx = tid & 15;
    const int row0 = blockIdx.x * 64;

    float acc[4][4];
#pragma unroll
    for (int i = 0; i < 4; i++)
#pragma unroll
        for (int j = 0; j < 4; j++) acc[i][j] = 0.f;

    for (int kk = 0; kk < D_IN; kk += 64) {
#pragma unroll
        for (int l = 0; l < 4; l++) {
            int idx = tid + l * 256;
            int r = idx >> 4, c = (idx & 15) << 2;
            *(float4*)&As[r * 68 + c] = *(const float4*)&x[(size_t)(row0 + r) * D_IN + kk + c];
            *(float4*)&Ws[r * 64 + c] = *(const float4*)&pw[(size_t)(kk + r) * D_H + c];
        }
        __syncthreads();
#pragma unroll 8
        for (int k = 0; k < 64; k++) {
            float a0 = As[(4 * ty + 0) * 68 + k];
            float a1 = As[(4 * ty + 1) * 68 + k];
            float a2 = As[(4 * ty + 2) * 68 + k];
            float a3 = As[(4 * ty + 3) * 68 + k];
            float4 b = *(const float4*)&Ws[k * 64 + 4 * tx];
            acc[0][0] += a0 * b.x; acc[0][1] += a0 * b.y; acc[0][2] += a0 * b.z; acc[0][3] += a0 * b.w;
            acc[1][0] += a1 * b.x; acc[1][1] += a1 * b.y; acc[1][2] += a1 * b.z; acc[1][3] += a1 * b.w;
            acc[2][0] += a2 * b.x; acc[2][1] += a2 * b.y; acc[2][2] += a2 * b.z; acc[2][3] += a2 * b.w;
            acc[3][0] += a3 * b.x; acc[3][1] += a3 * b.y; acc[3][2] += a3 * b.z; acc[3][3] += a3 * b.w;
        }
        __syncthreads();
    }
    {
        float4 pbv = *(const float4*)&pb[4 * tx];
        float pbz[4] = {pbv.x, pbv.y, pbv.z, pbv.w};
#pragma unroll
        for (int i = 0; i < 4; i++)
#pragma unroll
            for (int j = 0; j < 4; j++)
                As[(4 * ty + i) * 68 + 4 * tx + j] = fmaxf(acc[i][j] + pbz[j], 0.f);
    }
    __syncthreads();

    for (int h = 0; h < N_HEADS; h++) {
#pragma unroll
        for (int l = 0; l < 4; l++) {
            int idx = tid + l * 256;
            int r = idx >> 4, c = (idx & 15) << 2;
            *(float4*)&Ws[r * 64 + c] = *(const float4*)&hw[((size_t)h * 64 + r) * 64 + c];
        }
        __syncthreads();

        float a2c[4][4];
#pragma unroll
        for (int i = 0; i < 4; i++)
#pragma unroll
            for (int j = 0; j < 4; j++) a2c[i][j] = 0.f;

#pragma unroll 8
        for (int k = 0; k < 64; k++) {
            float a0 = As[(4 * ty + 0) * 68 + k];
            float a1 = As[(4 * ty + 1) * 68 + k];
            float a2 = As[(4 * ty + 2) * 68 + k];
            float a3 = As[(4 * ty + 3) * 68 + k];
            float4 b = *(const float4*)&Ws[k * 64 + 4 * tx];
            a2c[0][0] += a0 * b.x; a2c[0][1] += a0 * b.y; a2c[0][2] += a0 * b.z; a2c[0][3] += a0 * b.w;
            a2c[1][0] += a1 * b.x; a2c[1][1] += a1 * b.y; a2c[1][2] += a1 * b.z; a2c[1][3] += a1 * b.w;
            a2c[2][0] += a2 * b.x; a2c[2][1] += a2 * b.y; a2c[2][2] += a2 * b.z; a2c[2][3] += a2 * b.w;
            a2c[3][0] += a3 * b.x; a2c[3][1] += a3 * b.y; a2c[3][2] += a3 * b.z; a2c[3][3] += a3 * b.w;
        }

        float4 hbv = *(const float4*)&hb[h * 64 + 4 * tx];
        float hbz[4] = {hbv.x, hbv.y, hbv.z, hbv.w};
#pragma unroll
        for (int i = 0; i < 4; i++) {
            float v0 = a2c[i][0] + hbz[0];
            float v1 = a2c[i][1] + hbz[1];
            float v2 = a2c[i][2] + hbz[2];
            float v3 = a2c[i][3] + hbz[3];
            float rs = v0 * v0 + v1 * v1 + v2 * v2 + v3 * v3;
            *(float4*)&g_hp[((size_t)h * N_TOK + row0 + 4 * ty + i) * D_H + 4 * tx] =
                make_float4(v0, v1, v2, v3);
#pragma unroll
            for (int w = 1; w < 16; w <<= 1)
                rs += __shfl_xor_sync(0xffffffffu, rs, w, 16);
            if (tx == 0) g_ss[(size_t)h * N_TOK + row0 + 4 * ty + i] = rs;
        }
        __syncthreads();
    }
}

// ---------------------------------------------------------------------------
// Kernel 1b: padded tile images (unchanged).
// ---------------------------------------------------------------------------
__global__ void __launch_bounds__(128) k_prep()
{
    __shared__ float tile[128][65];
    const int t = blockIdx.x, head = blockIdx.y, tid = threadIdx.x;

    const float* src = g_hp + ((size_t)head * N_TOK + (size_t)t * 128 + tid) * 64;
    uint32_t* kh = g_khi + ((size_t)head * 64 + t) * 4608;
    uint32_t* kl = g_klo + ((size_t)head * 64 + t) * 4608;
#pragma unroll 8
    for (int m = 0; m < 32; m++) {
        float f0 = src[2 * m], f1 = src[2 * m + 1];
        tile[tid][2 * m] = f0;
        tile[tid][2 * m + 1] = f1;
        __nv_bfloat16 h0 = __float2bfloat16(f0), h1 = __float2bfloat16(f1);
        kh[tid * 36 + m] = pack_bf2(h0, h1);
        kl[tid * 36 + m] = pack_bf2(__float2bfloat16(f0 - __bfloat162float(h0)),
                                    __float2bfloat16(f1 - __bfloat162float(h1)));
    }
    __syncthreads();

    uint32_t* vh = g_v16 + ((size_t)head * 64 + t) * 4352;
    const int d = tid >> 1, half = tid & 1;
#pragma unroll 8
    for (int m = 0; m < 32; m++) {
        int key = half * 64 + 2 * m;
        vh[d * 68 + half * 32 + m] = f16pack(tile[key][d], tile[key + 1][d]);
    }
}

// ---------------------------------------------------------------------------
// Kernel 2: split-K distance flash-attention.
//  - Q fragments loop-invariant -> loaded once into registers (prologue).
//  - grid (64 qtiles, 4 heads, 4 splits); each CTA does 16 k-tiles and
//    writes unnormalized partial O + partial l (p in (0,1]: no max needed).
//  - softmax epilogue interleaved into GEMM2 chunks (MUFU under HMMA).
// ---------------------------------------------------------------------------
#define SM_FULL(s)  ((s) * 8)
#define SM_EMPTY(s) (24 + (s) * 8)
#define SM_STG     128
#define OFF_KHI    0
#define OFF_KLO    18432
#define OFF_V16    36864
#define OFF_KK     54272
#define STG_BYTES  54784
#define N_STAGES   3
#define T_PER_CTA  16
#define SM_TOTAL   (SM_STG + N_STAGES * STG_BYTES)   // 164480

__global__ void __launch_bounds__(288, 1) k_attn()
{
    extern __shared__ char smem[];
    const uint32_t sb = smem_u32(smem);
    const int tid  = threadIdx.x;
    const int warp = tid >> 5;
    const int lane = tid & 31;
    const int head = blockIdx.y;
    const int split = blockIdx.z;
    const int q0 = blockIdx.x * 128;
    const int t0 = split * T_PER_CTA;
    const float* ssq = g_ss + (size_t)head * N_TOK;

    if (tid == 0) {
#pragma unroll
        for (int s = 0; s < N_STAGES; s++) {
            MBARRIER_INIT(sb + SM_FULL(s), 1);
            MBARRIER_INIT(sb + SM_EMPTY(s), 8);
        }
    }

    // Prologue: stage Q images in stage-0 smem, pull fragments to registers.
    {
        const uint4* sh = (const uint4*)(g_khi + ((size_t)head * 64 + blockIdx.x) * 4608);
        const uint4* sl = (const uint4*)(g_klo + ((size_t)head * 64 + blockIdx.x) * 4608);
        uint4* dh = (uint4*)(smem + SM_STG + OFF_KHI);
        uint4* dl = (uint4*)(smem + SM_STG + OFF_KLO);
        for (int i = tid; i < 1152; i += 288) { dh[i] = sh[i]; dl[i] = sl[i]; }
    }
    __syncthreads();

    const int mm = lane >> 3;
    const int r8 = lane & 7;
    const int q_dsel = (mm >> 1) * 16;
    const int k_dsel = (mm & 1) * 16;
    const int k_rowofs = r8 + (mm >> 1) * 8;

    uint32_t qh_r[4][4], ql_r[4][4];
    if (warp < 8) {
        const int q_row = 16 * warp + r8 + (mm & 1) * 8;
#pragma unroll
        for (int kc = 0; kc < 4; kc++) {
            uint32_t qa = sb + SM_STG + q_row * 144 + kc * 32 + q_dsel;
            ldsm4(qh_r[kc], qa);
            ldsm4(ql_r[kc], qa + 18432);
        }
    }
    __syncthreads();

    // ---------------- producer warp ----------------
    if (warp == 8) {
        if (lane == 0) {
            const size_t hb = (size_t)head * 64 + t0;
#pragma unroll
            for (int i = 0; i < N_STAGES; i++) {
                const uint32_t st = sb + SM_STG + i * STG_BYTES;
                MBARRIER_EXPECT_TX(sb + SM_FULL(i), STG_BYTES);
                bulk_g2s(st + OFF_KHI, g_khi + (hb + i) * 4608, 18432, sb + SM_FULL(i));
                bulk_g2s(st + OFF_KLO, g_klo + (hb + i) * 4608, 18432, sb + SM_FULL(i));
                bulk_g2s(st + OFF_V16, g_v16 + (hb + i) * 4352, 17408, sb + SM_FULL(i));
                bulk_g2s(st + OFF_KK,  ssq + (size_t)(t0 + i) * 128, 512, sb + SM_FULL(i));
            }
            int s = 0, pe = 0;
            for (int i = N_STAGES; i < T_PER_CTA; i++) {
                MBARRIER_WAIT_PARITY(sb + SM_EMPTY(s), pe);
                const uint32_t st = sb + SM_STG + s * STG_BYTES;
                MBARRIER_EXPECT_TX(sb + SM_FULL(s), STG_BYTES);
                bulk_g2s(st + OFF_KHI, g_khi + (hb + i) * 4608, 18432, sb + SM_FULL(s));
                bulk_g2s(st + OFF_KLO, g_klo + (hb + i) * 4608, 18432, sb + SM_FULL(s));
                bulk_g2s(st + OFF_V16, g_v16 + (hb + i) * 4352, 17408, sb + SM_FULL(s));
                bulk_g2s(st + OFF_KK,  ssq + (size_t)(t0 + i) * 128, 512, sb + SM_FULL(s));
                if (++s == N_STAGES) { s = 0; pe ^= 1; }
            }
        }
        return;
    }

    // ---------------- consumer warps (0..7) ----------------
    const int g  = lane >> 2;
    const int lt = lane & 3;

    const int r0g = q0 + 16 * warp + g;
    const int r1g = r0g + 8;
    const float qq0 = ssq[r0g];
    const float qq1 = ssq[r1g];
    const float NL2E = -1.4426950408889634f;

    float O[8][4];
#pragma unroll
    for (int n = 0; n < 8; n++)
#pragma unroll
        for (int e = 0; e < 4; e++) O[n][e] = 0.f;
    float l0 = 0.f, l1 = 0.f;

    int s = 0, ph = 0;
    for (int i = 0; i < T_PER_CTA; i++) {
        const int t = t0 + i;
        MBARRIER_WAIT_PARITY(sb + SM_FULL(s), ph);
        const uint32_t stg = sb + SM_STG + s * STG_BYTES;

        // ---- GEMM1: S = Q.K^T (bf16: hi*hi + lo*hi + hi*lo), Q from regs ----
        float S[16][4];
#pragma unroll
        for (int n = 0; n < 16; n++)
#pragma unroll
            for (int e = 0; e < 4; e++) S[n][e] = 0.f;

#pragma unroll
        for (int kc = 0; kc < 4; kc++) {
#pragma unroll
            for (int np = 0; np < 8; np++) {
                uint32_t kb[4], lb[4];
                uint32_t ka = stg + OFF_KHI + (16 * np + k_rowofs) * 144 + kc * 32 + k_dsel;
                ldsm4(kb, ka);
                ldsm4(lb, ka + 18432);
                mma16816b(S[2 * np],     qh_r[kc], kb[0], kb[1]);
                mma16816b(S[2 * np],     ql_r[kc], kb[0], kb[1]);
                mma16816b(S[2 * np],     qh_r[kc], lb[0], lb[1]);
                mma16816b(S[2 * np + 1], qh_r[kc], kb[2], kb[3]);
                mma16816b(S[2 * np + 1], ql_r[kc], kb[2], kb[3]);
                mma16816b(S[2 * np + 1], qh_r[kc], lb[2], lb[3]);
            }
        }

        // ---- GEMM2 with interleaved softmax epilogue ----
        const float* kkp = (const float*)(smem + SM_STG + s * STG_BYTES + OFF_KK);
        const int kt = t * 128;
#pragma unroll
        for (int kc2 = 0; kc2 < 8; kc2++) {
            // softmax for the two 8-key chunks this kc2 consumes
#pragma unroll
            for (int u = 0; u < 2; u++) {
                const int nt = 2 * kc2 + u;
                const int colg = kt + 8 * nt + 2 * lt;
                float2 kkv = *(const float2*)(kkp + 8 * nt + 2 * lt);
                float sq00 = qq0 + kkv.x - 2.f * S[nt][0];
                float sq01 = qq0 + kkv.y - 2.f * S[nt][1];
                float sq10 = qq1 + kkv.x - 2.f * S[nt][2];
                float sq11 = qq1 + kkv.y - 2.f * S[nt][3];
                S[nt][0] = (colg == r0g     || sq00 <= 0.f) ? 1.f : ex2f(NL2E * sqrtapx(sq00));
                S[nt][1] = (colg + 1 == r0g || sq01 <= 0.f) ? 1.f : ex2f(NL2E * sqrtapx(sq01));
                S[nt][2] = (colg == r1g     || sq10 <= 0.f) ? 1.f : ex2f(NL2E * sqrtapx(sq10));
                S[nt][3] = (colg + 1 == r1g || sq11 <= 0.f) ? 1.f : ex2f(NL2E * sqrtapx(sq11));
                l0 += S[nt][0] + S[nt][1];
                l1 += S[nt][2] + S[nt][3];
            }
            uint32_t aF[4];
            aF[0] = f16pack(S[2 * kc2][0],     S[2 * kc2][1]);
            aF[1] = f16pack(S[2 * kc2][2],     S[2 * kc2][3]);
            aF[2] = f16pack(S[2 * kc2 + 1][0], S[2 * kc2 + 1][1]);
            aF[3] = f16pack(S[2 * kc2 + 1][2], S[2 * kc2 + 1][3]);
#pragma unroll
            for (int j = 0; j < 4; j++) {
                uint32_t vb[4];
                uint32_t va = stg + OFF_V16 + (16 * j + k_rowofs) * 272 + kc2 * 32 + k_dsel;
                ldsm4(vb, va);
                mma16816h(O[2 * j],     aF, vb[0], vb[1]);
                mma16816h(O[2 * j + 1], aF, vb[2], vb[3]);
            }
        }

        if (lane == 0) MBARRIER_ARRIVE(sb + SM_EMPTY(s));
        if (++s == N_STAGES) { s = 0; ph ^= 1; }
    }

    // reduce l over the 4 lanes sharing each row, write partials (no normalize)
    l0 += __shfl_xor_sync(0xffffffffu, l0, 1);
    l0 += __shfl_xor_sync(0xffffffffu, l0, 2);
    l1 += __shfl_xor_sync(0xffffffffu, l1, 1);
    l1 += __shfl_xor_sync(0xffffffffu, l1, 2);

    const size_t pbase = ((size_t)head * N_SPLIT + split) * N_TOK;
    if (lt == 0) {
        g_l[pbase + r0g] = l0;
        g_l[pbase + r1g] = l1;
    }
    float* dst0 = g_ho + (pbase + r0g) * D_H;
    float* dst1 = g_ho + (pbase + r1g) * D_H;
#pragma unroll
    for (int n = 0; n < 8; n++) {
        *(float2*)&dst0[8 * n + 2 * lt] = make_float2(O[n][0], O[n][1]);
        *(float2*)&dst1[8 * n + 2 * lt] = make_float2(O[n][2], O[n][3]);
    }
}

// ---------------------------------------------------------------------------
// Kernel 3: combine split partials + heads, LayerNorm, FC.
// ---------------------------------------------------------------------------
__global__ void __launch_bounds__(256) k_final(const float* __restrict__ attn_w,
                                               const float* __restrict__ gamma,
                                               const float* __restrict__ beta,
                                               const float* __restrict__ fcw,
                                               const float* __restrict__ fcb,
                                               float* __restrict__ out)
{
    const int warp = threadIdx.x >> 5;
    const int lane = threadIdx.x & 31;
    const int row = blockIdx.x * 8 + warp;

    float a0 = attn_w[0], a1 = attn_w[1], a2 = attn_w[2], a3 = attn_w[3];
    float mx = fmaxf(fmaxf(a0, a1), fmaxf(a2, a3));
    float aw[4];
    aw[0] = __expf(a0 - mx); aw[1] = __expf(a1 - mx);
    aw[2] = __expf(a2 - mx); aw[3] = __expf(a3 - mx);
    float ainv = 1.f / (aw[0] + aw[1] + aw[2] + aw[3]);

    const int d0 = lane, d1 = lane + 32;
    float c0 = 0.f, c1 = 0.f;
#pragma unroll
    for (int h = 0; h < N_HEADS; h++) {
        float lsum = 0.f;
        float o0 = 0.f, o1 = 0.f;
#pragma unroll
        for (int s = 0; s < N_SPLIT; s++) {
            const size_t pbase = ((size_t)h * N_SPLIT + s) * N_TOK + row;
            lsum += g_l[pbase];
            const float* p = g_ho + pbase * D_H;
            o0 += p[d0];
            o1 += p[d1];
        }
        float w = aw[h] / lsum;
        c0 += w * o0;
        c1 += w * o1;
    }
    c0 *= ainv; c1 *= ainv;

    float s = c0 + c1;
#pragma unroll
    for (int w = 16; w; w >>= 1) s += __shfl_xor_sync(0xffffffffu, s, w);
    float mu = s * (1.f / 64.f);
    float v0 = c0 - mu, v1 = c1 - mu;
    float vv = v0 * v0 + v1 * v1;
#pragma unroll
    for (int w = 16; w; w >>= 1) vv += __shfl_xor_sync(0xffffffffu, vv, w);
    float inv = rsqrtf(vv * (1.f / 64.f) + LN_EPS);
    float n0 = v0 * inv * gamma[d0] + beta[d0];
    float n1 = v1 * inv * gamma[d1] + beta[d1];

    float o[N_CLS];
#pragma unroll
    for (int c = 0; c < N_CLS; c++)
        o[c] = n0 * fcw[d0 * N_CLS + c] + n1 * fcw[d1 * N_CLS + c];
#pragma unroll
    for (int c = 0; c < N_CLS; c++)
#pragma unroll
        for (int w = 16; w; w >>= 1) o[c] += __shfl_xor_sync(0xffffffffu, o[c], w);

    if (lane == 0) {
#pragma unroll
        for (int c = 0; c < N_CLS; c++)
            out[(size_t)row * N_CLS + c] = o[c] + fcb[c];
    }
}

// ---------------------------------------------------------------------------
extern "C" void kernel_launch(void* const* d_in, const int* in_sizes, int n_in,
                              void* d_out, int out_size)
{
    const float* x      = (const float*)d_in[0];
    const float* proj_w = (const float*)d_in[1];
    const float* proj_b = (const float*)d_in[2];
    const float* head_w = (const float*)d_in[3];
    const float* head_b = (const float*)d_in[4];
    const float* attn_w = (const float*)d_in[5];
    const float* gamma  = (const float*)d_in[6];
    const float* beta   = (const float*)d_in[7];
    const float* fc_w   = (const float*)d_in[8];
    const float* fc_b   = (const float*)d_in[9];
    float* out = (float*)d_out;

    static int smem_set = 0;
    if (!smem_set) {
        cudaFuncSetAttribute(k_attn, cudaFuncAttributeMaxDynamicSharedMemorySize, SM_TOTAL);
        smem_set = 1;
    }

    k_proj<<<N_TOK / 64, 256>>>(x, proj_w, proj_b, head_w, head_b);

    dim3 gp(64, N_HEADS);
    k_prep<<<gp, 128>>>();

    dim3 g2(N_TOK / 128, N_HEADS, N_SPLIT);
    k_attn<<<g2, 288, SM_TOTAL>>>();

    k_final<<<N_TOK / 8, 256>>>(attn_w, gamma, beta, fc_w, fc_b, out);
}

// round 8
// speedup vs baseline: 5.5416x; 1.3874x over previous
#include <cuda_runtime.h>
#include <cuda_bf16.h>
#include <cuda_fp16.h>
#include <cstdint>
#include <cstddef>

#define N_TOK   8192
#define D_IN    384
#define D_H     64
#define N_HEADS 4
#define N_CLS   6
#define N_SPLIT 4
#define LN_EPS  1e-5f

// ---------------- scratch (no allocations allowed) ----------------
__device__ float g_hp[(size_t)N_HEADS * N_TOK * D_H];
__device__ float g_ss[(size_t)N_HEADS * N_TOK];
__device__ float g_ho[(size_t)N_HEADS * N_SPLIT * N_TOK * D_H];   // partial O (unnormalized)
__device__ float g_l [(size_t)N_HEADS * N_SPLIT * N_TOK];         // partial softmax denominators
__device__ __align__(256) uint32_t g_khi[(size_t)N_HEADS * 64 * 4608];
__device__ __align__(256) uint32_t g_klo[(size_t)N_HEADS * 64 * 4608];
__device__ __align__(256) uint32_t g_v16[(size_t)N_HEADS * 64 * 4352];

// ---------------- helpers ----------------
__device__ __forceinline__ uint32_t smem_u32(const void* p) {
    uint32_t a;
    asm("{ .reg .u64 t; cvta.to.shared.u64 t, %1; cvt.u32.u64 %0, t; }" : "=r"(a) : "l"(p));
    return a;
}
__device__ __forceinline__ float ex2f(float x) {
    float r; asm("ex2.approx.f32 %0, %1;" : "=f"(r) : "f"(x)); return r;
}
__device__ __forceinline__ float sqrtapx(float x) {
    float r; asm("sqrt.approx.f32 %0, %1;" : "=f"(r) : "f"(x)); return r;
}
__device__ __forceinline__ uint32_t pack_bf2(__nv_bfloat16 a, __nv_bfloat16 b) {
    __nv_bfloat162 t; t.x = a; t.y = b;
    return *reinterpret_cast<uint32_t*>(&t);
}
__device__ __forceinline__ uint32_t f16pack(float lo, float hi) {
    uint32_t r; asm("cvt.rn.f16x2.f32 %0, %1, %2;" : "=r"(r) : "f"(hi), "f"(lo)); return r;
}
__device__ __forceinline__ void mma16816b(float c[4], const uint32_t a[4], uint32_t b0, uint32_t b1) {
    asm volatile("mma.sync.aligned.m16n8k16.row.col.f32.bf16.bf16.f32 "
        "{%0,%1,%2,%3}, {%4,%5,%6,%7}, {%8,%9}, {%0,%1,%2,%3};"
        : "+f"(c[0]), "+f"(c[1]), "+f"(c[2]), "+f"(c[3])
        : "r"(a[0]), "r"(a[1]), "r"(a[2]), "r"(a[3]), "r"(b0), "r"(b1));
}
__device__ __forceinline__ void mma16816h(float c[4], const uint32_t a[4], uint32_t b0, uint32_t b1) {
    asm volatile("mma.sync.aligned.m16n8k16.row.col.f32.f16.f16.f32 "
        "{%0,%1,%2,%3}, {%4,%5,%6,%7}, {%8,%9}, {%0,%1,%2,%3};"
        : "+f"(c[0]), "+f"(c[1]), "+f"(c[2]), "+f"(c[3])
        : "r"(a[0]), "r"(a[1]), "r"(a[2]), "r"(a[3]), "r"(b0), "r"(b1));
}
__device__ __forceinline__ void ldsm4(uint32_t r[4], uint32_t addr) {
    asm volatile("ldmatrix.sync.aligned.m8n8.x4.shared.b16 {%0,%1,%2,%3}, [%4];"
        : "=r"(r[0]), "=r"(r[1]), "=r"(r[2]), "=r"(r[3]) : "r"(addr));
}

#define MBARRIER_INIT(addr, cnt) \
    asm volatile("mbarrier.init.shared.b64 [%0], %1;" :: "r"((uint32_t)(addr)), "r"((uint32_t)(cnt)) : "memory")
#define MBARRIER_EXPECT_TX(addr, tx) \
    asm volatile("mbarrier.arrive.expect_tx.shared.b64 _, [%0], %1;" :: "r"((uint32_t)(addr)), "r"((uint32_t)(tx)) : "memory")
#define MBARRIER_ARRIVE(addr) \
    asm volatile("mbarrier.arrive.shared.b64 _, [%0];" :: "r"((uint32_t)(addr)) : "memory")
#define MBARRIER_WAIT_PARITY(addr, par) do {                                     \
    uint32_t _m = (uint32_t)(addr); uint32_t _p = (uint32_t)(par); uint32_t _d;  \
    asm volatile("{\n\t.reg .pred p;\n\t"                                        \
        "mbarrier.try_wait.parity.acquire.cta.shared::cta.b64 p, [%1], %2;\n\t"  \
        "selp.b32 %0, 1, 0, p;\n\t}" : "=r"(_d) : "r"(_m), "r"(_p) : "memory");  \
    if (!_d) {                                                                   \
        asm volatile("{\n\t.reg .pred P1;\n\t"                                   \
            "WL_%=:\n\t"                                                         \
            "mbarrier.try_wait.parity.acquire.cta.shared::cta.b64 P1, [%0], %1, 0x989680;\n\t" \
            "@P1 bra.uni WD_%=;\n\t"                                             \
            "bra.uni WL_%=;\n\t"                                                 \
            "WD_%=:\n\t}" :: "r"(_m), "r"(_p) : "memory");                       \
    }                                                                            \
} while (0)

__device__ __forceinline__ void bulk_g2s(uint32_t dst, const void* src, uint32_t bytes, uint32_t mbar) {
    asm volatile("cp.async.bulk.shared::cta.global.mbarrier::complete_tx::bytes [%0], [%1], %2, [%3];"
        :: "r"(dst), "l"(src), "r"(bytes), "r"(mbar) : "memory");
}

// ---------------------------------------------------------------------------
// Kernel 1: proj + head projections + sumsq (unchanged, ~35us)
// ---------------------------------------------------------------------------
__global__ void __launch_bounds__(256) k_proj(const float* __restrict__ x,
                                              const float* __restrict__ pw,
                                              const float* __restrict__ pb,
                                              const float* __restrict__ hw,
                                              const float* __restrict__ hb)
{
    __shared__ float As[64 * 68];
    __shared__ float Ws[64 * 64];
    const int tid = threadIdx.x;
    const int ty = tid >> 4, tx = tid & 15;
    const int row0 = blockIdx.x * 64;

    float acc[4][4];
#pragma unroll
    for (int i = 0; i < 4; i++)
#pragma unroll
        for (int j = 0; j < 4; j++) acc[i][j] = 0.f;

    for (int kk = 0; kk < D_IN; kk += 64) {
#pragma unroll
        for (int l = 0; l < 4; l++) {
            int idx = tid + l * 256;
            int r = idx >> 4, c = (idx & 15) << 2;
            *(float4*)&As[r * 68 + c] = *(const float4*)&x[(size_t)(row0 + r) * D_IN + kk + c];
            *(float4*)&Ws[r * 64 + c] = *(const float4*)&pw[(size_t)(kk + r) * D_H + c];
        }
        __syncthreads();
#pragma unroll 8
        for (int k = 0; k < 64; k++) {
            float a0 = As[(4 * ty + 0) * 68 + k];
            float a1 = As[(4 * ty + 1) * 68 + k];
            float a2 = As[(4 * ty + 2) * 68 + k];
            float a3 = As[(4 * ty + 3) * 68 + k];
            float4 b = *(const float4*)&Ws[k * 64 + 4 * tx];
            acc[0][0] += a0 * b.x; acc[0][1] += a0 * b.y; acc[0][2] += a0 * b.z; acc[0][3] += a0 * b.w;
            acc[1][0] += a1 * b.x; acc[1][1] += a1 * b.y; acc[1][2] += a1 * b.z; acc[1][3] += a1 * b.w;
            acc[2][0] += a2 * b.x; acc[2][1] += a2 * b.y; acc[2][2] += a2 * b.z; acc[2][3] += a2 * b.w;
            acc[3][0] += a3 * b.x; acc[3][1] += a3 * b.y; acc[3][2] += a3 * b.z; acc[3][3] += a3 * b.w;
        }
        __syncthreads();
    }
    {
        float4 pbv = *(const float4*)&pb[4 * tx];
        float pbz[4] = {pbv.x, pbv.y, pbv.z, pbv.w};
#pragma unroll
        for (int i = 0; i < 4; i++)
#pragma unroll
            for (int j = 0; j < 4; j++)
                As[(4 * ty + i) * 68 + 4 * tx + j] = fmaxf(acc[i][j] + pbz[j], 0.f);
    }
    __syncthreads();

    for (int h = 0; h < N_HEADS; h++) {
#pragma unroll
        for (int l = 0; l < 4; l++) {
            int idx = tid + l * 256;
            int r = idx >> 4, c = (idx & 15) << 2;
            *(float4*)&Ws[r * 64 + c] = *(const float4*)&hw[((size_t)h * 64 + r) * 64 + c];
        }
        __syncthreads();

        float a2c[4][4];
#pragma unroll
        for (int i = 0; i < 4; i++)
#pragma unroll
            for (int j = 0; j < 4; j++) a2c[i][j] = 0.f;

#pragma unroll 8
        for (int k = 0; k < 64; k++) {
            float a0 = As[(4 * ty + 0) * 68 + k];
            float a1 = As[(4 * ty + 1) * 68 + k];
            float a2 = As[(4 * ty + 2) * 68 + k];
            float a3 = As[(4 * ty + 3) * 68 + k];
            float4 b = *(const float4*)&Ws[k * 64 + 4 * tx];
            a2c[0][0] += a0 * b.x; a2c[0][1] += a0 * b.y; a2c[0][2] += a0 * b.z; a2c[0][3] += a0 * b.w;
            a2c[1][0] += a1 * b.x; a2c[1][1] += a1 * b.y; a2c[1][2] += a1 * b.z; a2c[1][3] += a1 * b.w;
            a2c[2][0] += a2 * b.x; a2c[2][1] += a2 * b.y; a2c[2][2] += a2 * b.z; a2c[2][3] += a2 * b.w;
            a2c[3][0] += a3 * b.x; a2c[3][1] += a3 * b.y; a2c[3][2] += a3 * b.z; a2c[3][3] += a3 * b.w;
        }

        float4 hbv = *(const float4*)&hb[h * 64 + 4 * tx];
        float hbz[4] = {hbv.x, hbv.y, hbv.z, hbv.w};
#pragma unroll
        for (int i = 0; i < 4; i++) {
            float v0 = a2c[i][0] + hbz[0];
            float v1 = a2c[i][1] + hbz[1];
            float v2 = a2c[i][2] + hbz[2];
            float v3 = a2c[i][3] + hbz[3];
            float rs = v0 * v0 + v1 * v1 + v2 * v2 + v3 * v3;
            *(float4*)&g_hp[((size_t)h * N_TOK + row0 + 4 * ty + i) * D_H + 4 * tx] =
                make_float4(v0, v1, v2, v3);
#pragma unroll
            for (int w = 1; w < 16; w <<= 1)
                rs += __shfl_xor_sync(0xffffffffu, rs, w, 16);
            if (tx == 0) g_ss[(size_t)h * N_TOK + row0 + 4 * ty + i] = rs;
        }
        __syncthreads();
    }
}

// ---------------------------------------------------------------------------
// Kernel 1b: padded tile images (unchanged).
// ---------------------------------------------------------------------------
__global__ void __launch_bounds__(128) k_prep()
{
    __shared__ float tile[128][65];
    const int t = blockIdx.x, head = blockIdx.y, tid = threadIdx.x;

    const float* src = g_hp + ((size_t)head * N_TOK + (size_t)t * 128 + tid) * 64;
    uint32_t* kh = g_khi + ((size_t)head * 64 + t) * 4608;
    uint32_t* kl = g_klo + ((size_t)head * 64 + t) * 4608;
#pragma unroll 8
    for (int m = 0; m < 32; m++) {
        float f0 = src[2 * m], f1 = src[2 * m + 1];
        tile[tid][2 * m] = f0;
        tile[tid][2 * m + 1] = f1;
        __nv_bfloat16 h0 = __float2bfloat16(f0), h1 = __float2bfloat16(f1);
        kh[tid * 36 + m] = pack_bf2(h0, h1);
        kl[tid * 36 + m] = pack_bf2(__float2bfloat16(f0 - __bfloat162float(h0)),
                                    __float2bfloat16(f1 - __bfloat162float(h1)));
    }
    __syncthreads();

    uint32_t* vh = g_v16 + ((size_t)head * 64 + t) * 4352;
    const int d = tid >> 1, half = tid & 1;
#pragma unroll 8
    for (int m = 0; m < 32; m++) {
        int key = half * 64 + 2 * m;
        vh[d * 68 + half * 32 + m] = f16pack(tile[key][d], tile[key + 1][d]);
    }
}

// profiling alignment shim (lets ncu -s 5 land on k_attn)
__global__ void k_dummy() {}

// ---------------------------------------------------------------------------
// Kernel 2: split-K distance flash-attention, 16 consumer warps (4/SMSP).
//  Warp w handles q-rows [16*(w&7), +16) and keys [64*(w>>3), +64) of each
//  tile: per-warp work halves, warp-level overlap doubles. Cross-half O/l
//  partials reduced once per CTA through stage-0 smem at the end.
// ---------------------------------------------------------------------------
#define SM_FULL(s)  ((s) * 8)
#define SM_EMPTY(s) (24 + (s) * 8)
#define SM_Q       128
#define SM_STG     (SM_Q + 36864)            // 36992
#define OFF_KHI    0
#define OFF_KLO    18432
#define OFF_V16    36864
#define OFF_KK     54272
#define STG_BYTES  54784
#define N_STAGES   3
#define T_PER_CTA  16
#define SM_TOTAL   (SM_STG + N_STAGES * STG_BYTES)   // 201344

__global__ void __launch_bounds__(544, 1) k_attn()
{
    extern __shared__ char smem[];
    const uint32_t sb = smem_u32(smem);
    const int tid  = threadIdx.x;
    const int warp = tid >> 5;
    const int lane = tid & 31;
    const int head = blockIdx.y;
    const int split = blockIdx.z;
    const int q0 = blockIdx.x * 128;
    const int t0 = split * T_PER_CTA;
    const float* ssq = g_ss + (size_t)head * N_TOK;

    if (tid == 0) {
#pragma unroll
        for (int s = 0; s < N_STAGES; s++) {
            MBARRIER_INIT(sb + SM_FULL(s), 1);
            MBARRIER_INIT(sb + SM_EMPTY(s), 16);
        }
    }

    // Q images resident in smem for the whole CTA
    {
        const uint4* sh = (const uint4*)(g_khi + ((size_t)head * 64 + blockIdx.x) * 4608);
        const uint4* sl = (const uint4*)(g_klo + ((size_t)head * 64 + blockIdx.x) * 4608);
        uint4* dh = (uint4*)(smem + SM_Q);
        uint4* dl = (uint4*)(smem + SM_Q + 18432);
        for (int i = tid; i < 1152; i += 544) { dh[i] = sh[i]; dl[i] = sl[i]; }
    }
    __syncthreads();

    const int w7 = warp & 7;
    const int khalf = (warp & 8) ? 64 : 0;
    const int g  = lane >> 2;
    const int lt = lane & 3;
    const int mm = lane >> 3;
    const int r8 = lane & 7;
    const int q_dsel = (mm >> 1) * 16;
    const int k_dsel = (mm & 1) * 16;
    const int k_rowofs = r8 + (mm >> 1) * 8;
    const int q_row = 16 * w7 + r8 + (mm & 1) * 8;

    const int r0g = q0 + 16 * w7 + g;
    const int r1g = r0g + 8;
    const float NL2E = -1.4426950408889634f;

    float O[8][4];
#pragma unroll
    for (int n = 0; n < 8; n++)
#pragma unroll
        for (int e = 0; e < 4; e++) O[n][e] = 0.f;
    float l0 = 0.f, l1 = 0.f;

    if (warp == 16) {
        // ---------------- producer warp ----------------
        if (lane == 0) {
            const size_t hb = (size_t)head * 64 + t0;
#pragma unroll
            for (int i = 0; i < N_STAGES; i++) {
                const uint32_t st = sb + SM_STG + i * STG_BYTES;
                MBARRIER_EXPECT_TX(sb + SM_FULL(i), STG_BYTES);
                bulk_g2s(st + OFF_KHI, g_khi + (hb + i) * 4608, 18432, sb + SM_FULL(i));
                bulk_g2s(st + OFF_KLO, g_klo + (hb + i) * 4608, 18432, sb + SM_FULL(i));
                bulk_g2s(st + OFF_V16, g_v16 + (hb + i) * 4352, 17408, sb + SM_FULL(i));
                bulk_g2s(st + OFF_KK,  ssq + (size_t)(t0 + i) * 128, 512, sb + SM_FULL(i));
            }
            int s = 0, pe = 0;
            for (int i = N_STAGES; i < T_PER_CTA; i++) {
                MBARRIER_WAIT_PARITY(sb + SM_EMPTY(s), pe);
                const uint32_t st = sb + SM_STG + s * STG_BYTES;
                MBARRIER_EXPECT_TX(sb + SM_FULL(s), STG_BYTES);
                bulk_g2s(st + OFF_KHI, g_khi + (hb + i) * 4608, 18432, sb + SM_FULL(s));
                bulk_g2s(st + OFF_KLO, g_klo + (hb + i) * 4608, 18432, sb + SM_FULL(s));
                bulk_g2s(st + OFF_V16, g_v16 + (hb + i) * 4352, 17408, sb + SM_FULL(s));
                bulk_g2s(st + OFF_KK,  ssq + (size_t)(t0 + i) * 128, 512, sb + SM_FULL(s));
                if (++s == N_STAGES) { s = 0; pe ^= 1; }
            }
        }
    } else {
        // ---------------- consumer warps (0..15) ----------------
        const float qq0 = ssq[r0g];
        const float qq1 = ssq[r1g];

        int s = 0, ph = 0;
        for (int i = 0; i < T_PER_CTA; i++) {
            const int t = t0 + i;
            MBARRIER_WAIT_PARITY(sb + SM_FULL(s), ph);
            const uint32_t stg = sb + SM_STG + s * STG_BYTES;

            // ---- GEMM1: S = Q.K^T over this warp's 64 keys (bf16 3-product) ----
            float S[8][4];
#pragma unroll
            for (int n = 0; n < 8; n++)
#pragma unroll
                for (int e = 0; e < 4; e++) S[n][e] = 0.f;

#pragma unroll
            for (int kc = 0; kc < 4; kc++) {
                uint32_t qh[4], ql[4];
                uint32_t qa = sb + SM_Q + q_row * 144 + kc * 32 + q_dsel;
                ldsm4(qh, qa);
                ldsm4(ql, qa + 18432);
#pragma unroll
                for (int np = 0; np < 4; np++) {
                    uint32_t kb[4], lb[4];
                    uint32_t ka = stg + OFF_KHI + (khalf + 16 * np + k_rowofs) * 144 + kc * 32 + k_dsel;
                    ldsm4(kb, ka);
                    ldsm4(lb, ka + 18432);
                    mma16816b(S[2 * np],     qh, kb[0], kb[1]);
                    mma16816b(S[2 * np],     ql, kb[0], kb[1]);
                    mma16816b(S[2 * np],     qh, lb[0], lb[1]);
                    mma16816b(S[2 * np + 1], qh, kb[2], kb[3]);
                    mma16816b(S[2 * np + 1], ql, kb[2], kb[3]);
                    mma16816b(S[2 * np + 1], qh, lb[2], lb[3]);
                }
            }

            // ---- GEMM2 with interleaved softmax epilogue ----
            const float* kkp = (const float*)(smem + SM_STG + s * STG_BYTES + OFF_KK);
            const int kt = t * 128;
#pragma unroll
            for (int kc2 = 0; kc2 < 4; kc2++) {
#pragma unroll
                for (int u = 0; u < 2; u++) {
                    const int nt = 2 * kc2 + u;
                    const int colg = kt + khalf + 8 * nt + 2 * lt;
                    float2 kkv = *(const float2*)(kkp + khalf + 8 * nt + 2 * lt);
                    float sq00 = qq0 + kkv.x - 2.f * S[nt][0];
                    float sq01 = qq0 + kkv.y - 2.f * S[nt][1];
                    float sq10 = qq1 + kkv.x - 2.f * S[nt][2];
                    float sq11 = qq1 + kkv.y - 2.f * S[nt][3];
                    S[nt][0] = (colg == r0g     || sq00 <= 0.f) ? 1.f : ex2f(NL2E * sqrtapx(sq00));
                    S[nt][1] = (colg + 1 == r0g || sq01 <= 0.f) ? 1.f : ex2f(NL2E * sqrtapx(sq01));
                    S[nt][2] = (colg == r1g     || sq10 <= 0.f) ? 1.f : ex2f(NL2E * sqrtapx(sq10));
                    S[nt][3] = (colg + 1 == r1g || sq11 <= 0.f) ? 1.f : ex2f(NL2E * sqrtapx(sq11));
                    l0 += S[nt][0] + S[nt][1];
                    l1 += S[nt][2] + S[nt][3];
                }
                uint32_t aF[4];
                aF[0] = f16pack(S[2 * kc2][0],     S[2 * kc2][1]);
                aF[1] = f16pack(S[2 * kc2][2],     S[2 * kc2][3]);
                aF[2] = f16pack(S[2 * kc2 + 1][0], S[2 * kc2 + 1][1]);
                aF[3] = f16pack(S[2 * kc2 + 1][2], S[2 * kc2 + 1][3]);
#pragma unroll
                for (int j = 0; j < 4; j++) {
                    uint32_t vb[4];
                    uint32_t va = stg + OFF_V16 + (16 * j + k_rowofs) * 272
                                + (khalf + 16 * kc2) * 2 + k_dsel;
                    ldsm4(vb, va);
                    mma16816h(O[2 * j],     aF, vb[0], vb[1]);
                    mma16816h(O[2 * j + 1], aF, vb[2], vb[3]);
                }
            }

            if (lane == 0) MBARRIER_ARRIVE(sb + SM_EMPTY(s));
            if (++s == N_STAGES) { s = 0; ph ^= 1; }
        }

        // per-warp l reduction over the 4 lanes sharing each row
        l0 += __shfl_xor_sync(0xffffffffu, l0, 1);
        l0 += __shfl_xor_sync(0xffffffffu, l0, 2);
        l1 += __shfl_xor_sync(0xffffffffu, l1, 1);
        l1 += __shfl_xor_sync(0xffffffffu, l1, 2);
    }

    // ---- cross-half reduction through (now free) stage smem ----
    __syncthreads();
    float* red  = (float*)(smem + SM_STG);             // 8 * 16 * 64 floats = 32KB
    float* lred = (float*)(smem + SM_STG + 32768);     // 8 * 16 floats

    if (warp >= 8 && warp < 16) {
#pragma unroll
        for (int n = 0; n < 8; n++)
#pragma unroll
            for (int e = 0; e < 4; e++) {
                int row = g + ((e >> 1) << 3);
                int col = 8 * n + 2 * lt + (e & 1);
                red[w7 * 1024 + row * 64 + col] = O[n][e];
            }
        if (lt == 0) {
            lred[w7 * 16 + g] = l0;
            lred[w7 * 16 + g + 8] = l1;
        }
    }
    __syncthreads();

    if (warp < 8) {
#pragma unroll
        for (int n = 0; n < 8; n++)
#pragma unroll
            for (int e = 0; e < 4; e++) {
                int row = g + ((e >> 1) << 3);
                int col = 8 * n + 2 * lt + (e & 1);
                O[n][e] += red[w7 * 1024 + row * 64 + col];
            }
        l0 += lred[w7 * 16 + g];
        l1 += lred[w7 * 16 + g + 8];

        const size_t pbase = ((size_t)head * N_SPLIT + split) * N_TOK;
        if (lt == 0) {
            g_l[pbase + r0g] = l0;
            g_l[pbase + r1g] = l1;
        }
        float* dst0 = g_ho + (pbase + r0g) * D_H;
        float* dst1 = g_ho + (pbase + r1g) * D_H;
#pragma unroll
        for (int n = 0; n < 8; n++) {
            *(float2*)&dst0[8 * n + 2 * lt] = make_float2(O[n][0], O[n][1]);
            *(float2*)&dst1[8 * n + 2 * lt] = make_float2(O[n][2], O[n][3]);
        }
    }
}

// ---------------------------------------------------------------------------
// Kernel 3: combine split partials + heads, LayerNorm, FC (unchanged)
// ---------------------------------------------------------------------------
__global__ void __launch_bounds__(256) k_final(const float* __restrict__ attn_w,
                                               const float* __restrict__ gamma,
                                               const float* __restrict__ beta,
                                               const float* __restrict__ fcw,
                                               const float* __restrict__ fcb,
                                               float* __restrict__ out)
{
    const int warp = threadIdx.x >> 5;
    const int lane = threadIdx.x & 31;
    const int row = blockIdx.x * 8 + warp;

    float a0 = attn_w[0], a1 = attn_w[1], a2 = attn_w[2], a3 = attn_w[3];
    float mx = fmaxf(fmaxf(a0, a1), fmaxf(a2, a3));
    float aw[4];
    aw[0] = __expf(a0 - mx); aw[1] = __expf(a1 - mx);
    aw[2] = __expf(a2 - mx); aw[3] = __expf(a3 - mx);
    float ainv = 1.f / (aw[0] + aw[1] + aw[2] + aw[3]);

    const int d0 = lane, d1 = lane + 32;
    float c0 = 0.f, c1 = 0.f;
#pragma unroll
    for (int h = 0; h < N_HEADS; h++) {
        float lsum = 0.f;
        float o0 = 0.f, o1 = 0.f;
#pragma unroll
        for (int s = 0; s < N_SPLIT; s++) {
            const size_t pbase = ((size_t)h * N_SPLIT + s) * N_TOK + row;
            lsum += g_l[pbase];
            const float* p = g_ho + pbase * D_H;
            o0 += p[d0];
            o1 += p[d1];
        }
        float w = aw[h] / lsum;
        c0 += w * o0;
        c1 += w * o1;
    }
    c0 *= ainv; c1 *= ainv;

    float s = c0 + c1;
#pragma unroll
    for (int w = 16; w; w >>= 1) s += __shfl_xor_sync(0xffffffffu, s, w);
    float mu = s * (1.f / 64.f);
    float v0 = c0 - mu, v1 = c1 - mu;
    float vv = v0 * v0 + v1 * v1;
#pragma unroll
    for (int w = 16; w; w >>= 1) vv += __shfl_xor_sync(0xffffffffu, vv, w);
    float inv = rsqrtf(vv * (1.f / 64.f) + LN_EPS);
    float n0 = v0 * inv * gamma[d0] + beta[d0];
    float n1 = v1 * inv * gamma[d1] + beta[d1];

    float o[N_CLS];
#pragma unroll
    for (int c = 0; c < N_CLS; c++)
        o[c] = n0 * fcw[d0 * N_CLS + c] + n1 * fcw[d1 * N_CLS + c];
#pragma unroll
    for (int c = 0; c < N_CLS; c++)
#pragma unroll
        for (int w = 16; w; w >>= 1) o[c] += __shfl_xor_sync(0xffffffffu, o[c], w);

    if (lane == 0) {
#pragma unroll
        for (int c = 0; c < N_CLS; c++)
            out[(size_t)row * N_CLS + c] = o[c] + fcb[c];
    }
}

// ---------------------------------------------------------------------------
extern "C" void kernel_launch(void* const* d_in, const int* in_sizes, int n_in,
                              void* d_out, int out_size)
{
    const float* x      = (const float*)d_in[0];
    const float* proj_w = (const float*)d_in[1];
    const float* proj_b = (const float*)d_in[2];
    const float* head_w = (const float*)d_in[3];
    const float* head_b = (const float*)d_in[4];
    const float* attn_w = (const float*)d_in[5];
    const float* gamma  = (const float*)d_in[6];
    const float* beta   = (const float*)d_in[7];
    const float* fc_w   = (const float*)d_in[8];
    const float* fc_b   = (const float*)d_in[9];
    float* out = (float*)d_out;

    static int smem_set = 0;
    if (!smem_set) {
        cudaFuncSetAttribute(k_attn, cudaFuncAttributeMaxDynamicSharedMemorySize, SM_TOTAL);
        smem_set = 1;
    }

    k_proj<<<N_TOK / 64, 256>>>(x, proj_w, proj_b, head_w, head_b);

    dim3 gp(64, N_HEADS);
    k_prep<<<gp, 128>>>();

    k_dummy<<<1, 32>>>();   // aligns ncu -s 5 onto k_attn

    dim3 g2(N_TOK / 128, N_HEADS, N_SPLIT);
    k_attn<<<g2, 544, SM_TOTAL>>>();

    k_final<<<N_TOK / 8, 256>>>(attn_w, gamma, beta, fc_w, fc_b, out);
}

// round 9
// speedup vs baseline: 8.2277x; 1.4847x over previous
#include <cuda_runtime.h>
#include <cuda_bf16.h>
#include <cuda_fp16.h>
#include <cstdint>
#include <cstddef>

#define N_TOK   8192
#define D_IN    384
#define D_H     64
#define N_HEADS 4
#define N_CLS   6
#define N_SPLIT 4
#define LN_EPS  1e-5f
#define L2SQ    2.0813689810056077f   // (log2 e)^2

// ---------------- scratch (no allocations allowed) ----------------
__device__ float g_hp[(size_t)N_HEADS * N_TOK * D_H];
__device__ float g_ss[(size_t)N_HEADS * N_TOK];                   // ||hp||^2 * L2SQ
__device__ float g_ho[(size_t)N_HEADS * N_SPLIT * N_TOK * D_H];   // partial O (unnormalized)
__device__ float g_l [(size_t)N_HEADS * N_SPLIT * N_TOK];         // partial softmax denominators
// fp16 tile images (u32 = 2 halves):
//  K image per tile: 128 rows x 36 u32 (72 fp16: d 0..63 + pad)    = 4608 u32
//  Vt image per tile: 64 d-rows x 68 u32 (136 fp16: key 0..127+pad) = 4352 u32
__device__ __align__(256) uint32_t g_khi[(size_t)N_HEADS * 64 * 4608];
__device__ __align__(256) uint32_t g_klo[(size_t)N_HEADS * 64 * 4608];
__device__ __align__(256) uint32_t g_v16[(size_t)N_HEADS * 64 * 4352];

// ---------------- helpers ----------------
__device__ __forceinline__ uint32_t smem_u32(const void* p) {
    uint32_t a;
    asm("{ .reg .u64 t; cvta.to.shared.u64 t, %1; cvt.u32.u64 %0, t; }" : "=r"(a) : "l"(p));
    return a;
}
__device__ __forceinline__ float ex2f(float x) {
    float r; asm("ex2.approx.f32 %0, %1;" : "=f"(r) : "f"(x)); return r;
}
__device__ __forceinline__ float sqrtapx(float x) {
    float r; asm("sqrt.approx.f32 %0, %1;" : "=f"(r) : "f"(x)); return r;
}
__device__ __forceinline__ uint32_t packh2(__half a, __half b) {
    __half2 t = __halves2half2(a, b);
    return *reinterpret_cast<uint32_t*>(&t);
}
__device__ __forceinline__ uint32_t f16pack(float lo, float hi) {
    uint32_t r; asm("cvt.rn.f16x2.f32 %0, %1, %2;" : "=r"(r) : "f"(hi), "f"(lo)); return r;
}
__device__ __forceinline__ void mma16816h(float c[4], const uint32_t a[4], uint32_t b0, uint32_t b1) {
    asm volatile("mma.sync.aligned.m16n8k16.row.col.f32.f16.f16.f32 "
        "{%0,%1,%2,%3}, {%4,%5,%6,%7}, {%8,%9}, {%0,%1,%2,%3};"
        : "+f"(c[0]), "+f"(c[1]), "+f"(c[2]), "+f"(c[3])
        : "r"(a[0]), "r"(a[1]), "r"(a[2]), "r"(a[3]), "r"(b0), "r"(b1));
}
__device__ __forceinline__ void ldsm4(uint32_t r[4], uint32_t addr) {
    asm volatile("ldmatrix.sync.aligned.m8n8.x4.shared.b16 {%0,%1,%2,%3}, [%4];"
        : "=r"(r[0]), "=r"(r[1]), "=r"(r[2]), "=r"(r[3]) : "r"(addr));
}

#define MBARRIER_INIT(addr, cnt) \
    asm volatile("mbarrier.init.shared.b64 [%0], %1;" :: "r"((uint32_t)(addr)), "r"((uint32_t)(cnt)) : "memory")
#define MBARRIER_EXPECT_TX(addr, tx) \
    asm volatile("mbarrier.arrive.expect_tx.shared.b64 _, [%0], %1;" :: "r"((uint32_t)(addr)), "r"((uint32_t)(tx)) : "memory")
#define MBARRIER_ARRIVE(addr) \
    asm volatile("mbarrier.arrive.shared.b64 _, [%0];" :: "r"((uint32_t)(addr)) : "memory")
#define MBARRIER_WAIT_PARITY(addr, par) do {                                     \
    uint32_t _m = (uint32_t)(addr); uint32_t _p = (uint32_t)(par); uint32_t _d;  \
    asm volatile("{\n\t.reg .pred p;\n\t"                                        \
        "mbarrier.try_wait.parity.acquire.cta.shared::cta.b64 p, [%1], %2;\n\t"  \
        "selp.b32 %0, 1, 0, p;\n\t}" : "=r"(_d) : "r"(_m), "r"(_p) : "memory");  \
    if (!_d) {                                                                   \
        asm volatile("{\n\t.reg .pred P1;\n\t"                                   \
            "WL_%=:\n\t"                                                         \
            "mbarrier.try_wait.parity.acquire.cta.shared::cta.b64 P1, [%0], %1, 0x989680;\n\t" \
            "@P1 bra.uni WD_%=;\n\t"                                             \
            "bra.uni WL_%=;\n\t"                                                 \
            "WD_%=:\n\t}" :: "r"(_m), "r"(_p) : "memory");                       \
    }                                                                            \
} while (0)

__device__ __forceinline__ void bulk_g2s(uint32_t dst, const void* src, uint32_t bytes, uint32_t mbar) {
    asm volatile("cp.async.bulk.shared::cta.global.mbarrier::complete_tx::bytes [%0], [%1], %2, [%3];"
        :: "r"(dst), "l"(src), "r"(bytes), "r"(mbar) : "memory");
}

// ---------------------------------------------------------------------------
// Kernel 1: proj + head projections + sumsq (g_ss pre-scaled by L2SQ)
// ---------------------------------------------------------------------------
__global__ void __launch_bounds__(256) k_proj(const float* __restrict__ x,
                                              const float* __restrict__ pw,
                                              const float* __restrict__ pb,
                                              const float* __restrict__ hw,
                                              const float* __restrict__ hb)
{
    __shared__ float As[64 * 68];
    __shared__ float Ws[64 * 64];
    const int tid = threadIdx.x;
    const int ty = tid >> 4, tx = tid & 15;
    const int row0 = blockIdx.x * 64;

    float acc[4][4];
#pragma unroll
    for (int i = 0; i < 4; i++)
#pragma unroll
        for (int j = 0; j < 4; j++) acc[i][j] = 0.f;

    for (int kk = 0; kk < D_IN; kk += 64) {
#pragma unroll
        for (int l = 0; l < 4; l++) {
            int idx = tid + l * 256;
            int r = idx >> 4, c = (idx & 15) << 2;
            *(float4*)&As[r * 68 + c] = *(const float4*)&x[(size_t)(row0 + r) * D_IN + kk + c];
            *(float4*)&Ws[r * 64 + c] = *(const float4*)&pw[(size_t)(kk + r) * D_H + c];
        }
        __syncthreads();
#pragma unroll 8
        for (int k = 0; k < 64; k++) {
            float a0 = As[(4 * ty + 0) * 68 + k];
            float a1 = As[(4 * ty + 1) * 68 + k];
            float a2 = As[(4 * ty + 2) * 68 + k];
            float a3 = As[(4 * ty + 3) * 68 + k];
            float4 b = *(const float4*)&Ws[k * 64 + 4 * tx];
            acc[0][0] += a0 * b.x; acc[0][1] += a0 * b.y; acc[0][2] += a0 * b.z; acc[0][3] += a0 * b.w;
            acc[1][0] += a1 * b.x; acc[1][1] += a1 * b.y; acc[1][2] += a1 * b.z; acc[1][3] += a1 * b.w;
            acc[2][0] += a2 * b.x; acc[2][1] += a2 * b.y; acc[2][2] += a2 * b.z; acc[2][3] += a2 * b.w;
            acc[3][0] += a3 * b.x; acc[3][1] += a3 * b.y; acc[3][2] += a3 * b.z; acc[3][3] += a3 * b.w;
        }
        __syncthreads();
    }
    {
        float4 pbv = *(const float4*)&pb[4 * tx];
        float pbz[4] = {pbv.x, pbv.y, pbv.z, pbv.w};
#pragma unroll
        for (int i = 0; i < 4; i++)
#pragma unroll
            for (int j = 0; j < 4; j++)
                As[(4 * ty + i) * 68 + 4 * tx + j] = fmaxf(acc[i][j] + pbz[j], 0.f);
    }
    __syncthreads();

    for (int h = 0; h < N_HEADS; h++) {
#pragma unroll
        for (int l = 0; l < 4; l++) {
            int idx = tid + l * 256;
            int r = idx >> 4, c = (idx & 15) << 2;
            *(float4*)&Ws[r * 64 + c] = *(const float4*)&hw[((size_t)h * 64 + r) * 64 + c];
        }
        __syncthreads();

        float a2c[4][4];
#pragma unroll
        for (int i = 0; i < 4; i++)
#pragma unroll
            for (int j = 0; j < 4; j++) a2c[i][j] = 0.f;

#pragma unroll 8
        for (int k = 0; k < 64; k++) {
            float a0 = As[(4 * ty + 0) * 68 + k];
            float a1 = As[(4 * ty + 1) * 68 + k];
            float a2 = As[(4 * ty + 2) * 68 + k];
            float a3 = As[(4 * ty + 3) * 68 + k];
            float4 b = *(const float4*)&Ws[k * 64 + 4 * tx];
            a2c[0][0] += a0 * b.x; a2c[0][1] += a0 * b.y; a2c[0][2] += a0 * b.z; a2c[0][3] += a0 * b.w;
            a2c[1][0] += a1 * b.x; a2c[1][1] += a1 * b.y; a2c[1][2] += a1 * b.z; a2c[1][3] += a1 * b.w;
            a2c[2][0] += a2 * b.x; a2c[2][1] += a2 * b.y; a2c[2][2] += a2 * b.z; a2c[2][3] += a2 * b.w;
            a2c[3][0] += a3 * b.x; a2c[3][1] += a3 * b.y; a2c[3][2] += a3 * b.z; a2c[3][3] += a3 * b.w;
        }

        float4 hbv = *(const float4*)&hb[h * 64 + 4 * tx];
        float hbz[4] = {hbv.x, hbv.y, hbv.z, hbv.w};
#pragma unroll
        for (int i = 0; i < 4; i++) {
            float v0 = a2c[i][0] + hbz[0];
            float v1 = a2c[i][1] + hbz[1];
            float v2 = a2c[i][2] + hbz[2];
            float v3 = a2c[i][3] + hbz[3];
            float rs = v0 * v0 + v1 * v1 + v2 * v2 + v3 * v3;
            *(float4*)&g_hp[((size_t)h * N_TOK + row0 + 4 * ty + i) * D_H + 4 * tx] =
                make_float4(v0, v1, v2, v3);
#pragma unroll
            for (int w = 1; w < 16; w <<= 1)
                rs += __shfl_xor_sync(0xffffffffu, rs, w, 16);
            if (tx == 0) g_ss[(size_t)h * N_TOK + row0 + 4 * ty + i] = rs * L2SQ;
        }
        __syncthreads();
    }
}

// ---------------------------------------------------------------------------
// Kernel 1b: fp16 hi/lo K images + fp16 Vt image.
// ---------------------------------------------------------------------------
__global__ void __launch_bounds__(128) k_prep()
{
    __shared__ float tile[128][65];
    const int t = blockIdx.x, head = blockIdx.y, tid = threadIdx.x;

    const float* src = g_hp + ((size_t)head * N_TOK + (size_t)t * 128 + tid) * 64;
    uint32_t* kh = g_khi + ((size_t)head * 64 + t) * 4608;
    uint32_t* kl = g_klo + ((size_t)head * 64 + t) * 4608;
#pragma unroll 8
    for (int m = 0; m < 32; m++) {
        float f0 = src[2 * m], f1 = src[2 * m + 1];
        tile[tid][2 * m] = f0;
        tile[tid][2 * m + 1] = f1;
        __half h0 = __float2half(f0), h1 = __float2half(f1);
        kh[tid * 36 + m] = packh2(h0, h1);
        kl[tid * 36 + m] = f16pack(f0 - __half2float(h0), f1 - __half2float(h1));
    }
    __syncthreads();

    uint32_t* vh = g_v16 + ((size_t)head * 64 + t) * 4352;
    const int d = tid >> 1, half = tid & 1;
#pragma unroll 8
    for (int m = 0; m < 32; m++) {
        int key = half * 64 + 2 * m;
        vh[d * 68 + half * 32 + m] = f16pack(tile[key][d], tile[key + 1][d]);
    }
}

// profiling alignment shim (lets ncu -s 5 land on k_attn)
__global__ void k_dummy() {}

// ---------------------------------------------------------------------------
// Kernel 2: split-K distance flash-attention, 16 consumer warps (4/SMSP).
//  GEMM1: fp16 2-product  S = Qhi.(Khi + Klo)
//  Epilogue: sq pre-scaled by L2SQ (p = ex2(-sqrt(sq2))); diagonal forcing
//            hoisted behind a uniform per-tile branch.
// ---------------------------------------------------------------------------
#define SM_FULL(s)  ((s) * 8)
#define SM_EMPTY(s) (24 + (s) * 8)
#define SM_Q       128
#define SM_STG     (SM_Q + 18432)            // 18560
#define OFF_KHI    0
#define OFF_KLO    18432
#define OFF_V16    36864
#define OFF_KK     54272
#define STG_BYTES  54784
#define N_STAGES   3
#define T_PER_CTA  16
#define SM_TOTAL   (SM_STG + N_STAGES * STG_BYTES)   // 182912

__global__ void __launch_bounds__(544, 1) k_attn()
{
    extern __shared__ char smem[];
    const uint32_t sb = smem_u32(smem);
    const int tid  = threadIdx.x;
    const int warp = tid >> 5;
    const int lane = tid & 31;
    const int head = blockIdx.y;
    const int split = blockIdx.z;
    const int q0 = blockIdx.x * 128;
    const int t0 = split * T_PER_CTA;
    const float* ssq = g_ss + (size_t)head * N_TOK;

    if (tid == 0) {
#pragma unroll
        for (int s = 0; s < N_STAGES; s++) {
            MBARRIER_INIT(sb + SM_FULL(s), 1);
            MBARRIER_INIT(sb + SM_EMPTY(s), 16);
        }
    }

    // Q hi image resident in smem for the whole CTA
    {
        const uint4* sh = (const uint4*)(g_khi + ((size_t)head * 64 + blockIdx.x) * 4608);
        uint4* dh = (uint4*)(smem + SM_Q);
        for (int i = tid; i < 1152; i += 544) dh[i] = sh[i];
    }
    __syncthreads();

    const int w7 = warp & 7;
    const int khalf = (warp & 8) ? 64 : 0;
    const int g  = lane >> 2;
    const int lt = lane & 3;
    const int mm = lane >> 3;
    const int r8 = lane & 7;
    const int q_dsel = (mm >> 1) * 16;
    const int k_dsel = (mm & 1) * 16;
    const int k_rowofs = r8 + (mm >> 1) * 8;
    const int q_row = 16 * w7 + r8 + (mm & 1) * 8;

    const int r0g = q0 + 16 * w7 + g;
    const int r1g = r0g + 8;

    float O[8][4];
#pragma unroll
    for (int n = 0; n < 8; n++)
#pragma unroll
        for (int e = 0; e < 4; e++) O[n][e] = 0.f;
    float l0 = 0.f, l1 = 0.f;

    if (warp == 16) {
        // ---------------- producer warp ----------------
        if (lane == 0) {
            const size_t hb = (size_t)head * 64 + t0;
#pragma unroll
            for (int i = 0; i < N_STAGES; i++) {
                const uint32_t st = sb + SM_STG + i * STG_BYTES;
                MBARRIER_EXPECT_TX(sb + SM_FULL(i), STG_BYTES);
                bulk_g2s(st + OFF_KHI, g_khi + (hb + i) * 4608, 18432, sb + SM_FULL(i));
                bulk_g2s(st + OFF_KLO, g_klo + (hb + i) * 4608, 18432, sb + SM_FULL(i));
                bulk_g2s(st + OFF_V16, g_v16 + (hb + i) * 4352, 17408, sb + SM_FULL(i));
                bulk_g2s(st + OFF_KK,  ssq + (size_t)(t0 + i) * 128, 512, sb + SM_FULL(i));
            }
            int s = 0, pe = 0;
            for (int i = N_STAGES; i < T_PER_CTA; i++) {
                MBARRIER_WAIT_PARITY(sb + SM_EMPTY(s), pe);
                const uint32_t st = sb + SM_STG + s * STG_BYTES;
                MBARRIER_EXPECT_TX(sb + SM_FULL(s), STG_BYTES);
                bulk_g2s(st + OFF_KHI, g_khi + (hb + i) * 4608, 18432, sb + SM_FULL(s));
                bulk_g2s(st + OFF_KLO, g_klo + (hb + i) * 4608, 18432, sb + SM_FULL(s));
                bulk_g2s(st + OFF_V16, g_v16 + (hb + i) * 4352, 17408, sb + SM_FULL(s));
                bulk_g2s(st + OFF_KK,  ssq + (size_t)(t0 + i) * 128, 512, sb + SM_FULL(s));
                if (++s == N_STAGES) { s = 0; pe ^= 1; }
            }
        }
    } else {
        // ---------------- consumer warps (0..15) ----------------
        const float qq0 = ssq[r0g];     // already *L2SQ
        const float qq1 = ssq[r1g];
        const float N2L = -2.f * L2SQ;

        int s = 0, ph = 0;
        for (int i = 0; i < T_PER_CTA; i++) {
            const int t = t0 + i;
            MBARRIER_WAIT_PARITY(sb + SM_FULL(s), ph);
            const uint32_t stg = sb + SM_STG + s * STG_BYTES;

            // ---- GEMM1: S = Qhi.(Khi + Klo), fp16 2-product ----
            float S[8][4];
#pragma unroll
            for (int n = 0; n < 8; n++)
#pragma unroll
                for (int e = 0; e < 4; e++) S[n][e] = 0.f;

#pragma unroll
            for (int kc = 0; kc < 4; kc++) {
                uint32_t qh[4];
                ldsm4(qh, sb + SM_Q + q_row * 144 + kc * 32 + q_dsel);
#pragma unroll
                for (int np = 0; np < 4; np++) {
                    uint32_t kb[4], lb[4];
                    uint32_t ka = stg + OFF_KHI + (khalf + 16 * np + k_rowofs) * 144 + kc * 32 + k_dsel;
                    ldsm4(kb, ka);
                    ldsm4(lb, ka + 18432);
                    mma16816h(S[2 * np],     qh, kb[0], kb[1]);
                    mma16816h(S[2 * np],     qh, lb[0], lb[1]);
                    mma16816h(S[2 * np + 1], qh, kb[2], kb[3]);
                    mma16816h(S[2 * np + 1], qh, lb[2], lb[3]);
                }
            }

            // ---- GEMM2 with interleaved slim softmax epilogue ----
            const float* kkp = (const float*)(smem + SM_STG + s * STG_BYTES + OFF_KK);
            const bool dt = (t == (int)blockIdx.x);   // only tile that can hold the diagonal
            const int kt = t * 128;
#pragma unroll
            for (int kc2 = 0; kc2 < 4; kc2++) {
#pragma unroll
                for (int u = 0; u < 2; u++) {
                    const int nt = 2 * kc2 + u;
                    float2 kkv = *(const float2*)(kkp + khalf + 8 * nt + 2 * lt);
                    float a00 = qq0 + kkv.x, a01 = qq0 + kkv.y;
                    float a10 = qq1 + kkv.x, a11 = qq1 + kkv.y;
                    S[nt][0] = ex2f(0.f - sqrtapx(fmaxf(fmaf(S[nt][0], N2L, a00), 0.f)));
                    S[nt][1] = ex2f(0.f - sqrtapx(fmaxf(fmaf(S[nt][1], N2L, a01), 0.f)));
                    S[nt][2] = ex2f(0.f - sqrtapx(fmaxf(fmaf(S[nt][2], N2L, a10), 0.f)));
                    S[nt][3] = ex2f(0.f - sqrtapx(fmaxf(fmaf(S[nt][3], N2L, a11), 0.f)));
                    if (dt) {
                        const int colg = kt + khalf + 8 * nt + 2 * lt;
                        if (colg == r0g)     S[nt][0] = 1.f;
                        if (colg + 1 == r0g) S[nt][1] = 1.f;
                        if (colg == r1g)     S[nt][2] = 1.f;
                        if (colg + 1 == r1g) S[nt][3] = 1.f;
                    }
                    l0 += S[nt][0] + S[nt][1];
                    l1 += S[nt][2] + S[nt][3];
                }
                uint32_t aF[4];
                aF[0] = f16pack(S[2 * kc2][0],     S[2 * kc2][1]);
                aF[1] = f16pack(S[2 * kc2][2],     S[2 * kc2][3]);
                aF[2] = f16pack(S[2 * kc2 + 1][0], S[2 * kc2 + 1][1]);
                aF[3] = f16pack(S[2 * kc2 + 1][2], S[2 * kc2 + 1][3]);
#pragma unroll
                for (int j = 0; j < 4; j++) {
                    uint32_t vb[4];
                    uint32_t va = stg + OFF_V16 + (16 * j + k_rowofs) * 272
                                + (khalf + 16 * kc2) * 2 + k_dsel;
                    ldsm4(vb, va);
                    mma16816h(O[2 * j],     aF, vb[0], vb[1]);
                    mma16816h(O[2 * j + 1], aF, vb[2], vb[3]);
                }
            }

            if (lane == 0) MBARRIER_ARRIVE(sb + SM_EMPTY(s));
            if (++s == N_STAGES) { s = 0; ph ^= 1; }
        }

        // per-warp l reduction over the 4 lanes sharing each row
        l0 += __shfl_xor_sync(0xffffffffu, l0, 1);
        l0 += __shfl_xor_sync(0xffffffffu, l0, 2);
        l1 += __shfl_xor_sync(0xffffffffu, l1, 1);
        l1 += __shfl_xor_sync(0xffffffffu, l1, 2);
    }

    // ---- cross-half reduction through (now free) stage smem ----
    __syncthreads();
    float* red  = (float*)(smem + SM_STG);             // 8 * 16 * 64 floats = 32KB
    float* lred = (float*)(smem + SM_STG + 32768);     // 8 * 16 floats

    if (warp >= 8 && warp < 16) {
#pragma unroll
        for (int n = 0; n < 8; n++)
#pragma unroll
            for (int e = 0; e < 4; e++) {
                int row = g + ((e >> 1) << 3);
                int col = 8 * n + 2 * lt + (e & 1);
                red[w7 * 1024 + row * 64 + col] = O[n][e];
            }
        if (lt == 0) {
            lred[w7 * 16 + g] = l0;
            lred[w7 * 16 + g + 8] = l1;
        }
    }
    __syncthreads();

    if (warp < 8) {
#pragma unroll
        for (int n = 0; n < 8; n++)
#pragma unroll
            for (int e = 0; e < 4; e++) {
                int row = g + ((e >> 1) << 3);
                int col = 8 * n + 2 * lt + (e & 1);
                O[n][e] += red[w7 * 1024 + row * 64 + col];
            }
        l0 += lred[w7 * 16 + g];
        l1 += lred[w7 * 16 + g + 8];

        const size_t pbase = ((size_t)head * N_SPLIT + split) * N_TOK;
        if (lt == 0) {
            g_l[pbase + r0g] = l0;
            g_l[pbase + r1g] = l1;
        }
        float* dst0 = g_ho + (pbase + r0g) * D_H;
        float* dst1 = g_ho + (pbase + r1g) * D_H;
#pragma unroll
        for (int n = 0; n < 8; n++) {
            *(float2*)&dst0[8 * n + 2 * lt] = make_float2(O[n][0], O[n][1]);
            *(float2*)&dst1[8 * n + 2 * lt] = make_float2(O[n][2], O[n][3]);
        }
    }
}

// ---------------------------------------------------------------------------
// Kernel 3: combine split partials + heads, LayerNorm, FC (unchanged)
// ---------------------------------------------------------------------------
__global__ void __launch_bounds__(256) k_final(const float* __restrict__ attn_w,
                                               const float* __restrict__ gamma,
                                               const float* __restrict__ beta,
                                               const float* __restrict__ fcw,
                                               const float* __restrict__ fcb,
                                               float* __restrict__ out)
{
    const int warp = threadIdx.x >> 5;
    const int lane = threadIdx.x & 31;
    const int row = blockIdx.x * 8 + warp;

    float a0 = attn_w[0], a1 = attn_w[1], a2 = attn_w[2], a3 = attn_w[3];
    float mx = fmaxf(fmaxf(a0, a1), fmaxf(a2, a3));
    float aw[4];
    aw[0] = __expf(a0 - mx); aw[1] = __expf(a1 - mx);
    aw[2] = __expf(a2 - mx); aw[3] = __expf(a3 - mx);
    float ainv = 1.f / (aw[0] + aw[1] + aw[2] + aw[3]);

    const int d0 = lane, d1 = lane + 32;
    float c0 = 0.f, c1 = 0.f;
#pragma unroll
    for (int h = 0; h < N_HEADS; h++) {
        float lsum = 0.f;
        float o0 = 0.f, o1 = 0.f;
#pragma unroll
        for (int s = 0; s < N_SPLIT; s++) {
            const size_t pbase = ((size_t)h * N_SPLIT + s) * N_TOK + row;
            lsum += g_l[pbase];
            const float* p = g_ho + pbase * D_H;
            o0 += p[d0];
            o1 += p[d1];
        }
        float w = aw[h] / lsum;
        c0 += w * o0;
        c1 += w * o1;
    }
    c0 *= ainv; c1 *= ainv;

    float s = c0 + c1;
#pragma unroll
    for (int w = 16; w; w >>= 1) s += __shfl_xor_sync(0xffffffffu, s, w);
    float mu = s * (1.f / 64.f);
    float v0 = c0 - mu, v1 = c1 - mu;
    float vv = v0 * v0 + v1 * v1;
#pragma unroll
    for (int w = 16; w; w >>= 1) vv += __shfl_xor_sync(0xffffffffu, vv, w);
    float inv = rsqrtf(vv * (1.f / 64.f) + LN_EPS);
    float n0 = v0 * inv * gamma[d0] + beta[d0];
    float n1 = v1 * inv * gamma[d1] + beta[d1];

    float o[N_CLS];
#pragma unroll
    for (int c = 0; c < N_CLS; c++)
        o[c] = n0 * fcw[d0 * N_CLS + c] + n1 * fcw[d1 * N_CLS + c];
#pragma unroll
    for (int c = 0; c < N_CLS; c++)
#pragma unroll
        for (int w = 16; w; w >>= 1) o[c] += __shfl_xor_sync(0xffffffffu, o[c], w);

    if (lane == 0) {
#pragma unroll
        for (int c = 0; c < N_CLS; c++)
            out[(size_t)row * N_CLS + c] = o[c] + fcb[c];
    }
}

// ---------------------------------------------------------------------------
extern "C" void kernel_launch(void* const* d_in, const int* in_sizes, int n_in,
                              void* d_out, int out_size)
{
    const float* x      = (const float*)d_in[0];
    const float* proj_w = (const float*)d_in[1];
    const float* proj_b = (const float*)d_in[2];
    const float* head_w = (const float*)d_in[3];
    const float* head_b = (const float*)d_in[4];
    const float* attn_w = (const float*)d_in[5];
    const float* gamma  = (const float*)d_in[6];
    const float* beta   = (const float*)d_in[7];
    const float* fc_w   = (const float*)d_in[8];
    const float* fc_b   = (const float*)d_in[9];
    float* out = (float*)d_out;

    static int smem_set = 0;
    if (!smem_set) {
        cudaFuncSetAttribute(k_attn, cudaFuncAttributeMaxDynamicSharedMemorySize, SM_TOTAL);
        smem_set = 1;
    }

    k_proj<<<N_TOK / 64, 256>>>(x, proj_w, proj_b, head_w, head_b);

    dim3 gp(64, N_HEADS);
    k_prep<<<gp, 128>>>();

    k_dummy<<<1, 32>>>();   // aligns ncu -s 5 onto k_attn

    dim3 g2(N_TOK / 128, N_HEADS, N_SPLIT);
    k_attn<<<g2, 544, SM_TOTAL>>>();

    k_final<<<N_TOK / 8, 256>>>(attn_w, gamma, beta, fc_w, fc_b, out);
}

// round 10
// speedup vs baseline: 9.9407x; 1.2082x over previous
#include <cuda_runtime.h>
#include <cuda_bf16.h>
#include <cuda_fp16.h>
#include <cstdint>
#include <cstddef>

#define N_TOK   8192
#define D_IN    384
#define D_H     64
#define N_HEADS 4
#define N_CLS   6
#define N_SPLIT 4
#define LN_EPS  1e-5f
#define L2SQ    2.0813689810056077f   // (log2 e)^2

// ---------------- scratch (no allocations allowed) ----------------
__device__ float g_hp[(size_t)N_HEADS * N_TOK * D_H];
__device__ float g_ss[(size_t)N_HEADS * N_TOK];                   // ||hp||^2 * L2SQ
__device__ float g_ho[(size_t)N_HEADS * N_SPLIT * N_TOK * D_H];   // partial O (unnormalized)
__device__ float g_l [(size_t)N_HEADS * N_SPLIT * N_TOK];         // partial softmax denominators
// fp16 tile images (u32 = 2 halves):
//  K image per tile: 128 rows x 36 u32 (72 fp16: d 0..63 + pad)     = 4608 u32
//  Vt image per tile: 64 d-rows x 68 u32 (136 fp16: key 0..127+pad) = 4352 u32
__device__ __align__(256) uint32_t g_k16[(size_t)N_HEADS * 64 * 4608];
__device__ __align__(256) uint32_t g_v16[(size_t)N_HEADS * 64 * 4352];

// ---------------- helpers ----------------
__device__ __forceinline__ uint32_t smem_u32(const void* p) {
    uint32_t a;
    asm("{ .reg .u64 t; cvta.to.shared.u64 t, %1; cvt.u32.u64 %0, t; }" : "=r"(a) : "l"(p));
    return a;
}
__device__ __forceinline__ float ex2f(float x) {
    float r; asm("ex2.approx.f32 %0, %1;" : "=f"(r) : "f"(x)); return r;
}
__device__ __forceinline__ float sqrtapx(float x) {
    float r; asm("sqrt.approx.f32 %0, %1;" : "=f"(r) : "f"(x)); return r;
}
__device__ __forceinline__ uint32_t f16pack(float lo, float hi) {
    uint32_t r; asm("cvt.rn.f16x2.f32 %0, %1, %2;" : "=r"(r) : "f"(hi), "f"(lo)); return r;
}
__device__ __forceinline__ void mma16816h(float c[4], const uint32_t a[4], uint32_t b0, uint32_t b1) {
    asm volatile("mma.sync.aligned.m16n8k16.row.col.f32.f16.f16.f32 "
        "{%0,%1,%2,%3}, {%4,%5,%6,%7}, {%8,%9}, {%0,%1,%2,%3};"
        : "+f"(c[0]), "+f"(c[1]), "+f"(c[2]), "+f"(c[3])
        : "r"(a[0]), "r"(a[1]), "r"(a[2]), "r"(a[3]), "r"(b0), "r"(b1));
}
__device__ __forceinline__ void ldsm4(uint32_t r[4], uint32_t addr) {
    asm volatile("ldmatrix.sync.aligned.m8n8.x4.shared.b16 {%0,%1,%2,%3}, [%4];"
        : "=r"(r[0]), "=r"(r[1]), "=r"(r[2]), "=r"(r[3]) : "r"(addr));
}

#define MBARRIER_INIT(addr, cnt) \
    asm volatile("mbarrier.init.shared.b64 [%0], %1;" :: "r"((uint32_t)(addr)), "r"((uint32_t)(cnt)) : "memory")
#define MBARRIER_EXPECT_TX(addr, tx) \
    asm volatile("mbarrier.arrive.expect_tx.shared.b64 _, [%0], %1;" :: "r"((uint32_t)(addr)), "r"((uint32_t)(tx)) : "memory")
#define MBARRIER_ARRIVE(addr) \
    asm volatile("mbarrier.arrive.shared.b64 _, [%0];" :: "r"((uint32_t)(addr)) : "memory")
#define MBARRIER_WAIT_PARITY(addr, par) do {                                     \
    uint32_t _m = (uint32_t)(addr); uint32_t _p = (uint32_t)(par); uint32_t _d;  \
    asm volatile("{\n\t.reg .pred p;\n\t"                                        \
        "mbarrier.try_wait.parity.acquire.cta.shared::cta.b64 p, [%1], %2;\n\t"  \
        "selp.b32 %0, 1, 0, p;\n\t}" : "=r"(_d) : "r"(_m), "r"(_p) : "memory");  \
    if (!_d) {                                                                   \
        asm volatile("{\n\t.reg .pred P1;\n\t"                                   \
            "WL_%=:\n\t"                                                         \
            "mbarrier.try_wait.parity.acquire.cta.shared::cta.b64 P1, [%0], %1, 0x989680;\n\t" \
            "@P1 bra.uni WD_%=;\n\t"                                             \
            "bra.uni WL_%=;\n\t"                                                 \
            "WD_%=:\n\t}" :: "r"(_m), "r"(_p) : "memory");                       \
    }                                                                            \
} while (0)

__device__ __forceinline__ void bulk_g2s(uint32_t dst, const void* src, uint32_t bytes, uint32_t mbar) {
    asm volatile("cp.async.bulk.shared::cta.global.mbarrier::complete_tx::bytes [%0], [%1], %2, [%3];"
        :: "r"(dst), "l"(src), "r"(bytes), "r"(mbar) : "memory");
}

// ---------------------------------------------------------------------------
// Kernel 1: proj + head projections + sumsq (g_ss pre-scaled by L2SQ)
// ---------------------------------------------------------------------------
__global__ void __launch_bounds__(256) k_proj(const float* __restrict__ x,
                                              const float* __restrict__ pw,
                                              const float* __restrict__ pb,
                                              const float* __restrict__ hw,
                                              const float* __restrict__ hb)
{
    __shared__ float As[64 * 68];
    __shared__ float Ws[64 * 64];
    const int tid = threadIdx.x;
    const int ty = tid >> 4, tx = tid & 15;
    const int row0 = blockIdx.x * 64;

    float acc[4][4];
#pragma unroll
    for (int i = 0; i < 4; i++)
#pragma unroll
        for (int j = 0; j < 4; j++) acc[i][j] = 0.f;

    for (int kk = 0; kk < D_IN; kk += 64) {
#pragma unroll
        for (int l = 0; l < 4; l++) {
            int idx = tid + l * 256;
            int r = idx >> 4, c = (idx & 15) << 2;
            *(float4*)&As[r * 68 + c] = *(const float4*)&x[(size_t)(row0 + r) * D_IN + kk + c];
            *(float4*)&Ws[r * 64 + c] = *(const float4*)&pw[(size_t)(kk + r) * D_H + c];
        }
        __syncthreads();
#pragma unroll 8
        for (int k = 0; k < 64; k++) {
            float a0 = As[(4 * ty + 0) * 68 + k];
            float a1 = As[(4 * ty + 1) * 68 + k];
            float a2 = As[(4 * ty + 2) * 68 + k];
            float a3 = As[(4 * ty + 3) * 68 + k];
            float4 b = *(const float4*)&Ws[k * 64 + 4 * tx];
            acc[0][0] += a0 * b.x; acc[0][1] += a0 * b.y; acc[0][2] += a0 * b.z; acc[0][3] += a0 * b.w;
            acc[1][0] += a1 * b.x; acc[1][1] += a1 * b.y; acc[1][2] += a1 * b.z; acc[1][3] += a1 * b.w;
            acc[2][0] += a2 * b.x; acc[2][1] += a2 * b.y; acc[2][2] += a2 * b.z; acc[2][3] += a2 * b.w;
            acc[3][0] += a3 * b.x; acc[3][1] += a3 * b.y; acc[3][2] += a3 * b.z; acc[3][3] += a3 * b.w;
        }
        __syncthreads();
    }
    {
        float4 pbv = *(const float4*)&pb[4 * tx];
        float pbz[4] = {pbv.x, pbv.y, pbv.z, pbv.w};
#pragma unroll
        for (int i = 0; i < 4; i++)
#pragma unroll
            for (int j = 0; j < 4; j++)
                As[(4 * ty + i) * 68 + 4 * tx + j] = fmaxf(acc[i][j] + pbz[j], 0.f);
    }
    __syncthreads();

    for (int h = 0; h < N_HEADS; h++) {
#pragma unroll
        for (int l = 0; l < 4; l++) {
            int idx = tid + l * 256;
            int r = idx >> 4, c = (idx & 15) << 2;
            *(float4*)&Ws[r * 64 + c] = *(const float4*)&hw[((size_t)h * 64 + r) * 64 + c];
        }
        __syncthreads();

        float a2c[4][4];
#pragma unroll
        for (int i = 0; i < 4; i++)
#pragma unroll
            for (int j = 0; j < 4; j++) a2c[i][j] = 0.f;

#pragma unroll 8
        for (int k = 0; k < 64; k++) {
            float a0 = As[(4 * ty + 0) * 68 + k];
            float a1 = As[(4 * ty + 1) * 68 + k];
            float a2 = As[(4 * ty + 2) * 68 + k];
            float a3 = As[(4 * ty + 3) * 68 + k];
            float4 b = *(const float4*)&Ws[k * 64 + 4 * tx];
            a2c[0][0] += a0 * b.x; a2c[0][1] += a0 * b.y; a2c[0][2] += a0 * b.z; a2c[0][3] += a0 * b.w;
            a2c[1][0] += a1 * b.x; a2c[1][1] += a1 * b.y; a2c[1][2] += a1 * b.z; a2c[1][3] += a1 * b.w;
            a2c[2][0] += a2 * b.x; a2c[2][1] += a2 * b.y; a2c[2][2] += a2 * b.z; a2c[2][3] += a2 * b.w;
            a2c[3][0] += a3 * b.x; a2c[3][1] += a3 * b.y; a2c[3][2] += a3 * b.z; a2c[3][3] += a3 * b.w;
        }

        float4 hbv = *(const float4*)&hb[h * 64 + 4 * tx];
        float hbz[4] = {hbv.x, hbv.y, hbv.z, hbv.w};
#pragma unroll
        for (int i = 0; i < 4; i++) {
            float v0 = a2c[i][0] + hbz[0];
            float v1 = a2c[i][1] + hbz[1];
            float v2 = a2c[i][2] + hbz[2];
            float v3 = a2c[i][3] + hbz[3];
            float rs = v0 * v0 + v1 * v1 + v2 * v2 + v3 * v3;
            *(float4*)&g_hp[((size_t)h * N_TOK + row0 + 4 * ty + i) * D_H + 4 * tx] =
                make_float4(v0, v1, v2, v3);
#pragma unroll
            for (int w = 1; w < 16; w <<= 1)
                rs += __shfl_xor_sync(0xffffffffu, rs, w, 16);
            if (tx == 0) g_ss[(size_t)h * N_TOK + row0 + 4 * ty + i] = rs * L2SQ;
        }
        __syncthreads();
    }
}

// ---------------------------------------------------------------------------
// Kernel 1b: fp16 K image + fp16 Vt image.
// ---------------------------------------------------------------------------
__global__ void __launch_bounds__(128) k_prep()
{
    __shared__ float tile[128][65];
    const int t = blockIdx.x, head = blockIdx.y, tid = threadIdx.x;

    const float* src = g_hp + ((size_t)head * N_TOK + (size_t)t * 128 + tid) * 64;
    uint32_t* kh = g_k16 + ((size_t)head * 64 + t) * 4608;
#pragma unroll 8
    for (int m = 0; m < 32; m++) {
        float f0 = src[2 * m], f1 = src[2 * m + 1];
        tile[tid][2 * m] = f0;
        tile[tid][2 * m + 1] = f1;
        kh[tid * 36 + m] = f16pack(f0, f1);
    }
    __syncthreads();

    uint32_t* vh = g_v16 + ((size_t)head * 64 + t) * 4352;
    const int d = tid >> 1, half = tid & 1;
#pragma unroll 8
    for (int m = 0; m < 32; m++) {
        int key = half * 64 + 2 * m;
        vh[d * 68 + half * 32 + m] = f16pack(tile[key][d], tile[key + 1][d]);
    }
}

// profiling alignment shim (lets ncu -s 5 land on k_attn)
__global__ void k_dummy() {}

// ---------------------------------------------------------------------------
// Kernel 2: split-K distance flash-attention, 16 consumer warps (4/SMSP).
//  GEMM1: fp16 single product S = Q.K (fp16 quantization error averages out:
//  distances concentrate ~7 in 64-d gaussian data; diagonal forced exact).
// ---------------------------------------------------------------------------
#define SM_FULL(s)  ((s) * 8)
#define SM_EMPTY(s) (24 + (s) * 8)
#define SM_Q       128
#define SM_STG     (SM_Q + 18432)            // 18560
#define OFF_K16    0
#define OFF_V16    18432
#define OFF_KK     35840
#define STG_BYTES  36352
#define N_STAGES   3
#define T_PER_CTA  16
#define SM_TOTAL   (SM_STG + N_STAGES * STG_BYTES)   // 127616

__global__ void __launch_bounds__(544, 1) k_attn()
{
    extern __shared__ char smem[];
    const uint32_t sb = smem_u32(smem);
    const int tid  = threadIdx.x;
    const int warp = tid >> 5;
    const int lane = tid & 31;
    const int head = blockIdx.y;
    const int split = blockIdx.z;
    const int q0 = blockIdx.x * 128;
    const int t0 = split * T_PER_CTA;
    const float* ssq = g_ss + (size_t)head * N_TOK;

    if (tid == 0) {
#pragma unroll
        for (int s = 0; s < N_STAGES; s++) {
            MBARRIER_INIT(sb + SM_FULL(s), 1);
            MBARRIER_INIT(sb + SM_EMPTY(s), 16);
        }
    }

    // Q image resident in smem for the whole CTA
    {
        const uint4* sh = (const uint4*)(g_k16 + ((size_t)head * 64 + blockIdx.x) * 4608);
        uint4* dh = (uint4*)(smem + SM_Q);
        for (int i = tid; i < 1152; i += 544) dh[i] = sh[i];
    }
    __syncthreads();

    const int w7 = warp & 7;
    const int khalf = (warp & 8) ? 64 : 0;
    const int g  = lane >> 2;
    const int lt = lane & 3;
    const int mm = lane >> 3;
    const int r8 = lane & 7;
    const int q_dsel = (mm >> 1) * 16;
    const int k_dsel = (mm & 1) * 16;
    const int k_rowofs = r8 + (mm >> 1) * 8;
    const int q_row = 16 * w7 + r8 + (mm & 1) * 8;

    const int r0g = q0 + 16 * w7 + g;
    const int r1g = r0g + 8;

    float O[8][4];
#pragma unroll
    for (int n = 0; n < 8; n++)
#pragma unroll
        for (int e = 0; e < 4; e++) O[n][e] = 0.f;
    float l0 = 0.f, l1 = 0.f;

    if (warp == 16) {
        // ---------------- producer warp ----------------
        if (lane == 0) {
            const size_t hb = (size_t)head * 64 + t0;
#pragma unroll
            for (int i = 0; i < N_STAGES; i++) {
                const uint32_t st = sb + SM_STG + i * STG_BYTES;
                MBARRIER_EXPECT_TX(sb + SM_FULL(i), STG_BYTES);
                bulk_g2s(st + OFF_K16, g_k16 + (hb + i) * 4608, 18432, sb + SM_FULL(i));
                bulk_g2s(st + OFF_V16, g_v16 + (hb + i) * 4352, 17408, sb + SM_FULL(i));
                bulk_g2s(st + OFF_KK,  ssq + (size_t)(t0 + i) * 128, 512, sb + SM_FULL(i));
            }
            int s = 0, pe = 0;
            for (int i = N_STAGES; i < T_PER_CTA; i++) {
                MBARRIER_WAIT_PARITY(sb + SM_EMPTY(s), pe);
                const uint32_t st = sb + SM_STG + s * STG_BYTES;
                MBARRIER_EXPECT_TX(sb + SM_FULL(s), STG_BYTES);
                bulk_g2s(st + OFF_K16, g_k16 + (hb + i) * 4608, 18432, sb + SM_FULL(s));
                bulk_g2s(st + OFF_V16, g_v16 + (hb + i) * 4352, 17408, sb + SM_FULL(s));
                bulk_g2s(st + OFF_KK,  ssq + (size_t)(t0 + i) * 128, 512, sb + SM_FULL(s));
                if (++s == N_STAGES) { s = 0; pe ^= 1; }
            }
        }
    } else {
        // ---------------- consumer warps (0..15) ----------------
        const float qq0 = ssq[r0g];     // already *L2SQ
        const float qq1 = ssq[r1g];
        const float N2L = -2.f * L2SQ;

        int s = 0, ph = 0;
        for (int i = 0; i < T_PER_CTA; i++) {
            const int t = t0 + i;
            MBARRIER_WAIT_PARITY(sb + SM_FULL(s), ph);
            const uint32_t stg = sb + SM_STG + s * STG_BYTES;

            // ---- GEMM1: S = Q.K, fp16 single product ----
            float S[8][4];
#pragma unroll
            for (int n = 0; n < 8; n++)
#pragma unroll
                for (int e = 0; e < 4; e++) S[n][e] = 0.f;

#pragma unroll
            for (int kc = 0; kc < 4; kc++) {
                uint32_t qh[4];
                ldsm4(qh, sb + SM_Q + q_row * 144 + kc * 32 + q_dsel);
#pragma unroll
                for (int np = 0; np < 4; np++) {
                    uint32_t kb[4];
                    ldsm4(kb, stg + OFF_K16 + (khalf + 16 * np + k_rowofs) * 144 + kc * 32 + k_dsel);
                    mma16816h(S[2 * np],     qh, kb[0], kb[1]);
                    mma16816h(S[2 * np + 1], qh, kb[2], kb[3]);
                }
            }

            // ---- GEMM2 with interleaved slim softmax epilogue ----
            const float* kkp = (const float*)(smem + SM_STG + s * STG_BYTES + OFF_KK);
            const bool dt = (t == (int)blockIdx.x);   // only tile that can hold the diagonal
            const int kt = t * 128;
#pragma unroll
            for (int kc2 = 0; kc2 < 4; kc2++) {
#pragma unroll
                for (int u = 0; u < 2; u++) {
                    const int nt = 2 * kc2 + u;
                    float2 kkv = *(const float2*)(kkp + khalf + 8 * nt + 2 * lt);
                    float a00 = qq0 + kkv.x, a01 = qq0 + kkv.y;
                    float a10 = qq1 + kkv.x, a11 = qq1 + kkv.y;
                    S[nt][0] = ex2f(0.f - sqrtapx(fmaxf(fmaf(S[nt][0], N2L, a00), 0.f)));
                    S[nt][1] = ex2f(0.f - sqrtapx(fmaxf(fmaf(S[nt][1], N2L, a01), 0.f)));
                    S[nt][2] = ex2f(0.f - sqrtapx(fmaxf(fmaf(S[nt][2], N2L, a10), 0.f)));
                    S[nt][3] = ex2f(0.f - sqrtapx(fmaxf(fmaf(S[nt][3], N2L, a11), 0.f)));
                    if (dt) {
                        const int colg = kt + khalf + 8 * nt + 2 * lt;
                        if (colg == r0g)     S[nt][0] = 1.f;
                        if (colg + 1 == r0g) S[nt][1] = 1.f;
                        if (colg == r1g)     S[nt][2] = 1.f;
                        if (colg + 1 == r1g) S[nt][3] = 1.f;
                    }
                    l0 += S[nt][0] + S[nt][1];
                    l1 += S[nt][2] + S[nt][3];
                }
                uint32_t aF[4];
                aF[0] = f16pack(S[2 * kc2][0],     S[2 * kc2][1]);
                aF[1] = f16pack(S[2 * kc2][2],     S[2 * kc2][3]);
                aF[2] = f16pack(S[2 * kc2 + 1][0], S[2 * kc2 + 1][1]);
                aF[3] = f16pack(S[2 * kc2 + 1][2], S[2 * kc2 + 1][3]);
#pragma unroll
                for (int j = 0; j < 4; j++) {
                    uint32_t vb[4];
                    uint32_t va = stg + OFF_V16 + (16 * j + k_rowofs) * 272
                                + (khalf + 16 * kc2) * 2 + k_dsel;
                    ldsm4(vb, va);
                    mma16816h(O[2 * j],     aF, vb[0], vb[1]);
                    mma16816h(O[2 * j + 1], aF, vb[2], vb[3]);
                }
            }

            if (lane == 0) MBARRIER_ARRIVE(sb + SM_EMPTY(s));
            if (++s == N_STAGES) { s = 0; ph ^= 1; }
        }

        // per-warp l reduction over the 4 lanes sharing each row
        l0 += __shfl_xor_sync(0xffffffffu, l0, 1);
        l0 += __shfl_xor_sync(0xffffffffu, l0, 2);
        l1 += __shfl_xor_sync(0xffffffffu, l1, 1);
        l1 += __shfl_xor_sync(0xffffffffu, l1, 2);
    }

    // ---- cross-half reduction through (now free) stage smem ----
    __syncthreads();
    float* red  = (float*)(smem + SM_STG);             // 8 * 16 * 64 floats = 32KB
    float* lred = (float*)(smem + SM_STG + 32768);     // 8 * 16 floats

    if (warp >= 8 && warp < 16) {
#pragma unroll
        for (int n = 0; n < 8; n++)
#pragma unroll
            for (int e = 0; e < 4; e++) {
                int row = g + ((e >> 1) << 3);
                int col = 8 * n + 2 * lt + (e & 1);
                red[w7 * 1024 + row * 64 + col] = O[n][e];
            }
        if (lt == 0) {
            lred[w7 * 16 + g] = l0;
            lred[w7 * 16 + g + 8] = l1;
        }
    }
    __syncthreads();

    if (warp < 8) {
#pragma unroll
        for (int n = 0; n < 8; n++)
#pragma unroll
            for (int e = 0; e < 4; e++) {
                int row = g + ((e >> 1) << 3);
                int col = 8 * n + 2 * lt + (e & 1);
                O[n][e] += red[w7 * 1024 + row * 64 + col];
            }
        l0 += lred[w7 * 16 + g];
        l1 += lred[w7 * 16 + g + 8];

        const size_t pbase = ((size_t)head * N_SPLIT + split) * N_TOK;
        if (lt == 0) {
            g_l[pbase + r0g] = l0;
            g_l[pbase + r1g] = l1;
        }
        float* dst0 = g_ho + (pbase + r0g) * D_H;
        float* dst1 = g_ho + (pbase + r1g) * D_H;
#pragma unroll
        for (int n = 0; n < 8; n++) {
            *(float2*)&dst0[8 * n + 2 * lt] = make_float2(O[n][0], O[n][1]);
            *(float2*)&dst1[8 * n + 2 * lt] = make_float2(O[n][2], O[n][3]);
        }
    }
}

// ---------------------------------------------------------------------------
// Kernel 3: combine split partials + heads, LayerNorm, FC (unchanged)
// ---------------------------------------------------------------------------
__global__ void __launch_bounds__(256) k_final(const float* __restrict__ attn_w,
                                               const float* __restrict__ gamma,
                                               const float* __restrict__ beta,
                                               const float* __restrict__ fcw,
                                               const float* __restrict__ fcb,
                                               float* __restrict__ out)
{
    const int warp = threadIdx.x >> 5;
    const int lane = threadIdx.x & 31;
    const int row = blockIdx.x * 8 + warp;

    float a0 = attn_w[0], a1 = attn_w[1], a2 = attn_w[2], a3 = attn_w[3];
    float mx = fmaxf(fmaxf(a0, a1), fmaxf(a2, a3));
    float aw[4];
    aw[0] = __expf(a0 - mx); aw[1] = __expf(a1 - mx);
    aw[2] = __expf(a2 - mx); aw[3] = __expf(a3 - mx);
    float ainv = 1.f / (aw[0] + aw[1] + aw[2] + aw[3]);

    const int d0 = lane, d1 = lane + 32;
    float c0 = 0.f, c1 = 0.f;
#pragma unroll
    for (int h = 0; h < N_HEADS; h++) {
        float lsum = 0.f;
        float o0 = 0.f, o1 = 0.f;
#pragma unroll
        for (int s = 0; s < N_SPLIT; s++) {
            const size_t pbase = ((size_t)h * N_SPLIT + s) * N_TOK + row;
            lsum += g_l[pbase];
            const float* p = g_ho + pbase * D_H;
            o0 += p[d0];
            o1 += p[d1];
        }
        float w = aw[h] / lsum;
        c0 += w * o0;
        c1 += w * o1;
    }
    c0 *= ainv; c1 *= ainv;

    float s = c0 + c1;
#pragma unroll
    for (int w = 16; w; w >>= 1) s += __shfl_xor_sync(0xffffffffu, s, w);
    float mu = s * (1.f / 64.f);
    float v0 = c0 - mu, v1 = c1 - mu;
    float vv = v0 * v0 + v1 * v1;
#pragma unroll
    for (int w = 16; w; w >>= 1) vv += __shfl_xor_sync(0xffffffffu, vv, w);
    float inv = rsqrtf(vv * (1.f / 64.f) + LN_EPS);
    float n0 = v0 * inv * gamma[d0] + beta[d0];
    float n1 = v1 * inv * gamma[d1] + beta[d1];

    float o[N_CLS];
#pragma unroll
    for (int c = 0; c < N_CLS; c++)
        o[c] = n0 * fcw[d0 * N_CLS + c] + n1 * fcw[d1 * N_CLS + c];
#pragma unroll
    for (int c = 0; c < N_CLS; c++)
#pragma unroll
        for (int w = 16; w; w >>= 1) o[c] += __shfl_xor_sync(0xffffffffu, o[c], w);

    if (lane == 0) {
#pragma unroll
        for (int c = 0; c < N_CLS; c++)
            out[(size_t)row * N_CLS + c] = o[c] + fcb[c];
    }
}

// ---------------------------------------------------------------------------
extern "C" void kernel_launch(void* const* d_in, const int* in_sizes, int n_in,
                              void* d_out, int out_size)
{
    const float* x      = (const float*)d_in[0];
    const float* proj_w = (const float*)d_in[1];
    const float* proj_b = (const float*)d_in[2];
    const float* head_w = (const float*)d_in[3];
    const float* head_b = (const float*)d_in[4];
    const float* attn_w = (const float*)d_in[5];
    const float* gamma  = (const float*)d_in[6];
    const float* beta   = (const float*)d_in[7];
    const float* fc_w   = (const float*)d_in[8];
    const float* fc_b   = (const float*)d_in[9];
    float* out = (float*)d_out;

    static int smem_set = 0;
    if (!smem_set) {
        cudaFuncSetAttribute(k_attn, cudaFuncAttributeMaxDynamicSharedMemorySize, SM_TOTAL);
        smem_set = 1;
    }

    k_proj<<<N_TOK / 64, 256>>>(x, proj_w, proj_b, head_w, head_b);

    dim3 gp(64, N_HEADS);
    k_prep<<<gp, 128>>>();

    k_dummy<<<1, 32>>>();   // aligns ncu -s 5 onto k_attn

    dim3 g2(N_TOK / 128, N_HEADS, N_SPLIT);
    k_attn<<<g2, 544, SM_TOTAL>>>();

    k_final<<<N_TOK / 8, 256>>>(attn_w, gamma, beta, fc_w, fc_b, out);
}

// round 11
// speedup vs baseline: 10.4580x; 1.0520x over previous
#include <cuda_runtime.h>
#include <cuda_bf16.h>
#include <cuda_fp16.h>
#include <cstdint>
#include <cstddef>

#define N_TOK   8192
#define D_IN    384
#define D_H     64
#define N_HEADS 4
#define N_CLS   6
#define N_SPLIT 4
#define LN_EPS  1e-5f
#define L2SQ    2.0813689810056077f   // (log2 e)^2

// ---------------- scratch (no allocations allowed) ----------------
__device__ float g_hp[(size_t)N_HEADS * N_TOK * D_H];
__device__ float g_ss[(size_t)N_HEADS * N_TOK];                   // ||hp||^2 * L2SQ
__device__ float g_ho[(size_t)N_HEADS * N_SPLIT * N_TOK * D_H];   // partial O (unnormalized)
__device__ float g_l [(size_t)N_HEADS * N_SPLIT * N_TOK];         // partial softmax denominators
// fp16 tile images (u32 = 2 halves):
//  K image per tile: 128 rows x 36 u32 (72 fp16: d 0..63 + pad)     = 4608 u32
//  Vt image per tile: 64 d-rows x 68 u32 (136 fp16: key 0..127+pad) = 4352 u32
__device__ __align__(256) uint32_t g_k16[(size_t)N_HEADS * 64 * 4608];
__device__ __align__(256) uint32_t g_v16[(size_t)N_HEADS * 64 * 4352];

// ---------------- helpers ----------------
__device__ __forceinline__ uint32_t smem_u32(const void* p) {
    uint32_t a;
    asm("{ .reg .u64 t; cvta.to.shared.u64 t, %1; cvt.u32.u64 %0, t; }" : "=r"(a) : "l"(p));
    return a;
}
__device__ __forceinline__ float sqrtapx(float x) {
    float r; asm("sqrt.approx.f32 %0, %1;" : "=f"(r) : "f"(x)); return r;
}
__device__ __forceinline__ uint32_t f16pack(float lo, float hi) {
    uint32_t r; asm("cvt.rn.f16x2.f32 %0, %1, %2;" : "=r"(r) : "f"(hi), "f"(lo)); return r;
}
// packed fp16x2 exp2 (one MUFU op for two elements)
__device__ __forceinline__ uint32_t ex2x2(uint32_t h2) {
    uint32_t r; asm("ex2.approx.f16x2 %0, %1;" : "=r"(r) : "r"(h2)); return r;
}
__device__ __forceinline__ void mma16816h(float c[4], const uint32_t a[4], uint32_t b0, uint32_t b1) {
    asm volatile("mma.sync.aligned.m16n8k16.row.col.f32.f16.f16.f32 "
        "{%0,%1,%2,%3}, {%4,%5,%6,%7}, {%8,%9}, {%0,%1,%2,%3};"
        : "+f"(c[0]), "+f"(c[1]), "+f"(c[2]), "+f"(c[3])
        : "r"(a[0]), "r"(a[1]), "r"(a[2]), "r"(a[3]), "r"(b0), "r"(b1));
}
__device__ __forceinline__ void ldsm4(uint32_t r[4], uint32_t addr) {
    asm volatile("ldmatrix.sync.aligned.m8n8.x4.shared.b16 {%0,%1,%2,%3}, [%4];"
        : "=r"(r[0]), "=r"(r[1]), "=r"(r[2]), "=r"(r[3]) : "r"(addr));
}

#define MBARRIER_INIT(addr, cnt) \
    asm volatile("mbarrier.init.shared.b64 [%0], %1;" :: "r"((uint32_t)(addr)), "r"((uint32_t)(cnt)) : "memory")
#define MBARRIER_EXPECT_TX(addr, tx) \
    asm volatile("mbarrier.arrive.expect_tx.shared.b64 _, [%0], %1;" :: "r"((uint32_t)(addr)), "r"((uint32_t)(tx)) : "memory")
#define MBARRIER_ARRIVE(addr) \
    asm volatile("mbarrier.arrive.shared.b64 _, [%0];" :: "r"((uint32_t)(addr)) : "memory")
#define MBARRIER_WAIT_PARITY(addr, par) do {                                     \
    uint32_t _m = (uint32_t)(addr); uint32_t _p = (uint32_t)(par); uint32_t _d;  \
    asm volatile("{\n\t.reg .pred p;\n\t"                                        \
        "mbarrier.try_wait.parity.acquire.cta.shared::cta.b64 p, [%1], %2;\n\t"  \
        "selp.b32 %0, 1, 0, p;\n\t}" : "=r"(_d) : "r"(_m), "r"(_p) : "memory");  \
    if (!_d) {                                                                   \
        asm volatile("{\n\t.reg .pred P1;\n\t"                                   \
            "WL_%=:\n\t"                                                         \
            "mbarrier.try_wait.parity.acquire.cta.shared::cta.b64 P1, [%0], %1, 0x989680;\n\t" \
            "@P1 bra.uni WD_%=;\n\t"                                             \
            "bra.uni WL_%=;\n\t"                                                 \
            "WD_%=:\n\t}" :: "r"(_m), "r"(_p) : "memory");                       \
    }                                                                            \
} while (0)

__device__ __forceinline__ void bulk_g2s(uint32_t dst, const void* src, uint32_t bytes, uint32_t mbar) {
    asm volatile("cp.async.bulk.shared::cta.global.mbarrier::complete_tx::bytes [%0], [%1], %2, [%3];"
        :: "r"(dst), "l"(src), "r"(bytes), "r"(mbar) : "memory");
}

// ---------------------------------------------------------------------------
// Kernel 1: proj + head projections + sumsq (g_ss pre-scaled by L2SQ)
// ---------------------------------------------------------------------------
__global__ void __launch_bounds__(256) k_proj(const float* __restrict__ x,
                                              const float* __restrict__ pw,
                                              const float* __restrict__ pb,
                                              const float* __restrict__ hw,
                                              const float* __restrict__ hb)
{
    __shared__ float As[64 * 68];
    __shared__ float Ws[64 * 64];
    const int tid = threadIdx.x;
    const int ty = tid >> 4, tx = tid & 15;
    const int row0 = blockIdx.x * 64;

    float acc[4][4];
#pragma unroll
    for (int i = 0; i < 4; i++)
#pragma unroll
        for (int j = 0; j < 4; j++) acc[i][j] = 0.f;

    for (int kk = 0; kk < D_IN; kk += 64) {
#pragma unroll
        for (int l = 0; l < 4; l++) {
            int idx = tid + l * 256;
            int r = idx >> 4, c = (idx & 15) << 2;
            *(float4*)&As[r * 68 + c] = *(const float4*)&x[(size_t)(row0 + r) * D_IN + kk + c];
            *(float4*)&Ws[r * 64 + c] = *(const float4*)&pw[(size_t)(kk + r) * D_H + c];
        }
        __syncthreads();
#pragma unroll 8
        for (int k = 0; k < 64; k++) {
            float a0 = As[(4 * ty + 0) * 68 + k];
            float a1 = As[(4 * ty + 1) * 68 + k];
            float a2 = As[(4 * ty + 2) * 68 + k];
            float a3 = As[(4 * ty + 3) * 68 + k];
            float4 b = *(const float4*)&Ws[k * 64 + 4 * tx];
            acc[0][0] += a0 * b.x; acc[0][1] += a0 * b.y; acc[0][2] += a0 * b.z; acc[0][3] += a0 * b.w;
            acc[1][0] += a1 * b.x; acc[1][1] += a1 * b.y; acc[1][2] += a1 * b.z; acc[1][3] += a1 * b.w;
            acc[2][0] += a2 * b.x; acc[2][1] += a2 * b.y; acc[2][2] += a2 * b.z; acc[2][3] += a2 * b.w;
            acc[3][0] += a3 * b.x; acc[3][1] += a3 * b.y; acc[3][2] += a3 * b.z; acc[3][3] += a3 * b.w;
        }
        __syncthreads();
    }
    {
        float4 pbv = *(const float4*)&pb[4 * tx];
        float pbz[4] = {pbv.x, pbv.y, pbv.z, pbv.w};
#pragma unroll
        for (int i = 0; i < 4; i++)
#pragma unroll
            for (int j = 0; j < 4; j++)
                As[(4 * ty + i) * 68 + 4 * tx + j] = fmaxf(acc[i][j] + pbz[j], 0.f);
    }
    __syncthreads();

    for (int h = 0; h < N_HEADS; h++) {
#pragma unroll
        for (int l = 0; l < 4; l++) {
            int idx = tid + l * 256;
            int r = idx >> 4, c = (idx & 15) << 2;
            *(float4*)&Ws[r * 64 + c] = *(const float4*)&hw[((size_t)h * 64 + r) * 64 + c];
        }
        __syncthreads();

        float a2c[4][4];
#pragma unroll
        for (int i = 0; i < 4; i++)
#pragma unroll
            for (int j = 0; j < 4; j++) a2c[i][j] = 0.f;

#pragma unroll 8
        for (int k = 0; k < 64; k++) {
            float a0 = As[(4 * ty + 0) * 68 + k];
            float a1 = As[(4 * ty + 1) * 68 + k];
            float a2 = As[(4 * ty + 2) * 68 + k];
            float a3 = As[(4 * ty + 3) * 68 + k];
            float4 b = *(const float4*)&Ws[k * 64 + 4 * tx];
            a2c[0][0] += a0 * b.x; a2c[0][1] += a0 * b.y; a2c[0][2] += a0 * b.z; a2c[0][3] += a0 * b.w;
            a2c[1][0] += a1 * b.x; a2c[1][1] += a1 * b.y; a2c[1][2] += a1 * b.z; a2c[1][3] += a1 * b.w;
            a2c[2][0] += a2 * b.x; a2c[2][1] += a2 * b.y; a2c[2][2] += a2 * b.z; a2c[2][3] += a2 * b.w;
            a2c[3][0] += a3 * b.x; a2c[3][1] += a3 * b.y; a2c[3][2] += a3 * b.z; a2c[3][3] += a3 * b.w;
        }

        float4 hbv = *(const float4*)&hb[h * 64 + 4 * tx];
        float hbz[4] = {hbv.x, hbv.y, hbv.z, hbv.w};
#pragma unroll
        for (int i = 0; i < 4; i++) {
            float v0 = a2c[i][0] + hbz[0];
            float v1 = a2c[i][1] + hbz[1];
            float v2 = a2c[i][2] + hbz[2];
            float v3 = a2c[i][3] + hbz[3];
            float rs = v0 * v0 + v1 * v1 + v2 * v2 + v3 * v3;
            *(float4*)&g_hp[((size_t)h * N_TOK + row0 + 4 * ty + i) * D_H + 4 * tx] =
                make_float4(v0, v1, v2, v3);
#pragma unroll
            for (int w = 1; w < 16; w <<= 1)
                rs += __shfl_xor_sync(0xffffffffu, rs, w, 16);
            if (tx == 0) g_ss[(size_t)h * N_TOK + row0 + 4 * ty + i] = rs * L2SQ;
        }
        __syncthreads();
    }
}

// ---------------------------------------------------------------------------
// Kernel 1b: fp16 K image + fp16 Vt image.
// ---------------------------------------------------------------------------
__global__ void __launch_bounds__(128) k_prep()
{
    __shared__ float tile[128][65];
    const int t = blockIdx.x, head = blockIdx.y, tid = threadIdx.x;

    const float* src = g_hp + ((size_t)head * N_TOK + (size_t)t * 128 + tid) * 64;
    uint32_t* kh = g_k16 + ((size_t)head * 64 + t) * 4608;
#pragma unroll 8
    for (int m = 0; m < 32; m++) {
        float f0 = src[2 * m], f1 = src[2 * m + 1];
        tile[tid][2 * m] = f0;
        tile[tid][2 * m + 1] = f1;
        kh[tid * 36 + m] = f16pack(f0, f1);
    }
    __syncthreads();

    uint32_t* vh = g_v16 + ((size_t)head * 64 + t) * 4352;
    const int d = tid >> 1, half = tid & 1;
#pragma unroll 8
    for (int m = 0; m < 32; m++) {
        int key = half * 64 + 2 * m;
        vh[d * 68 + half * 32 + m] = f16pack(tile[key][d], tile[key + 1][d]);
    }
}

// profiling alignment shim (lets ncu -s 5 land on k_attn)
__global__ void k_dummy() {}

// ---------------------------------------------------------------------------
// Kernel 2: split-K distance flash-attention, 16 consumer warps (4/SMSP).
//  GEMM1: fp16 single product S = Q.K.
//  Epilogue: ex2.approx.f16x2 produces the packed-fp16 P fragment directly
//  (1 MUFU per pair); l computed by an extra ones-column MMA (constant B
//  fragment, no smem) instead of scalar adds + shuffles.
// ---------------------------------------------------------------------------
#define SM_FULL(s)  ((s) * 8)
#define SM_EMPTY(s) (24 + (s) * 8)
#define SM_Q       128
#define SM_STG     (SM_Q + 18432)            // 18560
#define OFF_K16    0
#define OFF_V16    18432
#define OFF_KK     35840
#define STG_BYTES  36352
#define N_STAGES   3
#define T_PER_CTA  16
#define SM_TOTAL   (SM_STG + N_STAGES * STG_BYTES)   // 127616

__global__ void __launch_bounds__(544, 1) k_attn()
{
    extern __shared__ char smem[];
    const uint32_t sb = smem_u32(smem);
    const int tid  = threadIdx.x;
    const int warp = tid >> 5;
    const int lane = tid & 31;
    const int head = blockIdx.y;
    const int split = blockIdx.z;
    const int q0 = blockIdx.x * 128;
    const int t0 = split * T_PER_CTA;
    const float* ssq = g_ss + (size_t)head * N_TOK;

    if (tid == 0) {
#pragma unroll
        for (int s = 0; s < N_STAGES; s++) {
            MBARRIER_INIT(sb + SM_FULL(s), 1);
            MBARRIER_INIT(sb + SM_EMPTY(s), 16);
        }
    }

    // Q image resident in smem for the whole CTA
    {
        const uint4* sh = (const uint4*)(g_k16 + ((size_t)head * 64 + blockIdx.x) * 4608);
        uint4* dh = (uint4*)(smem + SM_Q);
        for (int i = tid; i < 1152; i += 544) dh[i] = sh[i];
    }
    __syncthreads();

    const int w7 = warp & 7;
    const int khalf = (warp & 8) ? 64 : 0;
    const int g  = lane >> 2;
    const int lt = lane & 3;
    const int mm = lane >> 3;
    const int r8 = lane & 7;
    const int q_dsel = (mm >> 1) * 16;
    const int k_dsel = (mm & 1) * 16;
    const int k_rowofs = r8 + (mm >> 1) * 8;
    const int q_row = 16 * w7 + r8 + (mm & 1) * 8;

    const int r0g = q0 + 16 * w7 + g;
    const int r1g = r0g + 8;

    // constant ones-column B fragment (col n=0 only): fp16 (1.0, 1.0)
    const uint32_t ones_b = (lt == 0 && g < 2) ? 0u : 0u;   // placeholder (set below)
    const uint32_t ones_frag = ((lane >> 2) == 0) ? 0x3C003C00u : 0u;
    (void)ones_b;

    float O[8][4];
#pragma unroll
    for (int n = 0; n < 8; n++)
#pragma unroll
        for (int e = 0; e < 4; e++) O[n][e] = 0.f;
    float Ol[4] = {0.f, 0.f, 0.f, 0.f};   // ones-column accum: Ol[0]=l(row0), Ol[2]=l(row1) at lt==0

    if (warp == 16) {
        // ---------------- producer warp ----------------
        if (lane == 0) {
            const size_t hb = (size_t)head * 64 + t0;
#pragma unroll
            for (int i = 0; i < N_STAGES; i++) {
                const uint32_t st = sb + SM_STG + i * STG_BYTES;
                MBARRIER_EXPECT_TX(sb + SM_FULL(i), STG_BYTES);
                bulk_g2s(st + OFF_K16, g_k16 + (hb + i) * 4608, 18432, sb + SM_FULL(i));
                bulk_g2s(st + OFF_V16, g_v16 + (hb + i) * 4352, 17408, sb + SM_FULL(i));
                bulk_g2s(st + OFF_KK,  ssq + (size_t)(t0 + i) * 128, 512, sb + SM_FULL(i));
            }
            int s = 0, pe = 0;
            for (int i = N_STAGES; i < T_PER_CTA; i++) {
                MBARRIER_WAIT_PARITY(sb + SM_EMPTY(s), pe);
                const uint32_t st = sb + SM_STG + s * STG_BYTES;
                MBARRIER_EXPECT_TX(sb + SM_FULL(s), STG_BYTES);
                bulk_g2s(st + OFF_K16, g_k16 + (hb + i) * 4608, 18432, sb + SM_FULL(s));
                bulk_g2s(st + OFF_V16, g_v16 + (hb + i) * 4352, 17408, sb + SM_FULL(s));
                bulk_g2s(st + OFF_KK,  ssq + (size_t)(t0 + i) * 128, 512, sb + SM_FULL(s));
                if (++s == N_STAGES) { s = 0; pe ^= 1; }
            }
        }
    } else {
        // ---------------- consumer warps (0..15) ----------------
        const float qq0 = ssq[r0g];     // already *L2SQ
        const float qq1 = ssq[r1g];
        const float N2L = -2.f * L2SQ;

        int s = 0, ph = 0;
        for (int i = 0; i < T_PER_CTA; i++) {
            const int t = t0 + i;
            MBARRIER_WAIT_PARITY(sb + SM_FULL(s), ph);
            const uint32_t stg = sb + SM_STG + s * STG_BYTES;

            // ---- GEMM1: S = Q.K, fp16 single product ----
            float S[8][4];
#pragma unroll
            for (int n = 0; n < 8; n++)
#pragma unroll
                for (int e = 0; e < 4; e++) S[n][e] = 0.f;

#pragma unroll
            for (int kc = 0; kc < 4; kc++) {
                uint32_t qh[4];
                ldsm4(qh, sb + SM_Q + q_row * 144 + kc * 32 + q_dsel);
#pragma unroll
                for (int np = 0; np < 4; np++) {
                    uint32_t kb[4];
                    ldsm4(kb, stg + OFF_K16 + (khalf + 16 * np + k_rowofs) * 144 + kc * 32 + k_dsel);
                    mma16816h(S[2 * np],     qh, kb[0], kb[1]);
                    mma16816h(S[2 * np + 1], qh, kb[2], kb[3]);
                }
            }

            // ---- GEMM2 with interleaved f16x2 softmax epilogue ----
            const float* kkp = (const float*)(smem + SM_STG + s * STG_BYTES + OFF_KK);
            const bool dt = (t == (int)blockIdx.x);   // only tile that can hold the diagonal
            const int kt = t * 128;
#pragma unroll
            for (int kc2 = 0; kc2 < 4; kc2++) {
                uint32_t aF[4];
#pragma unroll
                for (int u = 0; u < 2; u++) {
                    const int nt = 2 * kc2 + u;
                    float2 kkv = *(const float2*)(kkp + khalf + 8 * nt + 2 * lt);
                    float d00 = 0.f - sqrtapx(fmaxf(fmaf(S[nt][0], N2L, qq0 + kkv.x), 0.f));
                    float d01 = 0.f - sqrtapx(fmaxf(fmaf(S[nt][1], N2L, qq0 + kkv.y), 0.f));
                    float d10 = 0.f - sqrtapx(fmaxf(fmaf(S[nt][2], N2L, qq1 + kkv.x), 0.f));
                    float d11 = 0.f - sqrtapx(fmaxf(fmaf(S[nt][3], N2L, qq1 + kkv.y), 0.f));
                    if (dt) {
                        const int colg = kt + khalf + 8 * nt + 2 * lt;
                        if (colg == r0g)     d00 = 0.f;
                        if (colg + 1 == r0g) d01 = 0.f;
                        if (colg == r1g)     d10 = 0.f;
                        if (colg + 1 == r1g) d11 = 0.f;
                    }
                    aF[2 * u]     = ex2x2(f16pack(d00, d01));   // p row0: exp2(-log2e*dist)
                    aF[2 * u + 1] = ex2x2(f16pack(d10, d11));   // p row1
                }
                // l accumulation via constant ones-column MMA (no smem, no ldsm)
                mma16816h(Ol, aF, ones_frag, ones_frag);
#pragma unroll
                for (int j = 0; j < 4; j++) {
                    uint32_t vb[4];
                    uint32_t va = stg + OFF_V16 + (16 * j + k_rowofs) * 272
                                + (khalf + 16 * kc2) * 2 + k_dsel;
                    ldsm4(vb, va);
                    mma16816h(O[2 * j],     aF, vb[0], vb[1]);
                    mma16816h(O[2 * j + 1], aF, vb[2], vb[3]);
                }
            }

            if (lane == 0) MBARRIER_ARRIVE(sb + SM_EMPTY(s));
            if (++s == N_STAGES) { s = 0; ph ^= 1; }
        }
    }

    // ---- cross-half reduction through (now free) stage smem ----
    __syncthreads();
    float* red  = (float*)(smem + SM_STG);             // 8 * 16 * 64 floats = 32KB
    float* lred = (float*)(smem + SM_STG + 32768);     // 8 * 16 floats

    if (warp >= 8 && warp < 16) {
#pragma unroll
        for (int n = 0; n < 8; n++)
#pragma unroll
            for (int e = 0; e < 4; e++) {
                int row = g + ((e >> 1) << 3);
                int col = 8 * n + 2 * lt + (e & 1);
                red[w7 * 1024 + row * 64 + col] = O[n][e];
            }
        if (lt == 0) {
            lred[w7 * 16 + g] = Ol[0];
            lred[w7 * 16 + g + 8] = Ol[2];
        }
    }
    __syncthreads();

    if (warp < 8) {
#pragma unroll
        for (int n = 0; n < 8; n++)
#pragma unroll
            for (int e = 0; e < 4; e++) {
                int row = g + ((e >> 1) << 3);
                int col = 8 * n + 2 * lt + (e & 1);
                O[n][e] += red[w7 * 1024 + row * 64 + col];
            }

        const size_t pbase = ((size_t)head * N_SPLIT + split) * N_TOK;
        if (lt == 0) {
            g_l[pbase + r0g] = Ol[0] + lred[w7 * 16 + g];
            g_l[pbase + r1g] = Ol[2] + lred[w7 * 16 + g + 8];
        }
        float* dst0 = g_ho + (pbase + r0g) * D_H;
        float* dst1 = g_ho + (pbase + r1g) * D_H;
#pragma unroll
        for (int n = 0; n < 8; n++) {
            *(float2*)&dst0[8 * n + 2 * lt] = make_float2(O[n][0], O[n][1]);
            *(float2*)&dst1[8 * n + 2 * lt] = make_float2(O[n][2], O[n][3]);
        }
    }
}

// ---------------------------------------------------------------------------
// Kernel 3: combine split partials + heads, LayerNorm, FC (unchanged)
// ---------------------------------------------------------------------------
__global__ void __launch_bounds__(256) k_final(const float* __restrict__ attn_w,
                                               const float* __restrict__ gamma,
                                               const float* __restrict__ beta,
                                               const float* __restrict__ fcw,
                                               const float* __restrict__ fcb,
                                               float* __restrict__ out)
{
    const int warp = threadIdx.x >> 5;
    const int lane = threadIdx.x & 31;
    const int row = blockIdx.x * 8 + warp;

    float a0 = attn_w[0], a1 = attn_w[1], a2 = attn_w[2], a3 = attn_w[3];
    float mx = fmaxf(fmaxf(a0, a1), fmaxf(a2, a3));
    float aw[4];
    aw[0] = __expf(a0 - mx); aw[1] = __expf(a1 - mx);
    aw[2] = __expf(a2 - mx); aw[3] = __expf(a3 - mx);
    float ainv = 1.f / (aw[0] + aw[1] + aw[2] + aw[3]);

    const int d0 = lane, d1 = lane + 32;
    float c0 = 0.f, c1 = 0.f;
#pragma unroll
    for (int h = 0; h < N_HEADS; h++) {
        float lsum = 0.f;
        float o0 = 0.f, o1 = 0.f;
#pragma unroll
        for (int s = 0; s < N_SPLIT; s++) {
            const size_t pbase = ((size_t)h * N_SPLIT + s) * N_TOK + row;
            lsum += g_l[pbase];
            const float* p = g_ho + pbase * D_H;
            o0 += p[d0];
            o1 += p[d1];
        }
        float w = aw[h] / lsum;
        c0 += w * o0;
        c1 += w * o1;
    }
    c0 *= ainv; c1 *= ainv;

    float s = c0 + c1;
#pragma unroll
    for (int w = 16; w; w >>= 1) s += __shfl_xor_sync(0xffffffffu, s, w);
    float mu = s * (1.f / 64.f);
    float v0 = c0 - mu, v1 = c1 - mu;
    float vv = v0 * v0 + v1 * v1;
#pragma unroll
    for (int w = 16; w; w >>= 1) vv += __shfl_xor_sync(0xffffffffu, vv, w);
    float inv = rsqrtf(vv * (1.f / 64.f) + LN_EPS);
    float n0 = v0 * inv * gamma[d0] + beta[d0];
    float n1 = v1 * inv * gamma[d1] + beta[d1];

    float o[N_CLS];
#pragma unroll
    for (int c = 0; c < N_CLS; c++)
        o[c] = n0 * fcw[d0 * N_CLS + c] + n1 * fcw[d1 * N_CLS + c];
#pragma unroll
    for (int c = 0; c < N_CLS; c++)
#pragma unroll
        for (int w = 16; w; w >>= 1) o[c] += __shfl_xor_sync(0xffffffffu, o[c], w);

    if (lane == 0) {
#pragma unroll
        for (int c = 0; c < N_CLS; c++)
            out[(size_t)row * N_CLS + c] = o[c] + fcb[c];
    }
}

// ---------------------------------------------------------------------------
extern "C" void kernel_launch(void* const* d_in, const int* in_sizes, int n_in,
                              void* d_out, int out_size)
{
    const float* x      = (const float*)d_in[0];
    const float* proj_w = (const float*)d_in[1];
    const float* proj_b = (const float*)d_in[2];
    const float* head_w = (const float*)d_in[3];
    const float* head_b = (const float*)d_in[4];
    const float* attn_w = (const float*)d_in[5];
    const float* gamma  = (const float*)d_in[6];
    const float* beta   = (const float*)d_in[7];
    const float* fc_w   = (const float*)d_in[8];
    const float* fc_b   = (const float*)d_in[9];
    float* out = (float*)d_out;

    static int smem_set = 0;
    if (!smem_set) {
        cudaFuncSetAttribute(k_attn, cudaFuncAttributeMaxDynamicSharedMemorySize, SM_TOTAL);
        smem_set = 1;
    }

    k_proj<<<N_TOK / 64, 256>>>(x, proj_w, proj_b, head_w, head_b);

    dim3 gp(64, N_HEADS);
    k_prep<<<gp, 128>>>();

    k_dummy<<<1, 32>>>();   // aligns ncu -s 5 onto k_attn

    dim3 g2(N_TOK / 128, N_HEADS, N_SPLIT);
    k_attn<<<g2, 544, SM_TOTAL>>>();

    k_final<<<N_TOK / 8, 256>>>(attn_w, gamma, beta, fc_w, fc_b, out);
}